// round 1
// baseline (speedup 1.0000x reference)
#include <cuda_runtime.h>
#include <cstdint>
#include <cstddef>

// ---------------------------------------------------------------------------
// Problem constants (fixed by the dataset)
// ---------------------------------------------------------------------------
#define Q_   8192
#define C_   256
#define BSZ  2
#define LVL  4
#define PPT  4
#define NH_  8
#define DH_  32
#define HMAX_ 128

// Compact valid-row layout: per batch, levels are 128^2, 64^2, 32^2, 16^2.
#define ROWS_PER_B 21760   // 16384+4096+1024+256
#define NROWS      43520   // 2 * ROWS_PER_B

// ---------------------------------------------------------------------------
// Scratch (device globals; no allocation allowed)
// ---------------------------------------------------------------------------
__device__ float g_vproj[(size_t)NROWS * C_];   // 44.6 MB: projected valid values
__device__ float g_offs [(size_t)Q_ * 256];     // sampling-offset raw proj
__device__ float g_awr  [(size_t)Q_ * 128];     // attention-weight logits
__device__ float g_agg  [(size_t)Q_ * C_];      // per-query aggregated heads

// ---------------------------------------------------------------------------
// Row mapping: compact row r -> offset into values[B,128,128,L,C]
// ---------------------------------------------------------------------------
__device__ __forceinline__ size_t map_a_row(int r) {
    int b  = r / ROWS_PER_B;
    int rr = r - b * ROWS_PER_B;
    int l, base, W;
    if (rr < 16384)      { l = 0; base = 0;     W = 128; }
    else if (rr < 20480) { l = 1; base = 16384; W = 64;  }
    else if (rr < 21504) { l = 2; base = 20480; W = 32;  }
    else                 { l = 3; base = 21504; W = 16;  }
    int idx = rr - base;
    int y = idx / W;
    int x = idx - y * W;
    return ((((size_t)b * HMAX_ + y) * HMAX_ + x) * LVL + l) * C_;
}

// ---------------------------------------------------------------------------
// SGEMM: C[m,n] = sum_k A[m,k] * B[n,k] + bias[n]
//   A: M x K row-major (MAPPED: rows gathered from values tensor)
//   B: N x K row-major (nn.Linear weight layout)
// Tile: 128x64, BK=32, 256 threads, 8x4 per-thread register tile.
// Requires M%128==0, N%64==0, K%32==0 (all shapes here satisfy this).
// ---------------------------------------------------------------------------
template <bool MAPPED>
__global__ void sgemm_nt_kernel(const float* __restrict__ A,
                                const float* __restrict__ Bm,
                                const float* __restrict__ bias,
                                float* __restrict__ Cm,
                                int M, int N, int K)
{
    constexpr int BM = 128, BN = 64, BK = 32;
    __shared__ __align__(16) float As[BK][BM];
    __shared__ __align__(16) float Bs[BK][BN];

    const int tid = threadIdx.x;            // 0..255
    const int tx  = tid & 15;               // N direction (4 cols each)
    const int ty  = tid >> 4;               // M direction (8 rows each)
    const int m0  = blockIdx.y * BM;
    const int n0  = blockIdx.x * BN;

    // A tile loading: 128 rows x 32 k, 2 threads per row (16 floats each)
    const int arow  = tid >> 1;
    const int akseg = (tid & 1) * 16;
    size_t aoff = MAPPED ? map_a_row(m0 + arow) : (size_t)(m0 + arow) * K;
    const float* Aptr = A + aoff + akseg;

    // B tile loading: 64 rows x 32 k, 4 threads per row (8 floats each)
    const int brow  = tid >> 2;
    const int bkseg = (tid & 3) * 8;
    const float* Bptr = Bm + (size_t)(n0 + brow) * K + bkseg;

    float acc[8][4];
#pragma unroll
    for (int i = 0; i < 8; i++)
#pragma unroll
        for (int j = 0; j < 4; j++) acc[i][j] = 0.0f;

    for (int k0 = 0; k0 < K; k0 += BK) {
#pragma unroll
        for (int j = 0; j < 4; j++) {
            float4 v = *(const float4*)(Aptr + k0 + j * 4);
            As[akseg + j * 4 + 0][arow] = v.x;
            As[akseg + j * 4 + 1][arow] = v.y;
            As[akseg + j * 4 + 2][arow] = v.z;
            As[akseg + j * 4 + 3][arow] = v.w;
        }
#pragma unroll
        for (int j = 0; j < 2; j++) {
            float4 v = *(const float4*)(Bptr + k0 + j * 4);
            Bs[bkseg + j * 4 + 0][brow] = v.x;
            Bs[bkseg + j * 4 + 1][brow] = v.y;
            Bs[bkseg + j * 4 + 2][brow] = v.z;
            Bs[bkseg + j * 4 + 3][brow] = v.w;
        }
        __syncthreads();

#pragma unroll
        for (int k = 0; k < BK; k++) {
            float4 a0 = *(const float4*)&As[k][ty * 8];
            float4 a1 = *(const float4*)&As[k][ty * 8 + 4];
            float4 bf = *(const float4*)&Bs[k][tx * 4];
            float av[8] = {a0.x, a0.y, a0.z, a0.w, a1.x, a1.y, a1.z, a1.w};
            float bv[4] = {bf.x, bf.y, bf.z, bf.w};
#pragma unroll
            for (int i = 0; i < 8; i++)
#pragma unroll
                for (int j = 0; j < 4; j++)
                    acc[i][j] += av[i] * bv[j];
        }
        __syncthreads();
    }

    float4 bb = *(const float4*)&bias[n0 + tx * 4];
#pragma unroll
    for (int i = 0; i < 8; i++) {
        float4 o = make_float4(acc[i][0] + bb.x, acc[i][1] + bb.y,
                               acc[i][2] + bb.z, acc[i][3] + bb.w);
        *(float4*)&Cm[(size_t)(m0 + ty * 8 + i) * N + n0 + tx * 4] = o;
    }
}

// ---------------------------------------------------------------------------
// Sampling kernel: one block (256 threads) per query.
//  - softmax attention weights per head (16 (l,p) entries per head)
//  - compute 4 bilinear corners per (l,p,h): compact row + fused weight
//  - gather head slices of g_vproj and accumulate into g_agg[q, h*32+d]
// ---------------------------------------------------------------------------
__global__ void sample_kernel(const float* __restrict__ ref,
                              const int* __restrict__ batch_offsets)
{
    const int q   = blockIdx.x;
    const int tid = threadIdx.x;

    __shared__ float sL[128];
    __shared__ float hM[8];
    __shared__ float hR[8];
    __shared__ int   srow[128][4];
    __shared__ float swt [128][4];

    if (tid < 128) sL[tid] = g_awr[(size_t)q * 128 + tid];
    __syncthreads();

    if (tid < 8) {
        float m = -1e30f;
#pragma unroll
        for (int lp = 0; lp < 16; lp++) m = fmaxf(m, sL[lp * 8 + tid]);
        float s = 0.0f;
#pragma unroll
        for (int lp = 0; lp < 16; lp++) s += __expf(sL[lp * 8 + tid] - m) * 0.0f + expf(sL[lp * 8 + tid] - m);
        hM[tid] = m;
        hR[tid] = 1.0f / s;
    }
    __syncthreads();

    if (tid < 128) {
        const int i  = tid;
        const int h  = i & 7;
        const int lp = i >> 3;
        const int l  = lp >> 2;

        float aw = expf(sL[i] - hM[h]) * hR[h];

        // inverse-sigmoid of the reference point (matches reference clipping)
        float rx = ref[q * 2 + 0];
        float ry = ref[q * 2 + 1];
        rx = fminf(fmaxf(rx, 0.0f), 1.0f);
        ry = fminf(fmaxf(ry, 0.0f), 1.0f);
        float isx = logf(fmaxf(rx, 1e-5f) / fmaxf(1.0f - rx, 1e-5f));
        float isy = logf(fmaxf(ry, 1e-5f) / fmaxf(1.0f - ry, 1e-5f));

        float ox = g_offs[(size_t)q * 256 + i * 2 + 0];
        float oy = g_offs[(size_t)q * 256 + i * 2 + 1];

        float locx = 1.0f / (1.0f + expf(-(isx + ox)));
        float locy = 1.0f / (1.0f + expf(-(isy + oy)));

        const int   Wl = HMAX_ >> l;          // square levels: H_l == W_l
        const float Wf = (float)Wl;
        float x = locx * Wf - 0.5f;
        float y = locy * Wf - 0.5f;

        float x0f = floorf(x), y0f = floorf(y);
        float wx1 = x - x0f, wx0 = 1.0f - wx1;
        float wy1 = y - y0f, wy0 = 1.0f - wy1;
        int x0 = (int)x0f, y0 = (int)y0f;

        int b = (q >= batch_offsets[1]) ? 1 : 0;
        int lbase = (l >= 1 ? 16384 : 0) + (l >= 2 ? 4096 : 0) + (l >= 3 ? 1024 : 0);
        int base = b * ROWS_PER_B + lbase;

        int   xs[2]  = {x0, x0 + 1};
        int   ys2[2] = {y0, y0 + 1};
        float wxs[2] = {wx0, wx1};
        float wys[2] = {wy0, wy1};

#pragma unroll
        for (int cy = 0; cy < 2; cy++) {
#pragma unroll
            for (int cx = 0; cx < 2; cx++) {
                int c  = cy * 2 + cx;
                int xi = xs[cx], yi = ys2[cy];
                bool valid = (xi >= 0) & (xi < Wl) & (yi >= 0) & (yi < Wl);
                srow[i][c] = valid ? (base + yi * Wl + xi) : -1;
                swt [i][c] = valid ? (aw * wys[cy] * wxs[cx]) : 0.0f;
            }
        }
    }
    __syncthreads();

    // Accumulate: thread tid -> (head h, channel d)
    const int h = tid >> 5;
    const int d = tid & 31;
    float acc = 0.0f;
#pragma unroll
    for (int lp = 0; lp < 16; lp++) {
        const int i = lp * 8 + h;
#pragma unroll
        for (int c = 0; c < 4; c++) {
            int r = srow[i][c];
            if (r >= 0)
                acc += swt[i][c] * __ldg(&g_vproj[(size_t)r * C_ + h * DH_ + d]);
        }
    }
    g_agg[(size_t)q * C_ + h * DH_ + d] = acc;
}

// ---------------------------------------------------------------------------
// kernel_launch
// ---------------------------------------------------------------------------
extern "C" void kernel_launch(void* const* d_in, const int* in_sizes, int n_in,
                              void* d_out, int out_size)
{
    const float* query  = (const float*)d_in[0];
    const float* ref    = (const float*)d_in[1];
    const float* values = (const float*)d_in[2];
    const float* W_so   = (const float*)d_in[3];
    const float* b_so   = (const float*)d_in[4];
    const float* W_aw   = (const float*)d_in[5];
    const float* b_aw   = (const float*)d_in[6];
    const float* W_v    = (const float*)d_in[7];
    const float* b_v    = (const float*)d_in[8];
    const float* W_o    = (const float*)d_in[9];
    const float* b_o    = (const float*)d_in[10];
    const int* batch_offsets = (const int*)d_in[11];
    // d_in[12]: spatial_shapes (fixed {128,64,32,16}^2, hardcoded)
    float* out = (float*)d_out;
    (void)in_sizes; (void)n_in; (void)out_size;

    float *vproj, *offs, *awr, *agg;
    cudaGetSymbolAddress((void**)&vproj, g_vproj);
    cudaGetSymbolAddress((void**)&offs,  g_offs);
    cudaGetSymbolAddress((void**)&awr,   g_awr);
    cudaGetSymbolAddress((void**)&agg,   g_agg);

    dim3 blk(256);

    // 1) project valid value rows: [43520,256] = values_valid @ W_v.T + b_v
    {
        dim3 grid(C_ / 64, NROWS / 128);
        sgemm_nt_kernel<true><<<grid, blk>>>(values, W_v, b_v, vproj, NROWS, C_, C_);
    }
    // 2) sampling offsets: [8192,256] = query @ W_so.T + b_so
    {
        dim3 grid(256 / 64, Q_ / 128);
        sgemm_nt_kernel<false><<<grid, blk>>>(query, W_so, b_so, offs, Q_, 256, C_);
    }
    // 3) attention-weight logits: [8192,128] = query @ W_aw.T + b_aw
    {
        dim3 grid(128 / 64, Q_ / 128);
        sgemm_nt_kernel<false><<<grid, blk>>>(query, W_aw, b_aw, awr, Q_, 128, C_);
    }
    // 4) softmax + bilinear sampling + head aggregation
    sample_kernel<<<Q_, blk>>>(ref, batch_offsets);

    // 5) output projection: out = agg @ W_o.T + b_o
    {
        dim3 grid(C_ / 64, Q_ / 128);
        sgemm_nt_kernel<false><<<grid, blk>>>(agg, W_o, b_o, out, Q_, C_, C_);
    }
}

// round 3
// speedup vs baseline: 1.1581x; 1.1581x over previous
#include <cuda_runtime.h>
#include <cstdint>
#include <cstddef>

// ---------------------------------------------------------------------------
// Problem constants (fixed by the dataset)
// ---------------------------------------------------------------------------
#define Q_   8192
#define C_   256
#define BSZ  2
#define LVL  4
#define PPT  4
#define NH_  8
#define DH_  32
#define HMAX_ 128

// Compact valid-row layout: per batch, levels are 128^2, 64^2, 32^2, 16^2.
#define ROWS_PER_B 21760   // 16384+4096+1024+256
#define NROWS      43520   // 2 * ROWS_PER_B

// ---------------------------------------------------------------------------
// Scratch (device globals; no allocation allowed)
// ---------------------------------------------------------------------------
__device__ float g_vproj[(size_t)NROWS * C_];   // 44.6 MB: projected valid values
__device__ float g_offs [(size_t)Q_ * 256];     // sampling-offset raw proj
__device__ float g_awr  [(size_t)Q_ * 128];     // attention-weight logits
__device__ float g_agg  [(size_t)Q_ * C_];      // per-query aggregated heads

// ---------------------------------------------------------------------------
// Row mapping: compact row r -> offset into values[B,128,128,L,C]
// ---------------------------------------------------------------------------
__device__ __forceinline__ size_t map_a_row(int r) {
    int b  = r / ROWS_PER_B;
    int rr = r - b * ROWS_PER_B;
    int l, base, W;
    if (rr < 16384)      { l = 0; base = 0;     W = 128; }
    else if (rr < 20480) { l = 1; base = 16384; W = 64;  }
    else if (rr < 21504) { l = 2; base = 20480; W = 32;  }
    else                 { l = 3; base = 21504; W = 16;  }
    int idx = rr - base;
    int y = idx / W;
    int x = idx - y * W;
    return ((((size_t)b * HMAX_ + y) * HMAX_ + x) * LVL + l) * C_;
}

// ---------------------------------------------------------------------------
// tf32 helpers
// ---------------------------------------------------------------------------
__device__ __forceinline__ float to_tf32(float x) {
    float r;
    asm("cvt.rna.tf32.f32 %0, %1;" : "=f"(r) : "f"(x));
    return r;
}

__device__ __forceinline__ void mma_tf32(float* c, const uint32_t* a, const uint32_t* b) {
    asm volatile(
        "mma.sync.aligned.m16n8k8.row.col.f32.tf32.tf32.f32 "
        "{%0,%1,%2,%3}, {%4,%5,%6,%7}, {%8,%9}, {%0,%1,%2,%3};\n"
        : "+f"(c[0]), "+f"(c[1]), "+f"(c[2]), "+f"(c[3])
        : "r"(a[0]), "r"(a[1]), "r"(a[2]), "r"(a[3]), "r"(b[0]), "r"(b[1]));
}

// ---------------------------------------------------------------------------
// 3xTF32 tensor-core GEMM (fp32-accurate): C[m,n] = sum_k A[m,k]*B[n,k] + bias[n]
//   Each operand split hi/lo; acc += ah*bh + ah*bl + al*bh (al*bl ~2^-22 dropped).
//   A: M x K row-major (MAPPED: rows gathered from values tensor)
//   B: N x K row-major (nn.Linear weight layout)
// Block tile 128x128, BK=16, 256 threads (8 warps as 2(m) x 4(n)),
// warp tile 64x32 via m16n8k8 tf32 mma (4 m-frags x 4 n-frags).
// Requires M%128==0, N%128==0, K%16==0.
// ---------------------------------------------------------------------------
template <bool MAPPED>
__global__ __launch_bounds__(256)
void gemm_tf32x3_nt(const float* __restrict__ A, const float* __restrict__ Bm,
                    const float* __restrict__ bias, float* __restrict__ Cm,
                    int M, int N, int K)
{
    constexpr int BM = 128, BN = 128, BK = 16, LDS = 136;  // pad 8 -> conflict-free
    __shared__ float AsH[BK * LDS];
    __shared__ float AsL[BK * LDS];
    __shared__ float BsH[BK * LDS];
    __shared__ float BsL[BK * LDS];

    const int tid  = threadIdx.x;
    const int wid  = tid >> 5, lane = tid & 31;
    const int g    = lane >> 2, t = lane & 3;   // groupID / threadID_in_group
    const int m0   = blockIdx.y * BM, n0 = blockIdx.x * BN;
    const int wm   = (wid & 1) * 64;            // warp m offset
    const int wn   = (wid >> 1) * 32;           // warp n offset

    // global->smem loading: 2 threads per row, 8 k each (two float4)
    const int row  = tid >> 1;
    const int kseg = (tid & 1) * 8;
    size_t aoff = MAPPED ? map_a_row(m0 + row) : (size_t)(m0 + row) * K;
    const float* Ap = A + aoff + kseg;
    const float* Bp = Bm + (size_t)(n0 + row) * K + kseg;

    float acc[4][4][4];
#pragma unroll
    for (int i = 0; i < 4; i++)
#pragma unroll
        for (int j = 0; j < 4; j++)
#pragma unroll
            for (int c = 0; c < 4; c++) acc[i][j][c] = 0.0f;

    for (int k0 = 0; k0 < K; k0 += BK) {
#pragma unroll
        for (int j = 0; j < 2; j++) {
            float4 va = *(const float4*)(Ap + k0 + j * 4);
            float4 vb = *(const float4*)(Bp + k0 + j * 4);
            int kk = kseg + j * 4;
            float av[4] = {va.x, va.y, va.z, va.w};
            float bv[4] = {vb.x, vb.y, vb.z, vb.w};
#pragma unroll
            for (int e = 0; e < 4; e++) {
                float ah = to_tf32(av[e]);
                float bh = to_tf32(bv[e]);
                AsH[(kk + e) * LDS + row] = ah;
                AsL[(kk + e) * LDS + row] = to_tf32(av[e] - ah);
                BsH[(kk + e) * LDS + row] = bh;
                BsL[(kk + e) * LDS + row] = to_tf32(bv[e] - bh);
            }
        }
        __syncthreads();

        const uint32_t* AsHu = (const uint32_t*)AsH;
        const uint32_t* AsLu = (const uint32_t*)AsL;
        const uint32_t* BsHu = (const uint32_t*)BsH;
        const uint32_t* BsLu = (const uint32_t*)BsL;
#pragma unroll
        for (int ks = 0; ks < BK; ks += 8) {
            uint32_t afH[4][4], afL[4][4], bfH[4][2], bfL[4][2];
#pragma unroll
            for (int fm = 0; fm < 4; fm++) {
                int mb = wm + fm * 16 + g;
                int i0 = (ks + t) * LDS + mb;
                int i1 = (ks + t + 4) * LDS + mb;
                afH[fm][0] = AsHu[i0];     afL[fm][0] = AsLu[i0];
                afH[fm][1] = AsHu[i0 + 8]; afL[fm][1] = AsLu[i0 + 8];
                afH[fm][2] = AsHu[i1];     afL[fm][2] = AsLu[i1];
                afH[fm][3] = AsHu[i1 + 8]; afL[fm][3] = AsLu[i1 + 8];
            }
#pragma unroll
            for (int fn = 0; fn < 4; fn++) {
                int nb = wn + fn * 8 + g;
                int i0 = (ks + t) * LDS + nb;
                int i1 = (ks + t + 4) * LDS + nb;
                bfH[fn][0] = BsHu[i0]; bfL[fn][0] = BsLu[i0];
                bfH[fn][1] = BsHu[i1]; bfL[fn][1] = BsLu[i1];
            }
#pragma unroll
            for (int fm = 0; fm < 4; fm++)
#pragma unroll
                for (int fn = 0; fn < 4; fn++) {
                    mma_tf32(acc[fm][fn], afL[fm], bfH[fn]);
                    mma_tf32(acc[fm][fn], afH[fm], bfL[fn]);
                    mma_tf32(acc[fm][fn], afH[fm], bfH[fn]);
                }
        }
        __syncthreads();
    }

    // epilogue: bias add + float2 stores
#pragma unroll
    for (int fn = 0; fn < 4; fn++) {
        int cn = n0 + wn + fn * 8 + t * 2;
        float b0 = bias[cn], b1 = bias[cn + 1];
#pragma unroll
        for (int fm = 0; fm < 4; fm++) {
            int r0 = m0 + wm + fm * 16 + g;
            float2 v0 = make_float2(acc[fm][fn][0] + b0, acc[fm][fn][1] + b1);
            float2 v1 = make_float2(acc[fm][fn][2] + b0, acc[fm][fn][3] + b1);
            *(float2*)&Cm[(size_t)r0 * N + cn]       = v0;
            *(float2*)&Cm[(size_t)(r0 + 8) * N + cn] = v1;
        }
    }
}

// ---------------------------------------------------------------------------
// Sampling kernel: one block (256 threads) handles 4 queries.
//  - softmax attention weights per head (16 (l,p) entries per head)
//  - compute 4 bilinear corners per (l,p,h): compact row + fused weight
//  - float4 gathers of g_vproj head slices, accumulate into g_agg
// ---------------------------------------------------------------------------
#define QPB 4
__global__ __launch_bounds__(256)
void sample_kernel(const float* __restrict__ ref,
                   const int* __restrict__ batch_offsets)
{
    __shared__ float sL[QPB][128];
    __shared__ float hM[QPB][8];
    __shared__ float hR[QPB][8];
    __shared__ int   srow[QPB][128][4];
    __shared__ float swt [QPB][128][4];

    const int tid = threadIdx.x;
    const int q0  = blockIdx.x * QPB;
    const int boundary = batch_offsets[1];

    // load attention logits for 4 queries
#pragma unroll
    for (int j = tid; j < QPB * 128; j += 256)
        sL[j >> 7][j & 127] = g_awr[(size_t)(q0 + (j >> 7)) * 128 + (j & 127)];
    __syncthreads();

    // per-head softmax normalizers
    if (tid < QPB * 8) {
        int qi = tid >> 3, h = tid & 7;
        float m = -1e30f;
#pragma unroll
        for (int lp = 0; lp < 16; lp++) m = fmaxf(m, sL[qi][lp * 8 + h]);
        float s = 0.0f;
#pragma unroll
        for (int lp = 0; lp < 16; lp++) s += expf(sL[qi][lp * 8 + h] - m);
        hM[qi][h] = m;
        hR[qi][h] = 1.0f / s;
    }
    __syncthreads();

    // corner rows + fused weights (512 (q,i) tasks over 256 threads)
#pragma unroll
    for (int j = tid; j < QPB * 128; j += 256) {
        const int qi = j >> 7;
        const int i  = j & 127;
        const int q  = q0 + qi;
        const int h  = i & 7;
        const int lp = i >> 3;
        const int l  = lp >> 2;

        float aw = expf(sL[qi][i] - hM[qi][h]) * hR[qi][h];

        float rx = ref[q * 2 + 0];
        float ry = ref[q * 2 + 1];
        rx = fminf(fmaxf(rx, 0.0f), 1.0f);
        ry = fminf(fmaxf(ry, 0.0f), 1.0f);
        float isx = logf(fmaxf(rx, 1e-5f) / fmaxf(1.0f - rx, 1e-5f));
        float isy = logf(fmaxf(ry, 1e-5f) / fmaxf(1.0f - ry, 1e-5f));

        float ox = g_offs[(size_t)q * 256 + i * 2 + 0];
        float oy = g_offs[(size_t)q * 256 + i * 2 + 1];

        float locx = 1.0f / (1.0f + expf(-(isx + ox)));
        float locy = 1.0f / (1.0f + expf(-(isy + oy)));

        const int   Wl = HMAX_ >> l;          // square levels: H_l == W_l
        const float Wf = (float)Wl;
        float x = locx * Wf - 0.5f;
        float y = locy * Wf - 0.5f;

        float x0f = floorf(x), y0f = floorf(y);
        float wx1 = x - x0f, wx0 = 1.0f - wx1;
        float wy1 = y - y0f, wy0 = 1.0f - wy1;
        int x0 = (int)x0f, y0 = (int)y0f;

        int b = (q >= boundary) ? 1 : 0;
        int lbase = (l >= 1 ? 16384 : 0) + (l >= 2 ? 4096 : 0) + (l >= 3 ? 1024 : 0);
        int base = b * ROWS_PER_B + lbase;

        int   xs[2]  = {x0, x0 + 1};
        int   ys2[2] = {y0, y0 + 1};
        float wxs[2] = {wx0, wx1};
        float wys[2] = {wy0, wy1};

#pragma unroll
        for (int cy = 0; cy < 2; cy++) {
#pragma unroll
            for (int cx = 0; cx < 2; cx++) {
                int c  = cy * 2 + cx;
                int xi = xs[cx], yi = ys2[cy];
                bool valid = (xi >= 0) & (xi < Wl) & (yi >= 0) & (yi < Wl);
                srow[qi][i][c] = valid ? (base + yi * Wl + xi) : -1;
                swt [qi][i][c] = valid ? (aw * wys[cy] * wxs[cx]) : 0.0f;
            }
        }
    }
    __syncthreads();

    // accumulate: 64 threads per query: (head h, channel quad)
    const int qi   = tid >> 6;
    const int tq   = tid & 63;
    const int h    = tq >> 3;
    const int coff = h * DH_ + (tq & 7) * 4;
    const int q    = q0 + qi;

    float4 acc = make_float4(0.0f, 0.0f, 0.0f, 0.0f);
#pragma unroll
    for (int lp = 0; lp < 16; lp++) {
        const int i = lp * 8 + h;
#pragma unroll
        for (int c = 0; c < 4; c++) {
            int   r = srow[qi][i][c];
            float w = swt[qi][i][c];
            if (r >= 0) {
                float4 v = *(const float4*)&g_vproj[(size_t)r * C_ + coff];
                acc.x += w * v.x;
                acc.y += w * v.y;
                acc.z += w * v.z;
                acc.w += w * v.w;
            }
        }
    }
    *(float4*)&g_agg[(size_t)q * C_ + coff] = acc;
}

// ---------------------------------------------------------------------------
// kernel_launch
// ---------------------------------------------------------------------------
extern "C" void kernel_launch(void* const* d_in, const int* in_sizes, int n_in,
                              void* d_out, int out_size)
{
    const float* query  = (const float*)d_in[0];
    const float* ref    = (const float*)d_in[1];
    const float* values = (const float*)d_in[2];
    const float* W_so   = (const float*)d_in[3];
    const float* b_so   = (const float*)d_in[4];
    const float* W_aw   = (const float*)d_in[5];
    const float* b_aw   = (const float*)d_in[6];
    const float* W_v    = (const float*)d_in[7];
    const float* b_v    = (const float*)d_in[8];
    const float* W_o    = (const float*)d_in[9];
    const float* b_o    = (const float*)d_in[10];
    const int* batch_offsets = (const int*)d_in[11];
    // d_in[12]: spatial_shapes (fixed {128,64,32,16}^2, hardcoded)
    float* out = (float*)d_out;
    (void)in_sizes; (void)n_in; (void)out_size;

    float *vproj, *offs, *awr, *agg;
    cudaGetSymbolAddress((void**)&vproj, g_vproj);
    cudaGetSymbolAddress((void**)&offs,  g_offs);
    cudaGetSymbolAddress((void**)&awr,   g_awr);
    cudaGetSymbolAddress((void**)&agg,   g_agg);

    dim3 blk(256);

    // 1) project valid value rows: [43520,256] = values_valid @ W_v.T + b_v
    {
        dim3 grid(C_ / 128, NROWS / 128);
        gemm_tf32x3_nt<true><<<grid, blk>>>(values, W_v, b_v, vproj, NROWS, C_, C_);
    }
    // 2) sampling offsets: [8192,256] = query @ W_so.T + b_so
    {
        dim3 grid(256 / 128, Q_ / 128);
        gemm_tf32x3_nt<false><<<grid, blk>>>(query, W_so, b_so, offs, Q_, 256, C_);
    }
    // 3) attention-weight logits: [8192,128] = query @ W_aw.T + b_aw
    {
        dim3 grid(128 / 128, Q_ / 128);
        gemm_tf32x3_nt<false><<<grid, blk>>>(query, W_aw, b_aw, awr, Q_, 128, C_);
    }
    // 4) softmax + bilinear sampling + head aggregation
    sample_kernel<<<Q_ / QPB, blk>>>(ref, batch_offsets);

    // 5) output projection: out = agg @ W_o.T + b_o
    {
        dim3 grid(C_ / 128, Q_ / 128);
        gemm_tf32x3_nt<false><<<grid, blk>>>(agg, W_o, b_o, out, Q_, C_, C_);
    }
}

// round 4
// speedup vs baseline: 1.6197x; 1.3986x over previous
#include <cuda_runtime.h>
#include <cuda_bf16.h>
#include <cstdint>
#include <cstddef>

// ---------------------------------------------------------------------------
// Problem constants (fixed by the dataset)
// ---------------------------------------------------------------------------
#define Q_   8192
#define C_   256
#define BSZ  2
#define LVL  4
#define PPT  4
#define NH_  8
#define DH_  32
#define HMAX_ 128

// Compact valid-row layout: per batch, levels are 128^2, 64^2, 32^2, 16^2.
#define ROWS_PER_B 21760   // 16384+4096+1024+256
#define NROWS      43520   // 2 * ROWS_PER_B

// ---------------------------------------------------------------------------
// Scratch (device globals; no allocation allowed)
// ---------------------------------------------------------------------------
__device__ float g_vproj[(size_t)NROWS * C_];   // 44.6 MB: projected valid values
__device__ float g_offs [(size_t)Q_ * 256];     // sampling-offset raw proj
__device__ float g_awr  [(size_t)Q_ * 128];     // attention-weight logits
__device__ float g_agg  [(size_t)Q_ * C_];      // per-query aggregated heads

// ---------------------------------------------------------------------------
// Row mapping: compact row r -> offset into values[B,128,128,L,C]
// ---------------------------------------------------------------------------
__device__ __forceinline__ size_t map_a_row(int r) {
    int b  = r / ROWS_PER_B;
    int rr = r - b * ROWS_PER_B;
    int l, base, W;
    if (rr < 16384)      { l = 0; base = 0;     W = 128; }
    else if (rr < 20480) { l = 1; base = 16384; W = 64;  }
    else if (rr < 21504) { l = 2; base = 20480; W = 32;  }
    else                 { l = 3; base = 21504; W = 16;  }
    int idx = rr - base;
    int y = idx / W;
    int x = idx - y * W;
    return ((((size_t)b * HMAX_ + y) * HMAX_ + x) * LVL + l) * C_;
}

// ---------------------------------------------------------------------------
// precision helpers
// ---------------------------------------------------------------------------
__device__ __forceinline__ float to_tf32(float x) {
    float r;
    asm("cvt.rna.tf32.f32 %0, %1;" : "=f"(r) : "f"(x));
    return r;
}

__device__ __forceinline__ void mma_tf32(float* c, const uint32_t* a, const uint32_t* b) {
    asm volatile(
        "mma.sync.aligned.m16n8k8.row.col.f32.tf32.tf32.f32 "
        "{%0,%1,%2,%3}, {%4,%5,%6,%7}, {%8,%9}, {%0,%1,%2,%3};\n"
        : "+f"(c[0]), "+f"(c[1]), "+f"(c[2]), "+f"(c[3])
        : "r"(a[0]), "r"(a[1]), "r"(a[2]), "r"(a[3]), "r"(b[0]), "r"(b[1]));
}

__device__ __forceinline__ void mma_bf16(float* c, const uint32_t* a, const uint32_t* b) {
    asm volatile(
        "mma.sync.aligned.m16n8k16.row.col.f32.bf16.bf16.f32 "
        "{%0,%1,%2,%3}, {%4,%5,%6,%7}, {%8,%9}, {%0,%1,%2,%3};\n"
        : "+f"(c[0]), "+f"(c[1]), "+f"(c[2]), "+f"(c[3])
        : "r"(a[0]), "r"(a[1]), "r"(a[2]), "r"(a[3]), "r"(b[0]), "r"(b[1]));
}

// pack two floats into bf16x2 (e0 -> low 16, e1 -> high 16), round-to-nearest
__device__ __forceinline__ uint32_t pack_bf16x2(float e0, float e1) {
    uint32_t r;
    asm("cvt.rn.bf16x2.f32 %0, %1, %2;" : "=r"(r) : "f"(e1), "f"(e0));
    return r;
}

// ---------------------------------------------------------------------------
// 3xBF16 tensor-core GEMM (compensated): C = A @ B^T + bias
//   a = ah + al (bf16 split, al = round(a - ah)); acc += al*bh + ah*bl + ah*bh.
// Block tile 128x128, BK=16 (8 bf16x2 pair-rows), 256 threads (8 warps 2x4),
// warp tile 64x32 via m16n8k16. Requires M%128==0, N%128==0, K%16==0.
// ---------------------------------------------------------------------------
template <bool MAPPED>
__global__ __launch_bounds__(256)
void gemm_bf16x3_nt(const float* __restrict__ A, const float* __restrict__ Bm,
                    const float* __restrict__ bias, float* __restrict__ Cm,
                    int M, int N, int K)
{
    constexpr int BM = 128, BN = 128, BK = 16;
    constexpr int PR = BK / 2;        // 8 pair-rows of bf16x2
    constexpr int LDSU = 136;         // u32 stride, pad 8 -> conflict-free
    __shared__ uint32_t AsH[PR * LDSU];
    __shared__ uint32_t AsL[PR * LDSU];
    __shared__ uint32_t BsH[PR * LDSU];
    __shared__ uint32_t BsL[PR * LDSU];

    const int tid  = threadIdx.x;
    const int wid  = tid >> 5, lane = tid & 31;
    const int g    = lane >> 2, t = lane & 3;
    const int m0   = blockIdx.y * BM, n0 = blockIdx.x * BN;
    const int wm   = (wid & 1) * 64;
    const int wn   = (wid >> 1) * 32;

    // global->smem: 2 threads per row, 8 consecutive k each
    const int row  = tid >> 1;
    const int kseg = (tid & 1) * 8;
    size_t aoff = MAPPED ? map_a_row(m0 + row) : (size_t)(m0 + row) * K;
    const float* Ap = A + aoff + kseg;
    const float* Bp = Bm + (size_t)(n0 + row) * K + kseg;

    float acc[4][4][4];
#pragma unroll
    for (int i = 0; i < 4; i++)
#pragma unroll
        for (int j = 0; j < 4; j++)
#pragma unroll
            for (int c = 0; c < 4; c++) acc[i][j][c] = 0.0f;

    float4 va0 = *(const float4*)(Ap);
    float4 va1 = *(const float4*)(Ap + 4);
    float4 vb0 = *(const float4*)(Bp);
    float4 vb1 = *(const float4*)(Bp + 4);

    for (int k0 = 0; k0 < K; k0 += BK) {
        // split + store current tile
        {
            float ae[8] = {va0.x, va0.y, va0.z, va0.w, va1.x, va1.y, va1.z, va1.w};
            float be[8] = {vb0.x, vb0.y, vb0.z, vb0.w, vb1.x, vb1.y, vb1.z, vb1.w};
#pragma unroll
            for (int j = 0; j < 4; j++) {
                int pr = (kseg >> 1) + j;
                float a0 = ae[2 * j], a1 = ae[2 * j + 1];
                float b0 = be[2 * j], b1 = be[2 * j + 1];
                float a0h = __bfloat162float(__float2bfloat16_rn(a0));
                float a1h = __bfloat162float(__float2bfloat16_rn(a1));
                float b0h = __bfloat162float(__float2bfloat16_rn(b0));
                float b1h = __bfloat162float(__float2bfloat16_rn(b1));
                AsH[pr * LDSU + row] = pack_bf16x2(a0h, a1h);
                AsL[pr * LDSU + row] = pack_bf16x2(a0 - a0h, a1 - a1h);
                BsH[pr * LDSU + row] = pack_bf16x2(b0h, b1h);
                BsL[pr * LDSU + row] = pack_bf16x2(b0 - b0h, b1 - b1h);
            }
        }
        __syncthreads();

        // prefetch next tile into registers (overlaps with MMA phase)
        const bool more = (k0 + BK) < K;
        if (more) {
            va0 = *(const float4*)(Ap + k0 + BK);
            va1 = *(const float4*)(Ap + k0 + BK + 4);
            vb0 = *(const float4*)(Bp + k0 + BK);
            vb1 = *(const float4*)(Bp + k0 + BK + 4);
        }

        uint32_t afH[4][4], afL[4][4], bfH[4][2], bfL[4][2];
#pragma unroll
        for (int fm = 0; fm < 4; fm++) {
            int mb = wm + fm * 16 + g;
            int i0 = t * LDSU + mb;
            int i1 = (t + 4) * LDSU + mb;
            afH[fm][0] = AsH[i0];     afL[fm][0] = AsL[i0];
            afH[fm][1] = AsH[i0 + 8]; afL[fm][1] = AsL[i0 + 8];
            afH[fm][2] = AsH[i1];     afL[fm][2] = AsL[i1];
            afH[fm][3] = AsH[i1 + 8]; afL[fm][3] = AsL[i1 + 8];
        }
#pragma unroll
        for (int fn = 0; fn < 4; fn++) {
            int nb = wn + fn * 8 + g;
            bfH[fn][0] = BsH[t * LDSU + nb];
            bfL[fn][0] = BsL[t * LDSU + nb];
            bfH[fn][1] = BsH[(t + 4) * LDSU + nb];
            bfL[fn][1] = BsL[(t + 4) * LDSU + nb];
        }
#pragma unroll
        for (int fm = 0; fm < 4; fm++)
#pragma unroll
            for (int fn = 0; fn < 4; fn++) {
                mma_bf16(acc[fm][fn], afL[fm], bfH[fn]);
                mma_bf16(acc[fm][fn], afH[fm], bfL[fn]);
                mma_bf16(acc[fm][fn], afH[fm], bfH[fn]);
            }
        __syncthreads();
    }

    // epilogue: bias add + float2 stores
#pragma unroll
    for (int fn = 0; fn < 4; fn++) {
        int cn = n0 + wn + fn * 8 + t * 2;
        float b0 = bias[cn], b1 = bias[cn + 1];
#pragma unroll
        for (int fm = 0; fm < 4; fm++) {
            int r0 = m0 + wm + fm * 16 + g;
            float2 v0 = make_float2(acc[fm][fn][0] + b0, acc[fm][fn][1] + b1);
            float2 v1 = make_float2(acc[fm][fn][2] + b0, acc[fm][fn][3] + b1);
            *(float2*)&Cm[(size_t)r0 * N + cn]       = v0;
            *(float2*)&Cm[(size_t)(r0 + 8) * N + cn] = v1;
        }
    }
}

// ---------------------------------------------------------------------------
// 3xTF32 tensor-core GEMM (fp32-accurate) — used only for the sampling-offset
// projection, whose error is amplified through sigmoid -> pixel coords.
// ---------------------------------------------------------------------------
template <bool MAPPED>
__global__ __launch_bounds__(256)
void gemm_tf32x3_nt(const float* __restrict__ A, const float* __restrict__ Bm,
                    const float* __restrict__ bias, float* __restrict__ Cm,
                    int M, int N, int K)
{
    constexpr int BM = 128, BN = 128, BK = 16, LDS = 136;
    __shared__ float AsH[BK * LDS];
    __shared__ float AsL[BK * LDS];
    __shared__ float BsH[BK * LDS];
    __shared__ float BsL[BK * LDS];

    const int tid  = threadIdx.x;
    const int wid  = tid >> 5, lane = tid & 31;
    const int g    = lane >> 2, t = lane & 3;
    const int m0   = blockIdx.y * BM, n0 = blockIdx.x * BN;
    const int wm   = (wid & 1) * 64;
    const int wn   = (wid >> 1) * 32;

    const int row  = tid >> 1;
    const int kseg = (tid & 1) * 8;
    size_t aoff = MAPPED ? map_a_row(m0 + row) : (size_t)(m0 + row) * K;
    const float* Ap = A + aoff + kseg;
    const float* Bp = Bm + (size_t)(n0 + row) * K + kseg;

    float acc[4][4][4];
#pragma unroll
    for (int i = 0; i < 4; i++)
#pragma unroll
        for (int j = 0; j < 4; j++)
#pragma unroll
            for (int c = 0; c < 4; c++) acc[i][j][c] = 0.0f;

    for (int k0 = 0; k0 < K; k0 += BK) {
#pragma unroll
        for (int j = 0; j < 2; j++) {
            float4 va = *(const float4*)(Ap + k0 + j * 4);
            float4 vb = *(const float4*)(Bp + k0 + j * 4);
            int kk = kseg + j * 4;
            float av[4] = {va.x, va.y, va.z, va.w};
            float bv[4] = {vb.x, vb.y, vb.z, vb.w};
#pragma unroll
            for (int e = 0; e < 4; e++) {
                float ah = to_tf32(av[e]);
                float bh = to_tf32(bv[e]);
                AsH[(kk + e) * LDS + row] = ah;
                AsL[(kk + e) * LDS + row] = to_tf32(av[e] - ah);
                BsH[(kk + e) * LDS + row] = bh;
                BsL[(kk + e) * LDS + row] = to_tf32(bv[e] - bh);
            }
        }
        __syncthreads();

        const uint32_t* AsHu = (const uint32_t*)AsH;
        const uint32_t* AsLu = (const uint32_t*)AsL;
        const uint32_t* BsHu = (const uint32_t*)BsH;
        const uint32_t* BsLu = (const uint32_t*)BsL;
#pragma unroll
        for (int ks = 0; ks < BK; ks += 8) {
            uint32_t afH[4][4], afL[4][4], bfH[4][2], bfL[4][2];
#pragma unroll
            for (int fm = 0; fm < 4; fm++) {
                int mb = wm + fm * 16 + g;
                int i0 = (ks + t) * LDS + mb;
                int i1 = (ks + t + 4) * LDS + mb;
                afH[fm][0] = AsHu[i0];     afL[fm][0] = AsLu[i0];
                afH[fm][1] = AsHu[i0 + 8]; afL[fm][1] = AsLu[i0 + 8];
                afH[fm][2] = AsHu[i1];     afL[fm][2] = AsLu[i1];
                afH[fm][3] = AsHu[i1 + 8]; afL[fm][3] = AsLu[i1 + 8];
            }
#pragma unroll
            for (int fn = 0; fn < 4; fn++) {
                int nb = wn + fn * 8 + g;
                int i0 = (ks + t) * LDS + nb;
                int i1 = (ks + t + 4) * LDS + nb;
                bfH[fn][0] = BsHu[i0]; bfL[fn][0] = BsLu[i0];
                bfH[fn][1] = BsHu[i1]; bfL[fn][1] = BsLu[i1];
            }
#pragma unroll
            for (int fm = 0; fm < 4; fm++)
#pragma unroll
                for (int fn = 0; fn < 4; fn++) {
                    mma_tf32(acc[fm][fn], afL[fm], bfH[fn]);
                    mma_tf32(acc[fm][fn], afH[fm], bfL[fn]);
                    mma_tf32(acc[fm][fn], afH[fm], bfH[fn]);
                }
        }
        __syncthreads();
    }

#pragma unroll
    for (int fn = 0; fn < 4; fn++) {
        int cn = n0 + wn + fn * 8 + t * 2;
        float b0 = bias[cn], b1 = bias[cn + 1];
#pragma unroll
        for (int fm = 0; fm < 4; fm++) {
            int r0 = m0 + wm + fm * 16 + g;
            float2 v0 = make_float2(acc[fm][fn][0] + b0, acc[fm][fn][1] + b1);
            float2 v1 = make_float2(acc[fm][fn][2] + b0, acc[fm][fn][3] + b1);
            *(float2*)&Cm[(size_t)r0 * N + cn]       = v0;
            *(float2*)&Cm[(size_t)(r0 + 8) * N + cn] = v1;
        }
    }
}

// ---------------------------------------------------------------------------
// Sampling kernel: one block (256 threads) handles 4 queries.
// ---------------------------------------------------------------------------
#define QPB 4
__global__ __launch_bounds__(256)
void sample_kernel(const float* __restrict__ ref,
                   const int* __restrict__ batch_offsets)
{
    __shared__ float sL[QPB][128];
    __shared__ float hM[QPB][8];
    __shared__ float hR[QPB][8];
    __shared__ __align__(16) int   srow[QPB][128][4];
    __shared__ __align__(16) float swt [QPB][128][4];

    const int tid = threadIdx.x;
    const int q0  = blockIdx.x * QPB;
    const int boundary = batch_offsets[1];

#pragma unroll
    for (int j = tid; j < QPB * 128; j += 256)
        sL[j >> 7][j & 127] = g_awr[(size_t)(q0 + (j >> 7)) * 128 + (j & 127)];
    __syncthreads();

    if (tid < QPB * 8) {
        int qi = tid >> 3, h = tid & 7;
        float m = -1e30f;
#pragma unroll
        for (int lp = 0; lp < 16; lp++) m = fmaxf(m, sL[qi][lp * 8 + h]);
        float s = 0.0f;
#pragma unroll
        for (int lp = 0; lp < 16; lp++) s += expf(sL[qi][lp * 8 + h] - m);
        hM[qi][h] = m;
        hR[qi][h] = 1.0f / s;
    }
    __syncthreads();

#pragma unroll
    for (int j = tid; j < QPB * 128; j += 256) {
        const int qi = j >> 7;
        const int i  = j & 127;
        const int q  = q0 + qi;
        const int h  = i & 7;
        const int lp = i >> 3;
        const int l  = lp >> 2;

        float aw = expf(sL[qi][i] - hM[qi][h]) * hR[qi][h];

        float rx = ref[q * 2 + 0];
        float ry = ref[q * 2 + 1];
        rx = fminf(fmaxf(rx, 0.0f), 1.0f);
        ry = fminf(fmaxf(ry, 0.0f), 1.0f);
        float isx = logf(fmaxf(rx, 1e-5f) / fmaxf(1.0f - rx, 1e-5f));
        float isy = logf(fmaxf(ry, 1e-5f) / fmaxf(1.0f - ry, 1e-5f));

        float ox = g_offs[(size_t)q * 256 + i * 2 + 0];
        float oy = g_offs[(size_t)q * 256 + i * 2 + 1];

        float locx = 1.0f / (1.0f + expf(-(isx + ox)));
        float locy = 1.0f / (1.0f + expf(-(isy + oy)));

        const int   Wl = HMAX_ >> l;
        const float Wf = (float)Wl;
        float x = locx * Wf - 0.5f;
        float y = locy * Wf - 0.5f;

        float x0f = floorf(x), y0f = floorf(y);
        float wx1 = x - x0f, wx0 = 1.0f - wx1;
        float wy1 = y - y0f, wy0 = 1.0f - wy1;
        int x0 = (int)x0f, y0 = (int)y0f;

        int b = (q >= boundary) ? 1 : 0;
        int lbase = (l >= 1 ? 16384 : 0) + (l >= 2 ? 4096 : 0) + (l >= 3 ? 1024 : 0);
        int base = b * ROWS_PER_B + lbase;

        int   xs[2]  = {x0, x0 + 1};
        int   ys2[2] = {y0, y0 + 1};
        float wxs[2] = {wx0, wx1};
        float wys[2] = {wy0, wy1};

#pragma unroll
        for (int cy = 0; cy < 2; cy++) {
#pragma unroll
            for (int cx = 0; cx < 2; cx++) {
                int c  = cy * 2 + cx;
                int xi = xs[cx], yi = ys2[cy];
                bool valid = (xi >= 0) & (xi < Wl) & (yi >= 0) & (yi < Wl);
                srow[qi][i][c] = valid ? (base + yi * Wl + xi) : -1;
                swt [qi][i][c] = valid ? (aw * wys[cy] * wxs[cx]) : 0.0f;
            }
        }
    }
    __syncthreads();

    // accumulate: 64 threads per query: (head h, channel quad)
    const int qi   = tid >> 6;
    const int tq   = tid & 63;
    const int h    = tq >> 3;
    const int coff = h * DH_ + (tq & 7) * 4;
    const int q    = q0 + qi;

    float4 acc = make_float4(0.0f, 0.0f, 0.0f, 0.0f);
#pragma unroll
    for (int lp = 0; lp < 16; lp++) {
        const int i = lp * 8 + h;
        int4   r4 = *(const int4*)  &srow[qi][i][0];
        float4 w4 = *(const float4*)&swt [qi][i][0];
        int   rr[4] = {r4.x, r4.y, r4.z, r4.w};
        float ww[4] = {w4.x, w4.y, w4.z, w4.w};
#pragma unroll
        for (int c = 0; c < 4; c++) {
            if (rr[c] >= 0) {
                float4 v = *(const float4*)&g_vproj[(size_t)rr[c] * C_ + coff];
                acc.x += ww[c] * v.x;
                acc.y += ww[c] * v.y;
                acc.z += ww[c] * v.z;
                acc.w += ww[c] * v.w;
            }
        }
    }
    *(float4*)&g_agg[(size_t)q * C_ + coff] = acc;
}

// ---------------------------------------------------------------------------
// kernel_launch
// ---------------------------------------------------------------------------
extern "C" void kernel_launch(void* const* d_in, const int* in_sizes, int n_in,
                              void* d_out, int out_size)
{
    const float* query  = (const float*)d_in[0];
    const float* ref    = (const float*)d_in[1];
    const float* values = (const float*)d_in[2];
    const float* W_so   = (const float*)d_in[3];
    const float* b_so   = (const float*)d_in[4];
    const float* W_aw   = (const float*)d_in[5];
    const float* b_aw   = (const float*)d_in[6];
    const float* W_v    = (const float*)d_in[7];
    const float* b_v    = (const float*)d_in[8];
    const float* W_o    = (const float*)d_in[9];
    const float* b_o    = (const float*)d_in[10];
    const int* batch_offsets = (const int*)d_in[11];
    // d_in[12]: spatial_shapes (fixed {128,64,32,16}^2, hardcoded)
    float* out = (float*)d_out;
    (void)in_sizes; (void)n_in; (void)out_size;

    float *vproj, *offs, *awr, *agg;
    cudaGetSymbolAddress((void**)&vproj, g_vproj);
    cudaGetSymbolAddress((void**)&offs,  g_offs);
    cudaGetSymbolAddress((void**)&awr,   g_awr);
    cudaGetSymbolAddress((void**)&agg,   g_agg);

    dim3 blk(256);

    // 1) project valid value rows: [43520,256] = values_valid @ W_v.T + b_v (bf16x3)
    {
        dim3 grid(C_ / 128, NROWS / 128);
        gemm_bf16x3_nt<true><<<grid, blk>>>(values, W_v, b_v, vproj, NROWS, C_, C_);
    }
    // 2) sampling offsets: [8192,256] = query @ W_so.T + b_so (tf32x3, error-amplified path)
    {
        dim3 grid(256 / 128, Q_ / 128);
        gemm_tf32x3_nt<false><<<grid, blk>>>(query, W_so, b_so, offs, Q_, 256, C_);
    }
    // 3) attention-weight logits: [8192,128] = query @ W_aw.T + b_aw (bf16x3)
    {
        dim3 grid(128 / 128, Q_ / 128);
        gemm_bf16x3_nt<false><<<grid, blk>>>(query, W_aw, b_aw, awr, Q_, 128, C_);
    }
    // 4) softmax + bilinear sampling + head aggregation
    sample_kernel<<<Q_ / QPB, blk>>>(ref, batch_offsets);

    // 5) output projection: out = agg @ W_o.T + b_o (bf16x3)
    {
        dim3 grid(C_ / 128, Q_ / 128);
        gemm_bf16x3_nt<false><<<grid, blk>>>(agg, W_o, b_o, out, Q_, C_, C_);
    }
}

// round 6
// speedup vs baseline: 1.7212x; 1.0627x over previous
#include <cuda_runtime.h>
#include <cuda_bf16.h>
#include <cstdint>
#include <cstddef>

// ---------------------------------------------------------------------------
// Problem constants (fixed by the dataset)
// ---------------------------------------------------------------------------
#define Q_   8192
#define C_   256
#define LVL  4
#define NH_  8
#define DH_  32
#define HMAX_ 128

#define ROWS_PER_B 21760   // 16384+4096+1024+256
#define NROWS      43520   // 2 * ROWS_PER_B

// ---------------------------------------------------------------------------
// Scratch (device globals; no allocation allowed)
// ---------------------------------------------------------------------------
__device__ float g_vproj[(size_t)NROWS * C_];   // projected valid values
__device__ float g_offs [(size_t)Q_ * 256];     // sampling-offset raw proj
__device__ float g_awr  [(size_t)Q_ * 128];     // attention-weight logits
__device__ float g_agg  [(size_t)Q_ * C_];      // per-query aggregated heads

// Pre-split weight images: per (k-block 32, n-block 128): [hi 10240B | lo 10240B]
// row layout: n_local (0..127) x stride 80B, 16 k-pairs (4B each) at bytes 0..63.
__device__ __align__(16) char g_wv_img [327680];   // 256 rows: 8 kb x 2 nb x 20480
__device__ __align__(16) char g_wso_img[327680];
__device__ __align__(16) char g_wo_img [327680];
__device__ __align__(16) char g_waw_img[163840];   // 128 rows: 8 kb x 1 nb x 20480

// ---------------------------------------------------------------------------
// Row mapping: compact row r -> offset into values[B,128,128,L,C]
// ---------------------------------------------------------------------------
__device__ __forceinline__ size_t map_a_row(int r) {
    int b  = r / ROWS_PER_B;
    int rr = r - b * ROWS_PER_B;
    int l, base, W;
    if (rr < 16384)      { l = 0; base = 0;     W = 128; }
    else if (rr < 20480) { l = 1; base = 16384; W = 64;  }
    else if (rr < 21504) { l = 2; base = 20480; W = 32;  }
    else                 { l = 3; base = 21504; W = 16;  }
    int idx = rr - base;
    int y = idx / W;
    int x = idx - y * W;
    return ((((size_t)b * HMAX_ + y) * HMAX_ + x) * LVL + l) * C_;
}

// ---------------------------------------------------------------------------
// helpers
// ---------------------------------------------------------------------------
__device__ __forceinline__ uint32_t smem_u32(const void* p) {
    uint32_t a;
    asm("{ .reg .u64 t; cvta.to.shared.u64 t, %1; cvt.u32.u64 %0, t; }"
        : "=r"(a) : "l"(p));
    return a;
}

__device__ __forceinline__ uint32_t pack_bf16x2(float e0, float e1) {
    uint32_t r;
    asm("cvt.rn.bf16x2.f32 %0, %1, %2;" : "=r"(r) : "f"(e1), "f"(e0));
    return r;
}

__device__ __forceinline__ float bf_hi(float x) {
    return __bfloat162float(__float2bfloat16_rn(x));
}

__device__ __forceinline__ void mma_bf16(float* c, const uint32_t* a, const uint32_t* b) {
    asm volatile(
        "mma.sync.aligned.m16n8k16.row.col.f32.bf16.bf16.f32 "
        "{%0,%1,%2,%3}, {%4,%5,%6,%7}, {%8,%9}, {%0,%1,%2,%3};\n"
        : "+f"(c[0]), "+f"(c[1]), "+f"(c[2]), "+f"(c[3])
        : "r"(a[0]), "r"(a[1]), "r"(a[2]), "r"(a[3]), "r"(b[0]), "r"(b[1]));
}

#define LDSM4(r, a) \
    asm volatile("ldmatrix.sync.aligned.m8n8.x4.shared.b16 {%0,%1,%2,%3}, [%4];" \
        : "=r"((r)[0]), "=r"((r)[1]), "=r"((r)[2]), "=r"((r)[3]) : "r"(a))

// ---------------------------------------------------------------------------
// Weight prep: W (R x 256 fp32, row-major, nn.Linear layout) -> hi/lo bf16
// image blobs in the padded k-contiguous layout described above.
// ---------------------------------------------------------------------------
__global__ void prep_w(const float* __restrict__ W, char* __restrict__ img, int R)
{
    int idx = blockIdx.x * 256 + threadIdx.x;   // one thread per (row n, k-pair)
    if (idx >= R * 128) return;
    int n = idx >> 7, p = idx & 127;
    int k = p * 2;
    int kb = k >> 5, pl = (k & 31) >> 1;
    int nb = n >> 7, nl = n & 127;
    float a = W[(size_t)n * 256 + k];
    float b = W[(size_t)n * 256 + k + 1];
    float ah = bf_hi(a), bh = bf_hi(b);
    char* blob = img + (size_t)(kb * (R >> 7) + nb) * 20480;
    uint32_t off = nl * 80 + pl * 4;
    *(uint32_t*)(blob + off)         = pack_bf16x2(ah, bh);
    *(uint32_t*)(blob + 10240 + off) = pack_bf16x2(a - ah, b - bh);
}

// ---------------------------------------------------------------------------
// bf16x3 compensated GEMM on mma.sync with ldmatrix fragment loads.
//   C[128 x 128] per CTA = A[128 x 256] @ B[128 x 256]^T + bias
//   ASRC: 0 = plain row-major fp32 A, 1 = mapped values rows.
//   B from pre-split image blobs. 256 threads, 8 warps as 2(m) x 4(n),
//   warp tile 64x32, BK=32 per stage (8 stages over K=256).
// smem: AH@0 AL@10240 BH@20480 BL@30720 (rows: stride 80B, 64B data)
// ---------------------------------------------------------------------------
template <int ASRC>
__global__ void __launch_bounds__(256)
gemm_bf3(const float* __restrict__ A, const char* __restrict__ Bimg,
         const float* __restrict__ bias, float* __restrict__ Cm,
         int M, int N)
{
    __shared__ __align__(16) char sm[40960];

    const int tid = threadIdx.x, wid = tid >> 5, lane = tid & 31;
    const int g = lane >> 2, t = lane & 3;
    const int m0 = blockIdx.x * 128, n0 = blockIdx.y * 128;
    const int wm = (wid & 1) * 64, wn = (wid >> 1) * 32;
    const int NBLK = N >> 7;

    // A loading: 2 threads per row, 16 consecutive k each (within BK=32)
    const int r    = tid >> 1;
    const int half = tid & 1;
    size_t aoff = ASRC ? map_a_row(m0 + r) : (size_t)(m0 + r) * 256;
    const float* Ap = A + aoff + half * 16;

    const uint32_t sbase = smem_u32(sm);

    float acc[4][4][4];
#pragma unroll
    for (int i = 0; i < 4; i++)
#pragma unroll
        for (int j = 0; j < 4; j++)
#pragma unroll
            for (int c = 0; c < 4; c++) acc[i][j][c] = 0.0f;

    // stage-0 prefetch
    float4 pa[4];
    uint4  pb[5];
#pragma unroll
    for (int j = 0; j < 4; j++) pa[j] = *(const float4*)(Ap + j * 4);
    {
        const uint4* src = (const uint4*)(Bimg + (size_t)blockIdx.y * 20480);
#pragma unroll
        for (int j = 0; j < 5; j++) pb[j] = src[tid + 256 * j];
    }

    for (int kb = 0; kb < 8; kb++) {
        // ---- store A (convert fp32 -> bf16 hi/lo) ----
        {
            char* AH = sm + r * 80 + half * 32;
            char* AL = AH + 10240;
#pragma unroll
            for (int j = 0; j < 4; j++) {
                float4 v = pa[j];
                float xh = bf_hi(v.x), yh = bf_hi(v.y);
                float zh = bf_hi(v.z), wh = bf_hi(v.w);
                *(uint32_t*)(AH + j * 8)     = pack_bf16x2(xh, yh);
                *(uint32_t*)(AH + j * 8 + 4) = pack_bf16x2(zh, wh);
                *(uint32_t*)(AL + j * 8)     = pack_bf16x2(v.x - xh, v.y - yh);
                *(uint32_t*)(AL + j * 8 + 4) = pack_bf16x2(v.z - zh, v.w - wh);
            }
        }
        // ---- store B (already split, linear copy) ----
        {
            uint4* dst = (uint4*)(sm + 20480);
#pragma unroll
            for (int j = 0; j < 5; j++) dst[tid + 256 * j] = pb[j];
        }
        __syncthreads();

        // ---- prefetch next stage ----
        if (kb < 7) {
#pragma unroll
            for (int j = 0; j < 4; j++)
                pa[j] = *(const float4*)(Ap + (kb + 1) * 32 + j * 4);
            const uint4* src = (const uint4*)(Bimg +
                (size_t)((kb + 1) * NBLK + blockIdx.y) * 20480);
#pragma unroll
            for (int j = 0; j < 5; j++) pb[j] = src[tid + 256 * j];
        }

        // ---- MMA phase ----
        const int rr16 = lane & 15;               // row within 16-row frag
        const int chi  = ((lane >> 4) & 1) * 16;  // +16B for k upper half
#pragma unroll
        for (int ks = 0; ks < 2; ks++) {
            const int cb = ks * 32 + chi;
            uint32_t aH[4][4], aL[4][4];
#pragma unroll
            for (int fm = 0; fm < 4; fm++) {
                uint32_t ad = sbase + (wm + fm * 16 + rr16) * 80 + cb;
                LDSM4(aH[fm], ad);
                LDSM4(aL[fm], ad + 10240);
            }
            uint32_t bH[2][4], bL[2][4];
#pragma unroll
            for (int fp = 0; fp < 2; fp++) {
                uint32_t bd = sbase + 20480 + (wn + fp * 16 + rr16) * 80 + cb;
                LDSM4(bH[fp], bd);
                LDSM4(bL[fp], bd + 10240);
            }
#pragma unroll
            for (int fm = 0; fm < 4; fm++)
#pragma unroll
                for (int fn = 0; fn < 4; fn++) {
                    const int fp = fn >> 1, o = fn & 1;
                    uint32_t bh2[2] = {bH[fp][o], bH[fp][o + 2]};
                    uint32_t bl2[2] = {bL[fp][o], bL[fp][o + 2]};
                    mma_bf16(acc[fm][fn], aL[fm], bh2);   // AL*BH
                    mma_bf16(acc[fm][fn], aH[fm], bl2);   // AH*BL
                    mma_bf16(acc[fm][fn], aH[fm], bh2);   // AH*BH
                }
        }
        __syncthreads();
    }

    // ---- epilogue: bias add + float2 stores ----
#pragma unroll
    for (int fn = 0; fn < 4; fn++) {
        int cn = n0 + wn + fn * 8 + t * 2;
        float b0 = bias[cn], b1 = bias[cn + 1];
#pragma unroll
        for (int fm = 0; fm < 4; fm++) {
            int r0 = m0 + wm + fm * 16 + g;
            float2 v0 = make_float2(acc[fm][fn][0] + b0, acc[fm][fn][1] + b1);
            float2 v1 = make_float2(acc[fm][fn][2] + b0, acc[fm][fn][3] + b1);
            *(float2*)&Cm[(size_t)r0 * N + cn]       = v0;
            *(float2*)&Cm[(size_t)(r0 + 8) * N + cn] = v1;
        }
    }
}

// ---------------------------------------------------------------------------
// Sampling kernel: one block (256 threads) handles 4 queries.
// ---------------------------------------------------------------------------
#define QPB 4
__global__ __launch_bounds__(256)
void sample_kernel(const float* __restrict__ ref,
                   const int* __restrict__ batch_offsets)
{
    __shared__ float sL[QPB][128];
    __shared__ float hM[QPB][8];
    __shared__ float hR[QPB][8];
    __shared__ __align__(16) int   srow[QPB][128][4];
    __shared__ __align__(16) float swt [QPB][128][4];

    const int tid = threadIdx.x;
    const int q0  = blockIdx.x * QPB;
    const int boundary = batch_offsets[1];

#pragma unroll
    for (int j = tid; j < QPB * 128; j += 256)
        sL[j >> 7][j & 127] = g_awr[(size_t)(q0 + (j >> 7)) * 128 + (j & 127)];
    __syncthreads();

    if (tid < QPB * 8) {
        int qi = tid >> 3, h = tid & 7;
        float m = -1e30f;
#pragma unroll
        for (int lp = 0; lp < 16; lp++) m = fmaxf(m, sL[qi][lp * 8 + h]);
        float s = 0.0f;
#pragma unroll
        for (int lp = 0; lp < 16; lp++) s += expf(sL[qi][lp * 8 + h] - m);
        hM[qi][h] = m;
        hR[qi][h] = 1.0f / s;
    }
    __syncthreads();

#pragma unroll
    for (int j = tid; j < QPB * 128; j += 256) {
        const int qi = j >> 7;
        const int i  = j & 127;
        const int q  = q0 + qi;
        const int h  = i & 7;
        const int lp = i >> 3;
        const int l  = lp >> 2;

        float aw = expf(sL[qi][i] - hM[qi][h]) * hR[qi][h];

        float rx = ref[q * 2 + 0];
        float ry = ref[q * 2 + 1];
        rx = fminf(fmaxf(rx, 0.0f), 1.0f);
        ry = fminf(fmaxf(ry, 0.0f), 1.0f);
        float isx = logf(fmaxf(rx, 1e-5f) / fmaxf(1.0f - rx, 1e-5f));
        float isy = logf(fmaxf(ry, 1e-5f) / fmaxf(1.0f - ry, 1e-5f));

        float ox = g_offs[(size_t)q * 256 + i * 2 + 0];
        float oy = g_offs[(size_t)q * 256 + i * 2 + 1];

        float locx = 1.0f / (1.0f + expf(-(isx + ox)));
        float locy = 1.0f / (1.0f + expf(-(isy + oy)));

        const int   Wl = HMAX_ >> l;
        const float Wf = (float)Wl;
        float x = locx * Wf - 0.5f;
        float y = locy * Wf - 0.5f;

        float x0f = floorf(x), y0f = floorf(y);
        float wx1 = x - x0f, wx0 = 1.0f - wx1;
        float wy1 = y - y0f, wy0 = 1.0f - wy1;
        int x0 = (int)x0f, y0 = (int)y0f;

        int b = (q >= boundary) ? 1 : 0;
        int lbase = (l >= 1 ? 16384 : 0) + (l >= 2 ? 4096 : 0) + (l >= 3 ? 1024 : 0);
        int base = b * ROWS_PER_B + lbase;

        int   xs[2]  = {x0, x0 + 1};
        int   ys2[2] = {y0, y0 + 1};
        float wxs[2] = {wx0, wx1};
        float wys[2] = {wy0, wy1};

#pragma unroll
        for (int cy = 0; cy < 2; cy++) {
#pragma unroll
            for (int cx = 0; cx < 2; cx++) {
                int c  = cy * 2 + cx;
                int xi = xs[cx], yi = ys2[cy];
                bool valid = (xi >= 0) & (xi < Wl) & (yi >= 0) & (yi < Wl);
                srow[qi][i][c] = valid ? (base + yi * Wl + xi) : -1;
                swt [qi][i][c] = valid ? (aw * wys[cy] * wxs[cx]) : 0.0f;
            }
        }
    }
    __syncthreads();

    const int qi   = tid >> 6;
    const int tq   = tid & 63;
    const int h    = tq >> 3;
    const int coff = h * DH_ + (tq & 7) * 4;
    const int q    = q0 + qi;

    float4 acc = make_float4(0.0f, 0.0f, 0.0f, 0.0f);
#pragma unroll
    for (int lp = 0; lp < 16; lp++) {
        const int i = lp * 8 + h;
        int4   r4 = *(const int4*)  &srow[qi][i][0];
        float4 w4 = *(const float4*)&swt [qi][i][0];
        int   rr[4] = {r4.x, r4.y, r4.z, r4.w};
        float ww[4] = {w4.x, w4.y, w4.z, w4.w};
#pragma unroll
        for (int c = 0; c < 4; c++) {
            if (rr[c] >= 0) {
                float4 v = *(const float4*)&g_vproj[(size_t)rr[c] * C_ + coff];
                acc.x += ww[c] * v.x;
                acc.y += ww[c] * v.y;
                acc.z += ww[c] * v.z;
                acc.w += ww[c] * v.w;
            }
        }
    }
    *(float4*)&g_agg[(size_t)q * C_ + coff] = acc;
}

// ---------------------------------------------------------------------------
// kernel_launch
// ---------------------------------------------------------------------------
extern "C" void kernel_launch(void* const* d_in, const int* in_sizes, int n_in,
                              void* d_out, int out_size)
{
    const float* query  = (const float*)d_in[0];
    const float* ref    = (const float*)d_in[1];
    const float* values = (const float*)d_in[2];
    const float* W_so   = (const float*)d_in[3];
    const float* b_so   = (const float*)d_in[4];
    const float* W_aw   = (const float*)d_in[5];
    const float* b_aw   = (const float*)d_in[6];
    const float* W_v    = (const float*)d_in[7];
    const float* b_v    = (const float*)d_in[8];
    const float* W_o    = (const float*)d_in[9];
    const float* b_o    = (const float*)d_in[10];
    const int* batch_offsets = (const int*)d_in[11];
    float* out = (float*)d_out;
    (void)in_sizes; (void)n_in; (void)out_size;

    float *vproj, *offs, *awr, *agg;
    char *wv, *wso, *wo, *waw;
    cudaGetSymbolAddress((void**)&vproj, g_vproj);
    cudaGetSymbolAddress((void**)&offs,  g_offs);
    cudaGetSymbolAddress((void**)&awr,   g_awr);
    cudaGetSymbolAddress((void**)&agg,   g_agg);
    cudaGetSymbolAddress((void**)&wv,    g_wv_img);
    cudaGetSymbolAddress((void**)&wso,   g_wso_img);
    cudaGetSymbolAddress((void**)&wo,    g_wo_img);
    cudaGetSymbolAddress((void**)&waw,   g_waw_img);

    // 0) split weights into hi/lo images
    prep_w<<<128, 256>>>(W_v,  wv,  256);
    prep_w<<<128, 256>>>(W_so, wso, 256);
    prep_w<<<128, 256>>>(W_o,  wo,  256);
    prep_w<<<64,  256>>>(W_aw, waw, 128);

    // 1) vproj = values_valid @ W_v^T + b_v   [43520 x 256]
    {
        dim3 grid(NROWS / 128, 2);
        gemm_bf3<1><<<grid, 256>>>(values, wv, b_v, vproj, NROWS, 256);
    }
    // 2) offs = query @ W_so^T + b_so         [8192 x 256]
    {
        dim3 grid(Q_ / 128, 2);
        gemm_bf3<0><<<grid, 256>>>(query, wso, b_so, offs, Q_, 256);
    }
    // 3) awr = query @ W_aw^T + b_aw          [8192 x 128]
    {
        dim3 grid(Q_ / 128, 1);
        gemm_bf3<0><<<grid, 256>>>(query, waw, b_aw, awr, Q_, 128);
    }
    // 4) softmax + bilinear sampling + head aggregation
    sample_kernel<<<Q_ / QPB, 256>>>(ref, batch_offsets);
    // 5) out = agg @ W_o^T + b_o              [8192 x 256]
    {
        dim3 grid(Q_ / 128, 2);
        gemm_bf3<0><<<grid, 256>>>(agg, wo, b_o, out, Q_, 256);
    }
}

// round 7
// speedup vs baseline: 1.7989x; 1.0451x over previous
#include <cuda_runtime.h>
#include <cuda_bf16.h>
#include <cuda_fp16.h>
#include <cstdint>
#include <cstddef>

// ---------------------------------------------------------------------------
// Problem constants (fixed by the dataset)
// ---------------------------------------------------------------------------
#define Q_   8192
#define C_   256
#define LVL  4
#define NH_  8
#define DH_  32
#define HMAX_ 128

#define ROWS_PER_B 21760   // 16384+4096+1024+256
#define NROWS      43520   // 2 * ROWS_PER_B

// ---------------------------------------------------------------------------
// Scratch (device globals; no allocation allowed)
// ---------------------------------------------------------------------------
__device__ __half g_vproj[(size_t)NROWS * C_];  // projected valid values (fp16)
__device__ float g_offs [(size_t)Q_ * 256];     // sampling-offset raw proj
__device__ float g_awr  [(size_t)Q_ * 128];     // attention-weight logits
__device__ float g_agg  [(size_t)Q_ * C_];      // per-query aggregated heads

// Pre-split weight images: per (k-block 32, n-block 128): [hi 10240B | lo 10240B]
// row layout: n_local (0..127) x stride 80B, 16 k-pairs (4B each) at bytes 0..63.
__device__ __align__(16) char g_wv_img [327680];   // 256 rows: 8 kb x 2 nb x 20480
__device__ __align__(16) char g_wso_img[327680];
__device__ __align__(16) char g_wo_img [327680];
__device__ __align__(16) char g_waw_img[163840];   // 128 rows: 8 kb x 1 nb x 20480

// ---------------------------------------------------------------------------
// Row mapping: compact row r -> offset into values[B,128,128,L,C]
// ---------------------------------------------------------------------------
__device__ __forceinline__ size_t map_a_row(int r) {
    int b  = r / ROWS_PER_B;
    int rr = r - b * ROWS_PER_B;
    int l, base, W;
    if (rr < 16384)      { l = 0; base = 0;     W = 128; }
    else if (rr < 20480) { l = 1; base = 16384; W = 64;  }
    else if (rr < 21504) { l = 2; base = 20480; W = 32;  }
    else                 { l = 3; base = 21504; W = 16;  }
    int idx = rr - base;
    int y = idx / W;
    int x = idx - y * W;
    return ((((size_t)b * HMAX_ + y) * HMAX_ + x) * LVL + l) * C_;
}

// ---------------------------------------------------------------------------
// helpers
// ---------------------------------------------------------------------------
__device__ __forceinline__ uint32_t smem_u32(const void* p) {
    uint32_t a;
    asm("{ .reg .u64 t; cvta.to.shared.u64 t, %1; cvt.u32.u64 %0, t; }"
        : "=r"(a) : "l"(p));
    return a;
}

__device__ __forceinline__ uint32_t pack_bf16x2(float e0, float e1) {
    uint32_t r;
    asm("cvt.rn.bf16x2.f32 %0, %1, %2;" : "=r"(r) : "f"(e1), "f"(e0));
    return r;
}

__device__ __forceinline__ float bf_hi(float x) {
    return __bfloat162float(__float2bfloat16_rn(x));
}

__device__ __forceinline__ void mma_bf16(float* c, const uint32_t* a, const uint32_t* b) {
    asm volatile(
        "mma.sync.aligned.m16n8k16.row.col.f32.bf16.bf16.f32 "
        "{%0,%1,%2,%3}, {%4,%5,%6,%7}, {%8,%9}, {%0,%1,%2,%3};\n"
        : "+f"(c[0]), "+f"(c[1]), "+f"(c[2]), "+f"(c[3])
        : "r"(a[0]), "r"(a[1]), "r"(a[2]), "r"(a[3]), "r"(b[0]), "r"(b[1]));
}

#define LDSM4(r, a) \
    asm volatile("ldmatrix.sync.aligned.m8n8.x4.shared.b16 {%0,%1,%2,%3}, [%4];" \
        : "=r"((r)[0]), "=r"((r)[1]), "=r"((r)[2]), "=r"((r)[3]) : "r"(a))

// ---------------------------------------------------------------------------
// Weight prep (single launch): 4 weight matrices -> hi/lo bf16 image blobs.
// blocks 0-127: W_v, 128-255: W_so, 256-383: W_o, 384-447: W_aw.
// ---------------------------------------------------------------------------
__global__ void prep_all(const float* __restrict__ Wv, const float* __restrict__ Wso,
                         const float* __restrict__ Wo, const float* __restrict__ Waw,
                         char* __restrict__ iv, char* __restrict__ iso,
                         char* __restrict__ io, char* __restrict__ iaw)
{
    int blk = blockIdx.x;
    const float* W; char* img; int R, lb;
    if (blk < 128)      { W = Wv;  img = iv;  R = 256; lb = blk; }
    else if (blk < 256) { W = Wso; img = iso; R = 256; lb = blk - 128; }
    else if (blk < 384) { W = Wo;  img = io;  R = 256; lb = blk - 256; }
    else                { W = Waw; img = iaw; R = 128; lb = blk - 384; }

    int idx = lb * 256 + threadIdx.x;   // one thread per (row n, k-pair)
    if (idx >= R * 128) return;
    int n = idx >> 7, p = idx & 127;
    int k = p * 2;
    int kb = k >> 5, pl = (k & 31) >> 1;
    int nb = n >> 7, nl = n & 127;
    float a = W[(size_t)n * 256 + k];
    float b = W[(size_t)n * 256 + k + 1];
    float ah = bf_hi(a), bh = bf_hi(b);
    char* blob = img + (size_t)(kb * (R >> 7) + nb) * 20480;
    uint32_t off = nl * 80 + pl * 4;
    *(uint32_t*)(blob + off)         = pack_bf16x2(ah, bh);
    *(uint32_t*)(blob + 10240 + off) = pack_bf16x2(a - ah, b - bh);
}

// ---------------------------------------------------------------------------
// bf16x3 compensated GEMM on mma.sync with ldmatrix fragment loads.
//   C[128 x 128] per CTA = A[128 x 256] @ B[128 x 256]^T + bias
//   ASRC: 0 = plain row-major fp32 A, 1 = mapped values rows.
//   OUTH: 0 = fp32 output, 1 = fp16 output.
// smem: AH@0 AL@10240 BH@20480 BL@30720 (rows: stride 80B, 64B data)
// ---------------------------------------------------------------------------
template <int ASRC, int OUTH>
__global__ void __launch_bounds__(256)
gemm_bf3(const float* __restrict__ A, const char* __restrict__ Bimg,
         const float* __restrict__ bias, void* __restrict__ Cv,
         int M, int N)
{
    __shared__ __align__(16) char sm[40960];

    const int tid = threadIdx.x, wid = tid >> 5, lane = tid & 31;
    const int g = lane >> 2, t = lane & 3;
    const int m0 = blockIdx.x * 128, n0 = blockIdx.y * 128;
    const int wm = (wid & 1) * 64, wn = (wid >> 1) * 32;
    const int NBLK = N >> 7;

    // A loading: 2 threads per row, 16 consecutive k each (within BK=32)
    const int r    = tid >> 1;
    const int half = tid & 1;
    size_t aoff = ASRC ? map_a_row(m0 + r) : (size_t)(m0 + r) * 256;
    const float* Ap = A + aoff + half * 16;

    const uint32_t sbase = smem_u32(sm);

    float acc[4][4][4];
#pragma unroll
    for (int i = 0; i < 4; i++)
#pragma unroll
        for (int j = 0; j < 4; j++)
#pragma unroll
            for (int c = 0; c < 4; c++) acc[i][j][c] = 0.0f;

    // stage-0 prefetch
    float4 pa[4];
    uint4  pb[5];
#pragma unroll
    for (int j = 0; j < 4; j++) pa[j] = *(const float4*)(Ap + j * 4);
    {
        const uint4* src = (const uint4*)(Bimg + (size_t)blockIdx.y * 20480);
#pragma unroll
        for (int j = 0; j < 5; j++) pb[j] = src[tid + 256 * j];
    }

    for (int kb = 0; kb < 8; kb++) {
        // ---- store A (convert fp32 -> bf16 hi/lo) ----
        {
            char* AH = sm + r * 80 + half * 32;
            char* AL = AH + 10240;
#pragma unroll
            for (int j = 0; j < 4; j++) {
                float4 v = pa[j];
                float xh = bf_hi(v.x), yh = bf_hi(v.y);
                float zh = bf_hi(v.z), wh = bf_hi(v.w);
                *(uint32_t*)(AH + j * 8)     = pack_bf16x2(xh, yh);
                *(uint32_t*)(AH + j * 8 + 4) = pack_bf16x2(zh, wh);
                *(uint32_t*)(AL + j * 8)     = pack_bf16x2(v.x - xh, v.y - yh);
                *(uint32_t*)(AL + j * 8 + 4) = pack_bf16x2(v.z - zh, v.w - wh);
            }
        }
        // ---- store B (already split, linear copy) ----
        {
            uint4* dst = (uint4*)(sm + 20480);
#pragma unroll
            for (int j = 0; j < 5; j++) dst[tid + 256 * j] = pb[j];
        }
        __syncthreads();

        // ---- prefetch next stage ----
        if (kb < 7) {
#pragma unroll
            for (int j = 0; j < 4; j++)
                pa[j] = *(const float4*)(Ap + (kb + 1) * 32 + j * 4);
            const uint4* src = (const uint4*)(Bimg +
                (size_t)((kb + 1) * NBLK + blockIdx.y) * 20480);
#pragma unroll
            for (int j = 0; j < 5; j++) pb[j] = src[tid + 256 * j];
        }

        // ---- MMA phase ----
        const int rr16 = lane & 15;               // row within 16-row frag
        const int chi  = ((lane >> 4) & 1) * 16;  // +16B for k upper half
#pragma unroll
        for (int ks = 0; ks < 2; ks++) {
            const int cb = ks * 32 + chi;
            uint32_t aH[4][4], aL[4][4];
#pragma unroll
            for (int fm = 0; fm < 4; fm++) {
                uint32_t ad = sbase + (wm + fm * 16 + rr16) * 80 + cb;
                LDSM4(aH[fm], ad);
                LDSM4(aL[fm], ad + 10240);
            }
            uint32_t bH[2][4], bL[2][4];
#pragma unroll
            for (int fp = 0; fp < 2; fp++) {
                uint32_t bd = sbase + 20480 + (wn + fp * 16 + rr16) * 80 + cb;
                LDSM4(bH[fp], bd);
                LDSM4(bL[fp], bd + 10240);
            }
#pragma unroll
            for (int fm = 0; fm < 4; fm++)
#pragma unroll
                for (int fn = 0; fn < 4; fn++) {
                    const int fp = fn >> 1, o = fn & 1;
                    uint32_t bh2[2] = {bH[fp][o], bH[fp][o + 2]};
                    uint32_t bl2[2] = {bL[fp][o], bL[fp][o + 2]};
                    mma_bf16(acc[fm][fn], aL[fm], bh2);   // AL*BH
                    mma_bf16(acc[fm][fn], aH[fm], bl2);   // AH*BL
                    mma_bf16(acc[fm][fn], aH[fm], bh2);   // AH*BH
                }
        }
        __syncthreads();
    }

    // ---- epilogue: bias add + stores ----
#pragma unroll
    for (int fn = 0; fn < 4; fn++) {
        int cn = n0 + wn + fn * 8 + t * 2;
        float b0 = bias[cn], b1 = bias[cn + 1];
#pragma unroll
        for (int fm = 0; fm < 4; fm++) {
            int r0 = m0 + wm + fm * 16 + g;
            if (OUTH) {
                __half* Cm = (__half*)Cv;
                *(__half2*)&Cm[(size_t)r0 * N + cn] =
                    __floats2half2_rn(acc[fm][fn][0] + b0, acc[fm][fn][1] + b1);
                *(__half2*)&Cm[(size_t)(r0 + 8) * N + cn] =
                    __floats2half2_rn(acc[fm][fn][2] + b0, acc[fm][fn][3] + b1);
            } else {
                float* Cm = (float*)Cv;
                *(float2*)&Cm[(size_t)r0 * N + cn] =
                    make_float2(acc[fm][fn][0] + b0, acc[fm][fn][1] + b1);
                *(float2*)&Cm[(size_t)(r0 + 8) * N + cn] =
                    make_float2(acc[fm][fn][2] + b0, acc[fm][fn][3] + b1);
            }
        }
    }
}

// ---------------------------------------------------------------------------
// Sampling kernel: one block (256 threads) handles 4 queries; fp16 gathers.
// ---------------------------------------------------------------------------
#define QPB 4
__global__ __launch_bounds__(256)
void sample_kernel(const float* __restrict__ ref,
                   const int* __restrict__ batch_offsets)
{
    __shared__ float sL[QPB][128];
    __shared__ float hM[QPB][8];
    __shared__ float hR[QPB][8];
    __shared__ __align__(16) int   srow[QPB][128][4];
    __shared__ __align__(16) float swt [QPB][128][4];

    const int tid = threadIdx.x;
    const int q0  = blockIdx.x * QPB;
    const int boundary = batch_offsets[1];

#pragma unroll
    for (int j = tid; j < QPB * 128; j += 256)
        sL[j >> 7][j & 127] = g_awr[(size_t)(q0 + (j >> 7)) * 128 + (j & 127)];
    __syncthreads();

    if (tid < QPB * 8) {
        int qi = tid >> 3, h = tid & 7;
        float m = -1e30f;
#pragma unroll
        for (int lp = 0; lp < 16; lp++) m = fmaxf(m, sL[qi][lp * 8 + h]);
        float s = 0.0f;
#pragma unroll
        for (int lp = 0; lp < 16; lp++) s += expf(sL[qi][lp * 8 + h] - m);
        hM[qi][h] = m;
        hR[qi][h] = 1.0f / s;
    }
    __syncthreads();

#pragma unroll
    for (int j = tid; j < QPB * 128; j += 256) {
        const int qi = j >> 7;
        const int i  = j & 127;
        const int q  = q0 + qi;
        const int h  = i & 7;
        const int lp = i >> 3;
        const int l  = lp >> 2;

        float aw = expf(sL[qi][i] - hM[qi][h]) * hR[qi][h];

        float rx = ref[q * 2 + 0];
        float ry = ref[q * 2 + 1];
        rx = fminf(fmaxf(rx, 0.0f), 1.0f);
        ry = fminf(fmaxf(ry, 0.0f), 1.0f);
        float isx = logf(fmaxf(rx, 1e-5f) / fmaxf(1.0f - rx, 1e-5f));
        float isy = logf(fmaxf(ry, 1e-5f) / fmaxf(1.0f - ry, 1e-5f));

        float ox = g_offs[(size_t)q * 256 + i * 2 + 0];
        float oy = g_offs[(size_t)q * 256 + i * 2 + 1];

        float locx = 1.0f / (1.0f + expf(-(isx + ox)));
        float locy = 1.0f / (1.0f + expf(-(isy + oy)));

        const int   Wl = HMAX_ >> l;
        const float Wf = (float)Wl;
        float x = locx * Wf - 0.5f;
        float y = locy * Wf - 0.5f;

        float x0f = floorf(x), y0f = floorf(y);
        float wx1 = x - x0f, wx0 = 1.0f - wx1;
        float wy1 = y - y0f, wy0 = 1.0f - wy1;
        int x0 = (int)x0f, y0 = (int)y0f;

        int b = (q >= boundary) ? 1 : 0;
        int lbase = (l >= 1 ? 16384 : 0) + (l >= 2 ? 4096 : 0) + (l >= 3 ? 1024 : 0);
        int base = b * ROWS_PER_B + lbase;

        int   xs[2]  = {x0, x0 + 1};
        int   ys2[2] = {y0, y0 + 1};
        float wxs[2] = {wx0, wx1};
        float wys[2] = {wy0, wy1};

#pragma unroll
        for (int cy = 0; cy < 2; cy++) {
#pragma unroll
            for (int cx = 0; cx < 2; cx++) {
                int c  = cy * 2 + cx;
                int xi = xs[cx], yi = ys2[cy];
                bool valid = (xi >= 0) & (xi < Wl) & (yi >= 0) & (yi < Wl);
                srow[qi][i][c] = valid ? (base + yi * Wl + xi) : -1;
                swt [qi][i][c] = valid ? (aw * wys[cy] * wxs[cx]) : 0.0f;
            }
        }
    }
    __syncthreads();

    const int qi   = tid >> 6;
    const int tq   = tid & 63;
    const int h    = tq >> 3;
    const int coff = h * DH_ + (tq & 7) * 4;
    const int q    = q0 + qi;

    float4 acc = make_float4(0.0f, 0.0f, 0.0f, 0.0f);
#pragma unroll
    for (int lp = 0; lp < 16; lp++) {
        const int i = lp * 8 + h;
        int4   r4 = *(const int4*)  &srow[qi][i][0];
        float4 w4 = *(const float4*)&swt [qi][i][0];
        int   rr[4] = {r4.x, r4.y, r4.z, r4.w};
        float ww[4] = {w4.x, w4.y, w4.z, w4.w};
#pragma unroll
        for (int c = 0; c < 4; c++) {
            if (rr[c] >= 0) {
                const __half2* vp = (const __half2*)&g_vproj[(size_t)rr[c] * C_ + coff];
                float2 f0 = __half22float2(vp[0]);
                float2 f1 = __half22float2(vp[1]);
                acc.x += ww[c] * f0.x;
                acc.y += ww[c] * f0.y;
                acc.z += ww[c] * f1.x;
                acc.w += ww[c] * f1.y;
            }
        }
    }
    *(float4*)&g_agg[(size_t)q * C_ + coff] = acc;
}

// ---------------------------------------------------------------------------
// kernel_launch
// ---------------------------------------------------------------------------
extern "C" void kernel_launch(void* const* d_in, const int* in_sizes, int n_in,
                              void* d_out, int out_size)
{
    const float* query  = (const float*)d_in[0];
    const float* ref    = (const float*)d_in[1];
    const float* values = (const float*)d_in[2];
    const float* W_so   = (const float*)d_in[3];
    const float* b_so   = (const float*)d_in[4];
    const float* W_aw   = (const float*)d_in[5];
    const float* b_aw   = (const float*)d_in[6];
    const float* W_v    = (const float*)d_in[7];
    const float* b_v    = (const float*)d_in[8];
    const float* W_o    = (const float*)d_in[9];
    const float* b_o    = (const float*)d_in[10];
    const int* batch_offsets = (const int*)d_in[11];
    float* out = (float*)d_out;
    (void)in_sizes; (void)n_in; (void)out_size;

    __half* vproj;
    float *offs, *awr, *agg;
    char *wv, *wso, *wo, *waw;
    cudaGetSymbolAddress((void**)&vproj, g_vproj);
    cudaGetSymbolAddress((void**)&offs,  g_offs);
    cudaGetSymbolAddress((void**)&awr,   g_awr);
    cudaGetSymbolAddress((void**)&agg,   g_agg);
    cudaGetSymbolAddress((void**)&wv,    g_wv_img);
    cudaGetSymbolAddress((void**)&wso,   g_wso_img);
    cudaGetSymbolAddress((void**)&wo,    g_wo_img);
    cudaGetSymbolAddress((void**)&waw,   g_waw_img);

    // 0) split all weights into hi/lo images (single launch)
    prep_all<<<448, 256>>>(W_v, W_so, W_o, W_aw, wv, wso, wo, waw);

    // 1) vproj = values_valid @ W_v^T + b_v   [43520 x 256] -> fp16
    {
        dim3 grid(NROWS / 128, 2);
        gemm_bf3<1, 1><<<grid, 256>>>(values, wv, b_v, vproj, NROWS, 256);
    }
    // 2) offs = query @ W_so^T + b_so         [8192 x 256]
    {
        dim3 grid(Q_ / 128, 2);
        gemm_bf3<0, 0><<<grid, 256>>>(query, wso, b_so, offs, Q_, 256);
    }
    // 3) awr = query @ W_aw^T + b_aw          [8192 x 128]
    {
        dim3 grid(Q_ / 128, 1);
        gemm_bf3<0, 0><<<grid, 256>>>(query, waw, b_aw, awr, Q_, 128);
    }
    // 4) softmax + bilinear sampling + head aggregation
    sample_kernel<<<Q_ / QPB, 256>>>(ref, batch_offsets);
    // 5) out = agg @ W_o^T + b_o              [8192 x 256]
    {
        dim3 grid(Q_ / 128, 2);
        gemm_bf3<0, 0><<<grid, 256>>>(agg, wo, b_o, out, Q_, 256);
    }
}

// round 8
// speedup vs baseline: 1.8403x; 1.0230x over previous
#include <cuda_runtime.h>
#include <cuda_bf16.h>
#include <cuda_fp16.h>
#include <cstdint>
#include <cstddef>

// ---------------------------------------------------------------------------
// Problem constants (fixed by the dataset)
// ---------------------------------------------------------------------------
#define Q_   8192
#define C_   256
#define LVL  4
#define NH_  8
#define DH_  32
#define HMAX_ 128

#define ROWS_PER_B 21760   // 16384+4096+1024+256
#define NROWS      43520   // 2 * ROWS_PER_B

// ---------------------------------------------------------------------------
// Scratch (device globals; no allocation allowed)
// ---------------------------------------------------------------------------
__device__ __half g_vproj[(size_t)NROWS * C_];  // projected valid values (fp16)
__device__ float g_offs [(size_t)Q_ * 256];     // sampling-offset raw proj
__device__ float g_awr  [(size_t)Q_ * 128];     // attention-weight logits
__device__ float g_agg  [(size_t)Q_ * C_];      // per-query aggregated heads

// Pre-split weight images: per (k-block 32, n-block 64): [hi 5120B | lo 5120B]
// row layout: n_local (0..63) x stride 80B, 16 k-pairs (4B each) at bytes 0..63.
__device__ __align__(16) char g_wv_img [327680];   // 256 rows: 8 kb x 4 nb x 10240
__device__ __align__(16) char g_wso_img[327680];
__device__ __align__(16) char g_wo_img [327680];
__device__ __align__(16) char g_waw_img[163840];   // 128 rows: 8 kb x 2 nb x 10240

// ---------------------------------------------------------------------------
// Row mapping: compact row r -> offset into values[B,128,128,L,C]
// ---------------------------------------------------------------------------
__device__ __forceinline__ size_t map_a_row(int r) {
    int b  = r / ROWS_PER_B;
    int rr = r - b * ROWS_PER_B;
    int l, base, W;
    if (rr < 16384)      { l = 0; base = 0;     W = 128; }
    else if (rr < 20480) { l = 1; base = 16384; W = 64;  }
    else if (rr < 21504) { l = 2; base = 20480; W = 32;  }
    else                 { l = 3; base = 21504; W = 16;  }
    int idx = rr - base;
    int y = idx / W;
    int x = idx - y * W;
    return ((((size_t)b * HMAX_ + y) * HMAX_ + x) * LVL + l) * C_;
}

// ---------------------------------------------------------------------------
// helpers
// ---------------------------------------------------------------------------
__device__ __forceinline__ uint32_t smem_u32(const void* p) {
    uint32_t a;
    asm("{ .reg .u64 t; cvta.to.shared.u64 t, %1; cvt.u32.u64 %0, t; }"
        : "=r"(a) : "l"(p));
    return a;
}

__device__ __forceinline__ uint32_t pack_bf16x2(float e0, float e1) {
    uint32_t r;
    asm("cvt.rn.bf16x2.f32 %0, %1, %2;" : "=r"(r) : "f"(e1), "f"(e0));
    return r;
}

__device__ __forceinline__ float bf_hi(float x) {
    return __bfloat162float(__float2bfloat16_rn(x));
}

__device__ __forceinline__ void mma_bf16(float* c, const uint32_t* a, const uint32_t* b) {
    asm volatile(
        "mma.sync.aligned.m16n8k16.row.col.f32.bf16.bf16.f32 "
        "{%0,%1,%2,%3}, {%4,%5,%6,%7}, {%8,%9}, {%0,%1,%2,%3};\n"
        : "+f"(c[0]), "+f"(c[1]), "+f"(c[2]), "+f"(c[3])
        : "r"(a[0]), "r"(a[1]), "r"(a[2]), "r"(a[3]), "r"(b[0]), "r"(b[1]));
}

#define LDSM4(r, a) \
    asm volatile("ldmatrix.sync.aligned.m8n8.x4.shared.b16 {%0,%1,%2,%3}, [%4];" \
        : "=r"((r)[0]), "=r"((r)[1]), "=r"((r)[2]), "=r"((r)[3]) : "r"(a))

// ---------------------------------------------------------------------------
// Weight prep (single launch): 4 weight matrices -> hi/lo bf16 image blobs.
// blob index (kb, nb64) -> offset (kb*(R/64)+nb)*10240; hi @0, lo @5120.
// blocks 0-127: W_v, 128-255: W_so, 256-383: W_o, 384-447: W_aw.
// ---------------------------------------------------------------------------
__global__ void prep_all(const float* __restrict__ Wv, const float* __restrict__ Wso,
                         const float* __restrict__ Wo, const float* __restrict__ Waw,
                         char* __restrict__ iv, char* __restrict__ iso,
                         char* __restrict__ io, char* __restrict__ iaw)
{
    int blk = blockIdx.x;
    const float* W; char* img; int R, lb;
    if (blk < 128)      { W = Wv;  img = iv;  R = 256; lb = blk; }
    else if (blk < 256) { W = Wso; img = iso; R = 256; lb = blk - 128; }
    else if (blk < 384) { W = Wo;  img = io;  R = 256; lb = blk - 256; }
    else                { W = Waw; img = iaw; R = 128; lb = blk - 384; }

    int idx = lb * 256 + threadIdx.x;   // one thread per (row n, k-pair)
    if (idx >= R * 128) return;
    int n = idx >> 7, p = idx & 127;
    int k = p * 2;
    int kb = k >> 5, pl = (k & 31) >> 1;
    int nb = n >> 6, nl = n & 63;
    float a = W[(size_t)n * 256 + k];
    float b = W[(size_t)n * 256 + k + 1];
    float ah = bf_hi(a), bh = bf_hi(b);
    char* blob = img + (size_t)(kb * (R >> 6) + nb) * 10240;
    uint32_t off = nl * 80 + pl * 4;
    *(uint32_t*)(blob + off)        = pack_bf16x2(ah, bh);
    *(uint32_t*)(blob + 5120 + off) = pack_bf16x2(a - ah, b - bh);
}

// ---------------------------------------------------------------------------
// bf16x3 compensated GEMM, 128x64 tile, double-buffered smem.
//   C[128 x 64] per CTA = A[128 x 256] @ B[64 x 256]^T + bias
//   ASRC: 0 = plain row-major fp32 A, 1 = mapped values rows.
//   OUTH: 0 = fp32 output, 1 = fp16 output.
// 256 threads, 8 warps as 4(m) x 2(n), warp tile 32x32.
// smem per stage (30720B): AH@0 AL@10240 B(hi|lo)@20480 (rows stride 80B)
// ---------------------------------------------------------------------------
template <int ASRC, int OUTH>
__global__ void __launch_bounds__(256)
gemm_bf3(const float* __restrict__ A, const char* __restrict__ Bimg,
         const float* __restrict__ bias, void* __restrict__ Cv,
         int M, int N)
{
    extern __shared__ __align__(16) char sm[];
    constexpr int STG = 30720;

    const int tid = threadIdx.x, wid = tid >> 5, lane = tid & 31;
    const int g = lane >> 2, t = lane & 3;
    const int m0 = blockIdx.x * 128, n0 = blockIdx.y * 64;
    const int wm = (wid & 3) * 32, wn = (wid >> 2) * 32;
    const int NBLK = N >> 6;

    // A loading: 2 threads per row, 16 consecutive k each (within BK=32)
    const int r    = tid >> 1;
    const int half = tid & 1;
    size_t aoff = ASRC ? map_a_row(m0 + r) : (size_t)(m0 + r) * 256;
    const float* Ap = A + aoff + half * 16;

    const uint32_t sbase = smem_u32(sm);

    float acc[2][4][4];
#pragma unroll
    for (int i = 0; i < 2; i++)
#pragma unroll
        for (int j = 0; j < 4; j++)
#pragma unroll
            for (int c = 0; c < 4; c++) acc[i][j][c] = 0.0f;

    float4 pa[4];
    uint4  pb[3];

    // stage-0 prefetch + store
#pragma unroll
    for (int j = 0; j < 4; j++) pa[j] = *(const float4*)(Ap + j * 4);
    {
        const uint4* src = (const uint4*)(Bimg + (size_t)blockIdx.y * 10240);
#pragma unroll
        for (int j = 0; j < 3; j++) {
            int idx = tid + 256 * j;
            if (idx < 640) pb[j] = src[idx];
        }
    }
    {
        char* AH = sm + r * 80 + half * 32;
#pragma unroll
        for (int j = 0; j < 4; j++) {
            float4 v = pa[j];
            float xh = bf_hi(v.x), yh = bf_hi(v.y);
            float zh = bf_hi(v.z), wh = bf_hi(v.w);
            *(uint32_t*)(AH + j * 8)             = pack_bf16x2(xh, yh);
            *(uint32_t*)(AH + j * 8 + 4)         = pack_bf16x2(zh, wh);
            *(uint32_t*)(AH + 10240 + j * 8)     = pack_bf16x2(v.x - xh, v.y - yh);
            *(uint32_t*)(AH + 10240 + j * 8 + 4) = pack_bf16x2(v.z - zh, v.w - wh);
        }
        uint4* dst = (uint4*)(sm + 20480);
#pragma unroll
        for (int j = 0; j < 3; j++) {
            int idx = tid + 256 * j;
            if (idx < 640) dst[idx] = pb[j];
        }
    }
    __syncthreads();

    const int rr16 = lane & 15;               // row within 16-row frag
    const int chi  = ((lane >> 4) & 1) * 16;  // +16B for k upper half

    for (int kb = 0; kb < 8; kb++) {
        const int p = kb & 1;

        // prefetch next stage from global
        if (kb < 7) {
#pragma unroll
            for (int j = 0; j < 4; j++)
                pa[j] = *(const float4*)(Ap + (kb + 1) * 32 + j * 4);
            const uint4* src = (const uint4*)(Bimg +
                (size_t)((kb + 1) * NBLK + blockIdx.y) * 10240);
#pragma unroll
            for (int j = 0; j < 3; j++) {
                int idx = tid + 256 * j;
                if (idx < 640) pb[j] = src[idx];
            }
        }

        // ---- MMA phase on buffer p ----
        const uint32_t base = sbase + p * STG;
#pragma unroll
        for (int ks = 0; ks < 2; ks++) {
            const int cb = ks * 32 + chi;
            uint32_t aH[2][4], aL[2][4];
#pragma unroll
            for (int fm = 0; fm < 2; fm++) {
                uint32_t ad = base + (wm + fm * 16 + rr16) * 80 + cb;
                LDSM4(aH[fm], ad);
                LDSM4(aL[fm], ad + 10240);
            }
            uint32_t bH[2][4], bL[2][4];
#pragma unroll
            for (int fp = 0; fp < 2; fp++) {
                uint32_t bd = base + 20480 + (wn + fp * 16 + rr16) * 80 + cb;
                LDSM4(bH[fp], bd);
                LDSM4(bL[fp], bd + 5120);
            }
#pragma unroll
            for (int fm = 0; fm < 2; fm++)
#pragma unroll
                for (int fn = 0; fn < 4; fn++) {
                    const int fp = fn >> 1, o = fn & 1;
                    uint32_t bh2[2] = {bH[fp][o], bH[fp][o + 2]};
                    uint32_t bl2[2] = {bL[fp][o], bL[fp][o + 2]};
                    mma_bf16(acc[fm][fn], aL[fm], bh2);   // AL*BH
                    mma_bf16(acc[fm][fn], aH[fm], bl2);   // AH*BL
                    mma_bf16(acc[fm][fn], aH[fm], bh2);   // AH*BH
                }
        }

        // ---- store next stage into buffer p^1 ----
        if (kb < 7) {
            char* bufn = sm + (p ^ 1) * STG;
            char* AH = bufn + r * 80 + half * 32;
#pragma unroll
            for (int j = 0; j < 4; j++) {
                float4 v = pa[j];
                float xh = bf_hi(v.x), yh = bf_hi(v.y);
                float zh = bf_hi(v.z), wh = bf_hi(v.w);
                *(uint32_t*)(AH + j * 8)             = pack_bf16x2(xh, yh);
                *(uint32_t*)(AH + j * 8 + 4)         = pack_bf16x2(zh, wh);
                *(uint32_t*)(AH + 10240 + j * 8)     = pack_bf16x2(v.x - xh, v.y - yh);
                *(uint32_t*)(AH + 10240 + j * 8 + 4) = pack_bf16x2(v.z - zh, v.w - wh);
            }
            uint4* dst = (uint4*)(bufn + 20480);
#pragma unroll
            for (int j = 0; j < 3; j++) {
                int idx = tid + 256 * j;
                if (idx < 640) dst[idx] = pb[j];
            }
        }
        __syncthreads();
    }

    // ---- epilogue: bias add + stores ----
#pragma unroll
    for (int fn = 0; fn < 4; fn++) {
        int cn = n0 + wn + fn * 8 + t * 2;
        float b0 = bias[cn], b1 = bias[cn + 1];
#pragma unroll
        for (int fm = 0; fm < 2; fm++) {
            int r0 = m0 + wm + fm * 16 + g;
            if (OUTH) {
                __half* Cm = (__half*)Cv;
                *(__half2*)&Cm[(size_t)r0 * N + cn] =
                    __floats2half2_rn(acc[fm][fn][0] + b0, acc[fm][fn][1] + b1);
                *(__half2*)&Cm[(size_t)(r0 + 8) * N + cn] =
                    __floats2half2_rn(acc[fm][fn][2] + b0, acc[fm][fn][3] + b1);
            } else {
                float* Cm = (float*)Cv;
                *(float2*)&Cm[(size_t)r0 * N + cn] =
                    make_float2(acc[fm][fn][0] + b0, acc[fm][fn][1] + b1);
                *(float2*)&Cm[(size_t)(r0 + 8) * N + cn] =
                    make_float2(acc[fm][fn][2] + b0, acc[fm][fn][3] + b1);
            }
        }
    }
}

// ---------------------------------------------------------------------------
// Sampling kernel: one block (256 threads) handles 4 queries; fp16 gathers.
// ---------------------------------------------------------------------------
#define QPB 4
__global__ __launch_bounds__(256)
void sample_kernel(const float* __restrict__ ref,
                   const int* __restrict__ batch_offsets)
{
    __shared__ float sL[QPB][128];
    __shared__ float hM[QPB][8];
    __shared__ float hR[QPB][8];
    __shared__ __align__(16) int   srow[QPB][128][4];
    __shared__ __align__(16) float swt [QPB][128][4];

    const int tid = threadIdx.x;
    const int q0  = blockIdx.x * QPB;
    const int boundary = batch_offsets[1];

#pragma unroll
    for (int j = tid; j < QPB * 128; j += 256)
        sL[j >> 7][j & 127] = g_awr[(size_t)(q0 + (j >> 7)) * 128 + (j & 127)];
    __syncthreads();

    if (tid < QPB * 8) {
        int qi = tid >> 3, h = tid & 7;
        float m = -1e30f;
#pragma unroll
        for (int lp = 0; lp < 16; lp++) m = fmaxf(m, sL[qi][lp * 8 + h]);
        float s = 0.0f;
#pragma unroll
        for (int lp = 0; lp < 16; lp++) s += expf(sL[qi][lp * 8 + h] - m);
        hM[qi][h] = m;
        hR[qi][h] = 1.0f / s;
    }
    __syncthreads();

#pragma unroll
    for (int j = tid; j < QPB * 128; j += 256) {
        const int qi = j >> 7;
        const int i  = j & 127;
        const int q  = q0 + qi;
        const int h  = i & 7;
        const int lp = i >> 3;
        const int l  = lp >> 2;

        float aw = expf(sL[qi][i] - hM[qi][h]) * hR[qi][h];

        float rx = ref[q * 2 + 0];
        float ry = ref[q * 2 + 1];
        rx = fminf(fmaxf(rx, 0.0f), 1.0f);
        ry = fminf(fmaxf(ry, 0.0f), 1.0f);
        float isx = logf(fmaxf(rx, 1e-5f) / fmaxf(1.0f - rx, 1e-5f));
        float isy = logf(fmaxf(ry, 1e-5f) / fmaxf(1.0f - ry, 1e-5f));

        float ox = g_offs[(size_t)q * 256 + i * 2 + 0];
        float oy = g_offs[(size_t)q * 256 + i * 2 + 1];

        float locx = 1.0f / (1.0f + expf(-(isx + ox)));
        float locy = 1.0f / (1.0f + expf(-(isy + oy)));

        const int   Wl = HMAX_ >> l;
        const float Wf = (float)Wl;
        float x = locx * Wf - 0.5f;
        float y = locy * Wf - 0.5f;

        float x0f = floorf(x), y0f = floorf(y);
        float wx1 = x - x0f, wx0 = 1.0f - wx1;
        float wy1 = y - y0f, wy0 = 1.0f - wy1;
        int x0 = (int)x0f, y0 = (int)y0f;

        int b = (q >= boundary) ? 1 : 0;
        int lbase = (l >= 1 ? 16384 : 0) + (l >= 2 ? 4096 : 0) + (l >= 3 ? 1024 : 0);
        int base = b * ROWS_PER_B + lbase;

        int   xs[2]  = {x0, x0 + 1};
        int   ys2[2] = {y0, y0 + 1};
        float wxs[2] = {wx0, wx1};
        float wys[2] = {wy0, wy1};

#pragma unroll
        for (int cy = 0; cy < 2; cy++) {
#pragma unroll
            for (int cx = 0; cx < 2; cx++) {
                int c  = cy * 2 + cx;
                int xi = xs[cx], yi = ys2[cy];
                bool valid = (xi >= 0) & (xi < Wl) & (yi >= 0) & (yi < Wl);
                srow[qi][i][c] = valid ? (base + yi * Wl + xi) : -1;
                swt [qi][i][c] = valid ? (aw * wys[cy] * wxs[cx]) : 0.0f;
            }
        }
    }
    __syncthreads();

    const int qi   = tid >> 6;
    const int tq   = tid & 63;
    const int h    = tq >> 3;
    const int coff = h * DH_ + (tq & 7) * 4;
    const int q    = q0 + qi;

    float4 acc = make_float4(0.0f, 0.0f, 0.0f, 0.0f);
#pragma unroll
    for (int lp = 0; lp < 16; lp++) {
        const int i = lp * 8 + h;
        int4   r4 = *(const int4*)  &srow[qi][i][0];
        float4 w4 = *(const float4*)&swt [qi][i][0];
        int   rr[4] = {r4.x, r4.y, r4.z, r4.w};
        float ww[4] = {w4.x, w4.y, w4.z, w4.w};
#pragma unroll
        for (int c = 0; c < 4; c++) {
            if (rr[c] >= 0) {
                const __half2* vp = (const __half2*)&g_vproj[(size_t)rr[c] * C_ + coff];
                float2 f0 = __half22float2(vp[0]);
                float2 f1 = __half22float2(vp[1]);
                acc.x += ww[c] * f0.x;
                acc.y += ww[c] * f0.y;
                acc.z += ww[c] * f1.x;
                acc.w += ww[c] * f1.y;
            }
        }
    }
    *(float4*)&g_agg[(size_t)q * C_ + coff] = acc;
}

// ---------------------------------------------------------------------------
// kernel_launch
// ---------------------------------------------------------------------------
extern "C" void kernel_launch(void* const* d_in, const int* in_sizes, int n_in,
                              void* d_out, int out_size)
{
    const float* query  = (const float*)d_in[0];
    const float* ref    = (const float*)d_in[1];
    const float* values = (const float*)d_in[2];
    const float* W_so   = (const float*)d_in[3];
    const float* b_so   = (const float*)d_in[4];
    const float* W_aw   = (const float*)d_in[5];
    const float* b_aw   = (const float*)d_in[6];
    const float* W_v    = (const float*)d_in[7];
    const float* b_v    = (const float*)d_in[8];
    const float* W_o    = (const float*)d_in[9];
    const float* b_o    = (const float*)d_in[10];
    const int* batch_offsets = (const int*)d_in[11];
    float* out = (float*)d_out;
    (void)in_sizes; (void)n_in; (void)out_size;

    __half* vproj;
    float *offs, *awr, *agg;
    char *wv, *wso, *wo, *waw;
    cudaGetSymbolAddress((void**)&vproj, g_vproj);
    cudaGetSymbolAddress((void**)&offs,  g_offs);
    cudaGetSymbolAddress((void**)&awr,   g_awr);
    cudaGetSymbolAddress((void**)&agg,   g_agg);
    cudaGetSymbolAddress((void**)&wv,    g_wv_img);
    cudaGetSymbolAddress((void**)&wso,   g_wso_img);
    cudaGetSymbolAddress((void**)&wo,    g_wo_img);
    cudaGetSymbolAddress((void**)&waw,   g_waw_img);

    const int SMEM = 61440;   // 2 x 30720 double buffer
    cudaFuncSetAttribute(gemm_bf3<1, 1>, cudaFuncAttributeMaxDynamicSharedMemorySize, SMEM);
    cudaFuncSetAttribute(gemm_bf3<0, 0>, cudaFuncAttributeMaxDynamicSharedMemorySize, SMEM);

    // 0) split all weights into hi/lo images (single launch)
    prep_all<<<448, 256>>>(W_v, W_so, W_o, W_aw, wv, wso, wo, waw);

    // 1) vproj = values_valid @ W_v^T + b_v   [43520 x 256] -> fp16
    {
        dim3 grid(NROWS / 128, 4);
        gemm_bf3<1, 1><<<grid, 256, SMEM>>>(values, wv, b_v, vproj, NROWS, 256);
    }
    // 2) offs = query @ W_so^T + b_so         [8192 x 256]
    {
        dim3 grid(Q_ / 128, 4);
        gemm_bf3<0, 0><<<grid, 256, SMEM>>>(query, wso, b_so, offs, Q_, 256);
    }
    // 3) awr = query @ W_aw^T + b_aw          [8192 x 128]
    {
        dim3 grid(Q_ / 128, 2);
        gemm_bf3<0, 0><<<grid, 256, SMEM>>>(query, waw, b_aw, awr, Q_, 128);
    }
    // 4) softmax + bilinear sampling + head aggregation
    sample_kernel<<<Q_ / QPB, 256>>>(ref, batch_offsets);
    // 5) out = agg @ W_o^T + b_o              [8192 x 256]
    {
        dim3 grid(Q_ / 128, 4);
        gemm_bf3<0, 0><<<grid, 256, SMEM>>>(agg, wo, b_o, out, Q_, 256);
    }
}

// round 9
// speedup vs baseline: 2.2366x; 1.2154x over previous
#include <cuda_runtime.h>
#include <cuda_bf16.h>
#include <cuda_fp16.h>
#include <cstdint>
#include <cstddef>

// ---------------------------------------------------------------------------
// Problem constants (fixed by the dataset)
// ---------------------------------------------------------------------------
#define Q_   8192
#define C_   256
#define LVL  4
#define NH_  8
#define DH_  32
#define HMAX_ 128

#define ROWS_PER_B 21760   // 16384+4096+1024+256
#define NROWS      43520   // 2 * ROWS_PER_B

// ---------------------------------------------------------------------------
// Scratch (device globals; no allocation allowed)
// ---------------------------------------------------------------------------
__device__ __half g_vproj[(size_t)NROWS * C_];  // projected valid values (fp16)
__device__ float g_offs [(size_t)Q_ * 256];     // sampling-offset raw proj
__device__ float g_awr  [(size_t)Q_ * 128];     // attention-weight logits
__device__ float g_agg  [(size_t)Q_ * C_];      // per-query aggregated heads

// bf16x3 weight images: per (k-block 32, n-block 64) blob: [hi 5120B | lo 5120B]
// row layout: n_local (0..63) x stride 80B, 16 k-pairs (4B each) at bytes 0..63.
__device__ __align__(16) char g_wso_img[327680];   // 256 rows: 8 kb x 4 nb x 10240
__device__ __align__(16) char g_wo_img [327680];
__device__ __align__(16) char g_waw_img[163840];   // 128 rows: 8 kb x 2 nb x 10240
// fp16 weight image for W_v: per (kb, nb64) blob: 5120B (fp16x2 pairs)
__device__ __align__(16) char g_wvh_img[163840];   // 8 kb x 4 nb x 5120

// ---------------------------------------------------------------------------
// Row mapping: compact row r -> offset into values[B,128,128,L,C]
// ---------------------------------------------------------------------------
__device__ __forceinline__ size_t map_a_row(int r) {
    int b  = r / ROWS_PER_B;
    int rr = r - b * ROWS_PER_B;
    int l, base, W;
    if (rr < 16384)      { l = 0; base = 0;     W = 128; }
    else if (rr < 20480) { l = 1; base = 16384; W = 64;  }
    else if (rr < 21504) { l = 2; base = 20480; W = 32;  }
    else                 { l = 3; base = 21504; W = 16;  }
    int idx = rr - base;
    int y = idx / W;
    int x = idx - y * W;
    return ((((size_t)b * HMAX_ + y) * HMAX_ + x) * LVL + l) * C_;
}

// ---------------------------------------------------------------------------
// helpers
// ---------------------------------------------------------------------------
__device__ __forceinline__ uint32_t smem_u32(const void* p) {
    uint32_t a;
    asm("{ .reg .u64 t; cvta.to.shared.u64 t, %1; cvt.u32.u64 %0, t; }"
        : "=r"(a) : "l"(p));
    return a;
}

__device__ __forceinline__ uint32_t pack_bf16x2(float e0, float e1) {
    uint32_t r;
    asm("cvt.rn.bf16x2.f32 %0, %1, %2;" : "=r"(r) : "f"(e1), "f"(e0));
    return r;
}

__device__ __forceinline__ uint32_t pack_f16x2(float e0, float e1) {
    uint32_t r;
    asm("cvt.rn.f16x2.f32 %0, %1, %2;" : "=r"(r) : "f"(e1), "f"(e0));
    return r;
}

__device__ __forceinline__ float bf_hi(float x) {
    return __bfloat162float(__float2bfloat16_rn(x));
}

__device__ __forceinline__ void mma_bf16(float* c, const uint32_t* a, const uint32_t* b) {
    asm volatile(
        "mma.sync.aligned.m16n8k16.row.col.f32.bf16.bf16.f32 "
        "{%0,%1,%2,%3}, {%4,%5,%6,%7}, {%8,%9}, {%0,%1,%2,%3};\n"
        : "+f"(c[0]), "+f"(c[1]), "+f"(c[2]), "+f"(c[3])
        : "r"(a[0]), "r"(a[1]), "r"(a[2]), "r"(a[3]), "r"(b[0]), "r"(b[1]));
}

__device__ __forceinline__ void mma_f16(float* c, const uint32_t* a, const uint32_t* b) {
    asm volatile(
        "mma.sync.aligned.m16n8k16.row.col.f32.f16.f16.f32 "
        "{%0,%1,%2,%3}, {%4,%5,%6,%7}, {%8,%9}, {%0,%1,%2,%3};\n"
        : "+f"(c[0]), "+f"(c[1]), "+f"(c[2]), "+f"(c[3])
        : "r"(a[0]), "r"(a[1]), "r"(a[2]), "r"(a[3]), "r"(b[0]), "r"(b[1]));
}

#define LDSM4(r, a) \
    asm volatile("ldmatrix.sync.aligned.m8n8.x4.shared.b16 {%0,%1,%2,%3}, [%4];" \
        : "=r"((r)[0]), "=r"((r)[1]), "=r"((r)[2]), "=r"((r)[3]) : "r"(a))

// ---------------------------------------------------------------------------
// Weight prep (single launch).
// blocks 0-127: W_v (fp16 image), 128-255: W_so, 256-383: W_o, 384-447: W_aw.
// ---------------------------------------------------------------------------
__global__ void prep_all(const float* __restrict__ Wv, const float* __restrict__ Wso,
                         const float* __restrict__ Wo, const float* __restrict__ Waw,
                         char* __restrict__ ivh, char* __restrict__ iso,
                         char* __restrict__ io, char* __restrict__ iaw)
{
    int blk = blockIdx.x;
    if (blk < 128) {
        // W_v -> fp16 image
        int idx = blk * 256 + threadIdx.x;
        int n = idx >> 7, p = idx & 127;
        int k = p * 2;
        int kb = k >> 5, pl = (k & 31) >> 1;
        int nb = n >> 6, nl = n & 63;
        float a = Wv[(size_t)n * 256 + k];
        float b = Wv[(size_t)n * 256 + k + 1];
        char* blob = ivh + (size_t)(kb * 4 + nb) * 5120;
        *(uint32_t*)(blob + nl * 80 + pl * 4) = pack_f16x2(a, b);
        return;
    }
    const float* W; char* img; int R, lb;
    if (blk < 256)      { W = Wso; img = iso; R = 256; lb = blk - 128; }
    else if (blk < 384) { W = Wo;  img = io;  R = 256; lb = blk - 256; }
    else                { W = Waw; img = iaw; R = 128; lb = blk - 384; }

    int idx = lb * 256 + threadIdx.x;
    if (idx >= R * 128) return;
    int n = idx >> 7, p = idx & 127;
    int k = p * 2;
    int kb = k >> 5, pl = (k & 31) >> 1;
    int nb = n >> 6, nl = n & 63;
    float a = W[(size_t)n * 256 + k];
    float b = W[(size_t)n * 256 + k + 1];
    float ah = bf_hi(a), bh = bf_hi(b);
    char* blob = img + (size_t)(kb * (R >> 6) + nb) * 10240;
    uint32_t off = nl * 80 + pl * 4;
    *(uint32_t*)(blob + off)        = pack_bf16x2(ah, bh);
    *(uint32_t*)(blob + 5120 + off) = pack_bf16x2(a - ah, b - bh);
}

// ---------------------------------------------------------------------------
// vproj GEMM: plain fp16 MMA (output is fp16 anyway), 128x64 tile, 256 thr.
//   C[128 x 64] = values_mapped[128 x 256] @ Wv[64 x 256]^T + bias  -> fp16
// 8 warps as 4(m) x 2(n), warp tile 32x32. Double-buffered 2 x 15360B smem.
// stage: A(fp16) @0 (128 rows x 80B = 10240), B(fp16) @10240 (64 x 80 = 5120)
// ---------------------------------------------------------------------------
__global__ void __launch_bounds__(256)
gemm_vproj(const float* __restrict__ A, const char* __restrict__ Bimg,
           const float* __restrict__ bias, __half* __restrict__ Cm)
{
    __shared__ __align__(16) char sm[2][15360];

    const int tid = threadIdx.x, wid = tid >> 5, lane = tid & 31;
    const int g = lane >> 2, t = lane & 3;
    const int m0 = blockIdx.x * 128, n0 = blockIdx.y * 64;
    const int wm = (wid & 3) * 32, wn = (wid >> 2) * 32;

    const int r    = tid >> 1;
    const int half = tid & 1;
    const float* Ap = A + map_a_row(m0 + r) + half * 16;

    const uint32_t sbase = smem_u32(sm);

    float acc[2][4][4];
#pragma unroll
    for (int i = 0; i < 2; i++)
#pragma unroll
        for (int j = 0; j < 4; j++)
#pragma unroll
            for (int c = 0; c < 4; c++) acc[i][j][c] = 0.0f;

    float4 pa[4];
    uint4  pb[2];

    // stage-0 prefetch + store
#pragma unroll
    for (int j = 0; j < 4; j++) pa[j] = *(const float4*)(Ap + j * 4);
    {
        const uint4* src = (const uint4*)(Bimg + (size_t)blockIdx.y * 5120);
#pragma unroll
        for (int j = 0; j < 2; j++) {
            int idx = tid + 256 * j;
            if (idx < 320) pb[j] = src[idx];
        }
    }
    {
        char* AH = sm[0] + r * 80 + half * 32;
#pragma unroll
        for (int j = 0; j < 4; j++) {
            float4 v = pa[j];
            *(uint32_t*)(AH + j * 8)     = pack_f16x2(v.x, v.y);
            *(uint32_t*)(AH + j * 8 + 4) = pack_f16x2(v.z, v.w);
        }
        uint4* dst = (uint4*)(sm[0] + 10240);
#pragma unroll
        for (int j = 0; j < 2; j++) {
            int idx = tid + 256 * j;
            if (idx < 320) dst[idx] = pb[j];
        }
    }
    __syncthreads();

    const int rr16 = lane & 15;
    const int chi  = ((lane >> 4) & 1) * 16;

    for (int kb = 0; kb < 8; kb++) {
        const int p = kb & 1;

        if (kb < 7) {
#pragma unroll
            for (int j = 0; j < 4; j++)
                pa[j] = *(const float4*)(Ap + (kb + 1) * 32 + j * 4);
            const uint4* src = (const uint4*)(Bimg +
                (size_t)((kb + 1) * 4 + blockIdx.y) * 5120);
#pragma unroll
            for (int j = 0; j < 2; j++) {
                int idx = tid + 256 * j;
                if (idx < 320) pb[j] = src[idx];
            }
        }

        const uint32_t base = sbase + p * 15360;
#pragma unroll
        for (int ks = 0; ks < 2; ks++) {
            const int cb = ks * 32 + chi;
            uint32_t aH[2][4];
#pragma unroll
            for (int fm = 0; fm < 2; fm++)
                LDSM4(aH[fm], base + (wm + fm * 16 + rr16) * 80 + cb);
            uint32_t bH[2][4];
#pragma unroll
            for (int fp = 0; fp < 2; fp++)
                LDSM4(bH[fp], base + 10240 + (wn + fp * 16 + rr16) * 80 + cb);
#pragma unroll
            for (int fm = 0; fm < 2; fm++)
#pragma unroll
                for (int fn = 0; fn < 4; fn++) {
                    const int fp = fn >> 1, o = fn & 1;
                    uint32_t bh2[2] = {bH[fp][o], bH[fp][o + 2]};
                    mma_f16(acc[fm][fn], aH[fm], bh2);
                }
        }

        if (kb < 7) {
            char* bufn = sm[p ^ 1];
            char* AH = bufn + r * 80 + half * 32;
#pragma unroll
            for (int j = 0; j < 4; j++) {
                float4 v = pa[j];
                *(uint32_t*)(AH + j * 8)     = pack_f16x2(v.x, v.y);
                *(uint32_t*)(AH + j * 8 + 4) = pack_f16x2(v.z, v.w);
            }
            uint4* dst = (uint4*)(bufn + 10240);
#pragma unroll
            for (int j = 0; j < 2; j++) {
                int idx = tid + 256 * j;
                if (idx < 320) dst[idx] = pb[j];
            }
        }
        __syncthreads();
    }

    // epilogue: bias + fp16 stores (row stride 256)
#pragma unroll
    for (int fn = 0; fn < 4; fn++) {
        int cn = n0 + wn + fn * 8 + t * 2;
        float b0 = bias[cn], b1 = bias[cn + 1];
#pragma unroll
        for (int fm = 0; fm < 2; fm++) {
            int r0 = m0 + wm + fm * 16 + g;
            *(__half2*)&Cm[(size_t)r0 * 256 + cn] =
                __floats2half2_rn(acc[fm][fn][0] + b0, acc[fm][fn][1] + b1);
            *(__half2*)&Cm[(size_t)(r0 + 8) * 256 + cn] =
                __floats2half2_rn(acc[fm][fn][2] + b0, acc[fm][fn][3] + b1);
        }
    }
}

// ---------------------------------------------------------------------------
// bf16x3 compensated GEMM, 64x64 tile, 128 threads, double-buffered smem.
//   C[64 x 64] = A[64 x 256] @ B[64 x 256]^T + bias  (fp32 in/out)
// 4 warps as 2(m) x 2(n), warp tile 32x32.
// stage (20480B): AH@0 AL@5120 BH@10240 BL@15360 (rows stride 80B)
// ---------------------------------------------------------------------------
__global__ void __launch_bounds__(128)
gemm_bf3(const float* __restrict__ A, const char* __restrict__ Bimg,
         const float* __restrict__ bias, float* __restrict__ Cm, int N)
{
    __shared__ __align__(16) char sm[2][20480];

    const int tid = threadIdx.x, wid = tid >> 5, lane = tid & 31;
    const int g = lane >> 2, t = lane & 3;
    const int m0 = blockIdx.x * 64, n0 = blockIdx.y * 64;
    const int wm = (wid & 1) * 32, wn = (wid >> 1) * 32;
    const int NBLK = N >> 6;

    const int r    = tid >> 1;
    const int half = tid & 1;
    const float* Ap = A + (size_t)(m0 + r) * 256 + half * 16;

    const uint32_t sbase = smem_u32(sm);

    float acc[2][4][4];
#pragma unroll
    for (int i = 0; i < 2; i++)
#pragma unroll
        for (int j = 0; j < 4; j++)
#pragma unroll
            for (int c = 0; c < 4; c++) acc[i][j][c] = 0.0f;

    float4 pa[4];
    uint4  pb[5];

    // stage-0 prefetch + store
#pragma unroll
    for (int j = 0; j < 4; j++) pa[j] = *(const float4*)(Ap + j * 4);
    {
        const uint4* src = (const uint4*)(Bimg + (size_t)blockIdx.y * 10240);
#pragma unroll
        for (int j = 0; j < 5; j++) pb[j] = src[tid + 128 * j];
    }
    {
        char* AH = sm[0] + r * 80 + half * 32;
#pragma unroll
        for (int j = 0; j < 4; j++) {
            float4 v = pa[j];
            float xh = bf_hi(v.x), yh = bf_hi(v.y);
            float zh = bf_hi(v.z), wh = bf_hi(v.w);
            *(uint32_t*)(AH + j * 8)            = pack_bf16x2(xh, yh);
            *(uint32_t*)(AH + j * 8 + 4)        = pack_bf16x2(zh, wh);
            *(uint32_t*)(AH + 5120 + j * 8)     = pack_bf16x2(v.x - xh, v.y - yh);
            *(uint32_t*)(AH + 5120 + j * 8 + 4) = pack_bf16x2(v.z - zh, v.w - wh);
        }
        uint4* dst = (uint4*)(sm[0] + 10240);
#pragma unroll
        for (int j = 0; j < 5; j++) dst[tid + 128 * j] = pb[j];
    }
    __syncthreads();

    const int rr16 = lane & 15;
    const int chi  = ((lane >> 4) & 1) * 16;

    for (int kb = 0; kb < 8; kb++) {
        const int p = kb & 1;

        if (kb < 7) {
#pragma unroll
            for (int j = 0; j < 4; j++)
                pa[j] = *(const float4*)(Ap + (kb + 1) * 32 + j * 4);
            const uint4* src = (const uint4*)(Bimg +
                (size_t)((kb + 1) * NBLK + blockIdx.y) * 10240);
#pragma unroll
            for (int j = 0; j < 5; j++) pb[j] = src[tid + 128 * j];
        }

        const uint32_t base = sbase + p * 20480;
#pragma unroll
        for (int ks = 0; ks < 2; ks++) {
            const int cb = ks * 32 + chi;
            uint32_t aH[2][4], aL[2][4];
#pragma unroll
            for (int fm = 0; fm < 2; fm++) {
                uint32_t ad = base + (wm + fm * 16 + rr16) * 80 + cb;
                LDSM4(aH[fm], ad);
                LDSM4(aL[fm], ad + 5120);
            }
            uint32_t bH[2][4], bL[2][4];
#pragma unroll
            for (int fp = 0; fp < 2; fp++) {
                uint32_t bd = base + 10240 + (wn + fp * 16 + rr16) * 80 + cb;
                LDSM4(bH[fp], bd);
                LDSM4(bL[fp], bd + 5120);
            }
#pragma unroll
            for (int fm = 0; fm < 2; fm++)
#pragma unroll
                for (int fn = 0; fn < 4; fn++) {
                    const int fp = fn >> 1, o = fn & 1;
                    uint32_t bh2[2] = {bH[fp][o], bH[fp][o + 2]};
                    uint32_t bl2[2] = {bL[fp][o], bL[fp][o + 2]};
                    mma_bf16(acc[fm][fn], aL[fm], bh2);   // AL*BH
                    mma_bf16(acc[fm][fn], aH[fm], bl2);   // AH*BL
                    mma_bf16(acc[fm][fn], aH[fm], bh2);   // AH*BH
                }
        }

        if (kb < 7) {
            char* bufn = sm[p ^ 1];
            char* AH = bufn + r * 80 + half * 32;
#pragma unroll
            for (int j = 0; j < 4; j++) {
                float4 v = pa[j];
                float xh = bf_hi(v.x), yh = bf_hi(v.y);
                float zh = bf_hi(v.z), wh = bf_hi(v.w);
                *(uint32_t*)(AH + j * 8)            = pack_bf16x2(xh, yh);
                *(uint32_t*)(AH + j * 8 + 4)        = pack_bf16x2(zh, wh);
                *(uint32_t*)(AH + 5120 + j * 8)     = pack_bf16x2(v.x - xh, v.y - yh);
                *(uint32_t*)(AH + 5120 + j * 8 + 4) = pack_bf16x2(v.z - zh, v.w - wh);
            }
            uint4* dst = (uint4*)(bufn + 10240);
#pragma unroll
            for (int j = 0; j < 5; j++) dst[tid + 128 * j] = pb[j];
        }
        __syncthreads();
    }

    // epilogue: bias + fp32 stores
#pragma unroll
    for (int fn = 0; fn < 4; fn++) {
        int cn = n0 + wn + fn * 8 + t * 2;
        float b0 = bias[cn], b1 = bias[cn + 1];
#pragma unroll
        for (int fm = 0; fm < 2; fm++) {
            int r0 = m0 + wm + fm * 16 + g;
            *(float2*)&Cm[(size_t)r0 * N + cn] =
                make_float2(acc[fm][fn][0] + b0, acc[fm][fn][1] + b1);
            *(float2*)&Cm[(size_t)(r0 + 8) * N + cn] =
                make_float2(acc[fm][fn][2] + b0, acc[fm][fn][3] + b1);
        }
    }
}

// ---------------------------------------------------------------------------
// Sampling kernel: one block (256 threads) handles 4 queries; fp16 gathers.
// ---------------------------------------------------------------------------
#define QPB 4
__global__ __launch_bounds__(256)
void sample_kernel(const float* __restrict__ ref,
                   const int* __restrict__ batch_offsets)
{
    __shared__ float sL[QPB][128];
    __shared__ float hM[QPB][8];
    __shared__ float hR[QPB][8];
    __shared__ __align__(16) int   srow[QPB][128][4];
    __shared__ __align__(16) float swt [QPB][128][4];

    const int tid = threadIdx.x;
    const int q0  = blockIdx.x * QPB;
    const int boundary = batch_offsets[1];

#pragma unroll
    for (int j = tid; j < QPB * 128; j += 256)
        sL[j >> 7][j & 127] = g_awr[(size_t)(q0 + (j >> 7)) * 128 + (j & 127)];
    __syncthreads();

    if (tid < QPB * 8) {
        int qi = tid >> 3, h = tid & 7;
        float m = -1e30f;
#pragma unroll
        for (int lp = 0; lp < 16; lp++) m = fmaxf(m, sL[qi][lp * 8 + h]);
        float s = 0.0f;
#pragma unroll
        for (int lp = 0; lp < 16; lp++) s += expf(sL[qi][lp * 8 + h] - m);
        hM[qi][h] = m;
        hR[qi][h] = 1.0f / s;
    }
    __syncthreads();

#pragma unroll
    for (int j = tid; j < QPB * 128; j += 256) {
        const int qi = j >> 7;
        const int i  = j & 127;
        const int q  = q0 + qi;
        const int h  = i & 7;
        const int lp = i >> 3;
        const int l  = lp >> 2;

        float aw = expf(sL[qi][i] - hM[qi][h]) * hR[qi][h];

        float rx = ref[q * 2 + 0];
        float ry = ref[q * 2 + 1];
        rx = fminf(fmaxf(rx, 0.0f), 1.0f);
        ry = fminf(fmaxf(ry, 0.0f), 1.0f);
        float isx = logf(fmaxf(rx, 1e-5f) / fmaxf(1.0f - rx, 1e-5f));
        float isy = logf(fmaxf(ry, 1e-5f) / fmaxf(1.0f - ry, 1e-5f));

        float ox = g_offs[(size_t)q * 256 + i * 2 + 0];
        float oy = g_offs[(size_t)q * 256 + i * 2 + 1];

        float locx = 1.0f / (1.0f + expf(-(isx + ox)));
        float locy = 1.0f / (1.0f + expf(-(isy + oy)));

        const int   Wl = HMAX_ >> l;
        const float Wf = (float)Wl;
        float x = locx * Wf - 0.5f;
        float y = locy * Wf - 0.5f;

        float x0f = floorf(x), y0f = floorf(y);
        float wx1 = x - x0f, wx0 = 1.0f - wx1;
        float wy1 = y - y0f, wy0 = 1.0f - wy1;
        int x0 = (int)x0f, y0 = (int)y0f;

        int b = (q >= boundary) ? 1 : 0;
        int lbase = (l >= 1 ? 16384 : 0) + (l >= 2 ? 4096 : 0) + (l >= 3 ? 1024 : 0);
        int base = b * ROWS_PER_B + lbase;

        int   xs[2]  = {x0, x0 + 1};
        int   ys2[2] = {y0, y0 + 1};
        float wxs[2] = {wx0, wx1};
        float wys[2] = {wy0, wy1};

#pragma unroll
        for (int cy = 0; cy < 2; cy++) {
#pragma unroll
            for (int cx = 0; cx < 2; cx++) {
                int c  = cy * 2 + cx;
                int xi = xs[cx], yi = ys2[cy];
                bool valid = (xi >= 0) & (xi < Wl) & (yi >= 0) & (yi < Wl);
                srow[qi][i][c] = valid ? (base + yi * Wl + xi) : -1;
                swt [qi][i][c] = valid ? (aw * wys[cy] * wxs[cx]) : 0.0f;
            }
        }
    }
    __syncthreads();

    const int qi   = tid >> 6;
    const int tq   = tid & 63;
    const int h    = tq >> 3;
    const int coff = h * DH_ + (tq & 7) * 4;
    const int q    = q0 + qi;

    float4 acc = make_float4(0.0f, 0.0f, 0.0f, 0.0f);
#pragma unroll
    for (int lp = 0; lp < 16; lp++) {
        const int i = lp * 8 + h;
        int4   r4 = *(const int4*)  &srow[qi][i][0];
        float4 w4 = *(const float4*)&swt [qi][i][0];
        int   rr[4] = {r4.x, r4.y, r4.z, r4.w};
        float ww[4] = {w4.x, w4.y, w4.z, w4.w};
#pragma unroll
        for (int c = 0; c < 4; c++) {
            if (rr[c] >= 0) {
                const __half2* vp = (const __half2*)&g_vproj[(size_t)rr[c] * C_ + coff];
                float2 f0 = __half22float2(vp[0]);
                float2 f1 = __half22float2(vp[1]);
                acc.x += ww[c] * f0.x;
                acc.y += ww[c] * f0.y;
                acc.z += ww[c] * f1.x;
                acc.w += ww[c] * f1.y;
            }
        }
    }
    *(float4*)&g_agg[(size_t)q * C_ + coff] = acc;
}

// ---------------------------------------------------------------------------
// kernel_launch
// ---------------------------------------------------------------------------
extern "C" void kernel_launch(void* const* d_in, const int* in_sizes, int n_in,
                              void* d_out, int out_size)
{
    const float* query  = (const float*)d_in[0];
    const float* ref    = (const float*)d_in[1];
    const float* values = (const float*)d_in[2];
    const float* W_so   = (const float*)d_in[3];
    const float* b_so   = (const float*)d_in[4];
    const float* W_aw   = (const float*)d_in[5];
    const float* b_aw   = (const float*)d_in[6];
    const float* W_v    = (const float*)d_in[7];
    const float* b_v    = (const float*)d_in[8];
    const float* W_o    = (const float*)d_in[9];
    const float* b_o    = (const float*)d_in[10];
    const int* batch_offsets = (const int*)d_in[11];
    float* out = (float*)d_out;
    (void)in_sizes; (void)n_in; (void)out_size;

    __half* vproj;
    float *offs, *awr, *agg;
    char *wvh, *wso, *wo, *waw;
    cudaGetSymbolAddress((void**)&vproj, g_vproj);
    cudaGetSymbolAddress((void**)&offs,  g_offs);
    cudaGetSymbolAddress((void**)&awr,   g_awr);
    cudaGetSymbolAddress((void**)&agg,   g_agg);
    cudaGetSymbolAddress((void**)&wvh,   g_wvh_img);
    cudaGetSymbolAddress((void**)&wso,   g_wso_img);
    cudaGetSymbolAddress((void**)&wo,    g_wo_img);
    cudaGetSymbolAddress((void**)&waw,   g_waw_img);

    // 0) weight images (single launch)
    prep_all<<<448, 256>>>(W_v, W_so, W_o, W_aw, wvh, wso, wo, waw);

    // 1) vproj = values_valid @ W_v^T + b_v   [43520 x 256] -> fp16 (fp16 MMA)
    {
        dim3 grid(NROWS / 128, 4);
        gemm_vproj<<<grid, 256>>>(values, wvh, b_v, vproj);
    }
    // 2) offs = query @ W_so^T + b_so         [8192 x 256] (bf16x3)
    {
        dim3 grid(Q_ / 64, 4);
        gemm_bf3<<<grid, 128>>>(query, wso, b_so, offs, 256);
    }
    // 3) awr = query @ W_aw^T + b_aw          [8192 x 128] (bf16x3)
    {
        dim3 grid(Q_ / 64, 2);
        gemm_bf3<<<grid, 128>>>(query, waw, b_aw, awr, 128);
    }
    // 4) softmax + bilinear sampling + head aggregation
    sample_kernel<<<Q_ / QPB, 256>>>(ref, batch_offsets);
    // 5) out = agg @ W_o^T + b_o              [8192 x 256] (bf16x3)
    {
        dim3 grid(Q_ / 64, 4);
        gemm_bf3<<<grid, 128>>>(agg, wo, b_o, out, 256);
    }
}

// round 10
// speedup vs baseline: 2.2857x; 1.0220x over previous
#include <cuda_runtime.h>
#include <cuda_bf16.h>
#include <cuda_fp16.h>
#include <cstdint>
#include <cstddef>

// ---------------------------------------------------------------------------
// Problem constants (fixed by the dataset)
// ---------------------------------------------------------------------------
#define Q_   8192
#define C_   256
#define LVL  4
#define NH_  8
#define DH_  32
#define HMAX_ 128

#define ROWS_PER_B 21760   // 16384+4096+1024+256
#define NROWS      43520   // 2 * ROWS_PER_B

// ---------------------------------------------------------------------------
// Scratch (device globals; no allocation allowed)
// ---------------------------------------------------------------------------
__device__ __half g_vproj[(size_t)NROWS * C_];  // projected valid values (fp16)
__device__ float g_offs [(size_t)Q_ * 256];     // sampling-offset raw proj
__device__ float g_awr  [(size_t)Q_ * 128];     // attention-weight logits
__device__ float g_agg  [(size_t)Q_ * C_];      // per-query aggregated heads

// bf16x3 weight images: per (k-block 32, n-block 64) blob: [hi 5120B | lo 5120B]
// row layout: n_local (0..63) x stride 80B, 16 k-pairs (4B each) at bytes 0..63.
__device__ __align__(16) char g_wqc_img[491520];   // combined W_so|W_aw: 384 rows, 8kb x 6nb x 10240
__device__ __align__(16) char g_wo_img [327680];   // 256 rows: 8 kb x 4 nb x 10240
// fp16 weight image for W_v: per (kb, nb64) blob: 5120B (fp16x2 pairs)
__device__ __align__(16) char g_wvh_img[163840];   // 8 kb x 4 nb x 5120

// ---------------------------------------------------------------------------
// Row mapping: compact row r -> offset into values[B,128,128,L,C]
// ---------------------------------------------------------------------------
__device__ __forceinline__ size_t map_a_row(int r) {
    int b  = r / ROWS_PER_B;
    int rr = r - b * ROWS_PER_B;
    int l, base, W;
    if (rr < 16384)      { l = 0; base = 0;     W = 128; }
    else if (rr < 20480) { l = 1; base = 16384; W = 64;  }
    else if (rr < 21504) { l = 2; base = 20480; W = 32;  }
    else                 { l = 3; base = 21504; W = 16;  }
    int idx = rr - base;
    int y = idx / W;
    int x = idx - y * W;
    return ((((size_t)b * HMAX_ + y) * HMAX_ + x) * LVL + l) * C_;
}

// ---------------------------------------------------------------------------
// helpers
// ---------------------------------------------------------------------------
__device__ __forceinline__ uint32_t smem_u32(const void* p) {
    uint32_t a;
    asm("{ .reg .u64 t; cvta.to.shared.u64 t, %1; cvt.u32.u64 %0, t; }"
        : "=r"(a) : "l"(p));
    return a;
}

__device__ __forceinline__ uint32_t pack_bf16x2(float e0, float e1) {
    uint32_t r;
    asm("cvt.rn.bf16x2.f32 %0, %1, %2;" : "=r"(r) : "f"(e1), "f"(e0));
    return r;
}

__device__ __forceinline__ uint32_t pack_f16x2(float e0, float e1) {
    uint32_t r;
    asm("cvt.rn.f16x2.f32 %0, %1, %2;" : "=r"(r) : "f"(e1), "f"(e0));
    return r;
}

__device__ __forceinline__ float bf_hi(float x) {
    return __bfloat162float(__float2bfloat16_rn(x));
}

__device__ __forceinline__ void mma_bf16(float* c, const uint32_t* a, const uint32_t* b) {
    asm volatile(
        "mma.sync.aligned.m16n8k16.row.col.f32.bf16.bf16.f32 "
        "{%0,%1,%2,%3}, {%4,%5,%6,%7}, {%8,%9}, {%0,%1,%2,%3};\n"
        : "+f"(c[0]), "+f"(c[1]), "+f"(c[2]), "+f"(c[3])
        : "r"(a[0]), "r"(a[1]), "r"(a[2]), "r"(a[3]), "r"(b[0]), "r"(b[1]));
}

__device__ __forceinline__ void mma_f16(float* c, const uint32_t* a, const uint32_t* b) {
    asm volatile(
        "mma.sync.aligned.m16n8k16.row.col.f32.f16.f16.f32 "
        "{%0,%1,%2,%3}, {%4,%5,%6,%7}, {%8,%9}, {%0,%1,%2,%3};\n"
        : "+f"(c[0]), "+f"(c[1]), "+f"(c[2]), "+f"(c[3])
        : "r"(a[0]), "r"(a[1]), "r"(a[2]), "r"(a[3]), "r"(b[0]), "r"(b[1]));
}

#define LDSM4(r, a) \
    asm volatile("ldmatrix.sync.aligned.m8n8.x4.shared.b16 {%0,%1,%2,%3}, [%4];" \
        : "=r"((r)[0]), "=r"((r)[1]), "=r"((r)[2]), "=r"((r)[3]) : "r"(a))

// ---------------------------------------------------------------------------
// Weight prep (single launch).
// blocks 0-127:   W_v  -> fp16 image (256 rows)
// blocks 128-319: W_so|W_aw combined -> bf16x3 image (384 rows)
// blocks 320-447: W_o  -> bf16x3 image (256 rows)
// ---------------------------------------------------------------------------
__global__ void prep_all(const float* __restrict__ Wv, const float* __restrict__ Wso,
                         const float* __restrict__ Waw, const float* __restrict__ Wo,
                         char* __restrict__ ivh, char* __restrict__ iqc,
                         char* __restrict__ io)
{
    int blk = blockIdx.x;
    if (blk < 128) {
        // W_v -> fp16 image
        int idx = blk * 256 + threadIdx.x;
        int n = idx >> 7, p = idx & 127;
        int k = p * 2;
        int kb = k >> 5, pl = (k & 31) >> 1;
        int nb = n >> 6, nl = n & 63;
        float a = Wv[(size_t)n * 256 + k];
        float b = Wv[(size_t)n * 256 + k + 1];
        char* blob = ivh + (size_t)(kb * 4 + nb) * 5120;
        *(uint32_t*)(blob + nl * 80 + pl * 4) = pack_f16x2(a, b);
        return;
    }
    const float* Wrow; char* img; int R, n, p;
    if (blk < 320) {
        int idx = (blk - 128) * 256 + threadIdx.x;   // 384*128 pairs
        n = idx >> 7; p = idx & 127;
        Wrow = (n < 256) ? (Wso + (size_t)n * 256) : (Waw + (size_t)(n - 256) * 256);
        img = iqc; R = 384;
    } else {
        int idx = (blk - 320) * 256 + threadIdx.x;   // 256*128 pairs
        n = idx >> 7; p = idx & 127;
        Wrow = Wo + (size_t)n * 256;
        img = io; R = 256;
    }
    int k = p * 2;
    int kb = k >> 5, pl = (k & 31) >> 1;
    int nb = n >> 6, nl = n & 63;
    float a = Wrow[k];
    float b = Wrow[k + 1];
    float ah = bf_hi(a), bh = bf_hi(b);
    char* blob = img + (size_t)(kb * (R >> 6) + nb) * 10240;
    uint32_t off = nl * 80 + pl * 4;
    *(uint32_t*)(blob + off)        = pack_bf16x2(ah, bh);
    *(uint32_t*)(blob + 5120 + off) = pack_bf16x2(a - ah, b - bh);
}

// ---------------------------------------------------------------------------
// Fused independent-GEMM batch, 64x64 tiles, 128 threads, double-buffered.
//  bid < 2720          : vproj tile  (fp16 MMA)   C=values_map @ Wv^T  -> fp16
//  bid >= 2720 (768)   : query tile  (bf16x3)     C=query @ [Wso|Waw]^T -> offs/awr
// 4 warps as 2(m) x 2(n), warp tile 32x32.
// ---------------------------------------------------------------------------
#define NV_BLK 2720   // (43520/64) * 4
#define NQ_BLK 768    // (8192/64) * 6

__global__ void __launch_bounds__(128)
gemm_all(const float* __restrict__ values, const char* __restrict__ wvh,
         const float* __restrict__ b_v, __half* __restrict__ vproj,
         const float* __restrict__ query, const char* __restrict__ wqc,
         const float* __restrict__ b_so, const float* __restrict__ b_aw,
         float* __restrict__ offs, float* __restrict__ awr)
{
    __shared__ __align__(16) char sm[2][20480];

    const int tid = threadIdx.x, wid = tid >> 5, lane = tid & 31;
    const int g = lane >> 2, t = lane & 3;
    const int wm = (wid & 1) * 32, wn = (wid >> 1) * 32;
    const int r    = tid >> 1;
    const int half = tid & 1;
    const int rr16 = lane & 15;
    const int chi  = ((lane >> 4) & 1) * 16;
    const uint32_t sbase = smem_u32(sm);

    float acc[2][4][4];
#pragma unroll
    for (int i = 0; i < 2; i++)
#pragma unroll
        for (int j = 0; j < 4; j++)
#pragma unroll
            for (int c = 0; c < 4; c++) acc[i][j][c] = 0.0f;

    const int bid = blockIdx.x;

    if (bid < NV_BLK) {
        // ================= vproj: fp16 MMA =================
        const int m0 = (bid >> 2) * 64, nb = bid & 3, n0 = nb * 64;
        const float* Ap = values + map_a_row(m0 + r) + half * 16;

        float4 pa[4];
        uint4  pb[3];
#pragma unroll
        for (int j = 0; j < 4; j++) pa[j] = *(const float4*)(Ap + j * 4);
        {
            const uint4* src = (const uint4*)(wvh + (size_t)nb * 5120);
#pragma unroll
            for (int j = 0; j < 3; j++) {
                int idx = tid + 128 * j;
                if (idx < 320) pb[j] = src[idx];
            }
        }
        {
            char* AH = sm[0] + r * 80 + half * 32;
#pragma unroll
            for (int j = 0; j < 4; j++) {
                float4 v = pa[j];
                *(uint32_t*)(AH + j * 8)     = pack_f16x2(v.x, v.y);
                *(uint32_t*)(AH + j * 8 + 4) = pack_f16x2(v.z, v.w);
            }
            uint4* dst = (uint4*)(sm[0] + 5120);
#pragma unroll
            for (int j = 0; j < 3; j++) {
                int idx = tid + 128 * j;
                if (idx < 320) dst[idx] = pb[j];
            }
        }
        __syncthreads();

        for (int kb = 0; kb < 8; kb++) {
            const int p = kb & 1;
            if (kb < 7) {
#pragma unroll
                for (int j = 0; j < 4; j++)
                    pa[j] = *(const float4*)(Ap + (kb + 1) * 32 + j * 4);
                const uint4* src = (const uint4*)(wvh + (size_t)((kb + 1) * 4 + nb) * 5120);
#pragma unroll
                for (int j = 0; j < 3; j++) {
                    int idx = tid + 128 * j;
                    if (idx < 320) pb[j] = src[idx];
                }
            }
            const uint32_t base = sbase + p * 20480;
#pragma unroll
            for (int ks = 0; ks < 2; ks++) {
                const int cb = ks * 32 + chi;
                uint32_t aH[2][4], bH[2][4];
#pragma unroll
                for (int fm = 0; fm < 2; fm++)
                    LDSM4(aH[fm], base + (wm + fm * 16 + rr16) * 80 + cb);
#pragma unroll
                for (int fp = 0; fp < 2; fp++)
                    LDSM4(bH[fp], base + 5120 + (wn + fp * 16 + rr16) * 80 + cb);
#pragma unroll
                for (int fm = 0; fm < 2; fm++)
#pragma unroll
                    for (int fn = 0; fn < 4; fn++) {
                        const int fp = fn >> 1, o = fn & 1;
                        uint32_t bh2[2] = {bH[fp][o], bH[fp][o + 2]};
                        mma_f16(acc[fm][fn], aH[fm], bh2);
                    }
            }
            if (kb < 7) {
                char* bufn = sm[p ^ 1];
                char* AH = bufn + r * 80 + half * 32;
#pragma unroll
                for (int j = 0; j < 4; j++) {
                    float4 v = pa[j];
                    *(uint32_t*)(AH + j * 8)     = pack_f16x2(v.x, v.y);
                    *(uint32_t*)(AH + j * 8 + 4) = pack_f16x2(v.z, v.w);
                }
                uint4* dst = (uint4*)(bufn + 5120);
#pragma unroll
                for (int j = 0; j < 3; j++) {
                    int idx = tid + 128 * j;
                    if (idx < 320) dst[idx] = pb[j];
                }
            }
            __syncthreads();
        }

#pragma unroll
        for (int fn = 0; fn < 4; fn++) {
            int cn = n0 + wn + fn * 8 + t * 2;
            float b0 = b_v[cn], b1 = b_v[cn + 1];
#pragma unroll
            for (int fm = 0; fm < 2; fm++) {
                int r0 = m0 + wm + fm * 16 + g;
                *(__half2*)&vproj[(size_t)r0 * 256 + cn] =
                    __floats2half2_rn(acc[fm][fn][0] + b0, acc[fm][fn][1] + b1);
                *(__half2*)&vproj[(size_t)(r0 + 8) * 256 + cn] =
                    __floats2half2_rn(acc[fm][fn][2] + b0, acc[fm][fn][3] + b1);
            }
        }
        return;
    }

    // ================= query offs+awr: bf16x3 =================
    {
        const int qid = bid - NV_BLK;
        const int m0 = (qid / 6) * 64, nb = qid % 6, n0 = nb * 64;
        const float* Ap = query + (size_t)(m0 + r) * 256 + half * 16;

        float4 pa[4];
        uint4  pb[5];
#pragma unroll
        for (int j = 0; j < 4; j++) pa[j] = *(const float4*)(Ap + j * 4);
        {
            const uint4* src = (const uint4*)(wqc + (size_t)nb * 10240);
#pragma unroll
            for (int j = 0; j < 5; j++) pb[j] = src[tid + 128 * j];
        }
        {
            char* AH = sm[0] + r * 80 + half * 32;
#pragma unroll
            for (int j = 0; j < 4; j++) {
                float4 v = pa[j];
                float xh = bf_hi(v.x), yh = bf_hi(v.y);
                float zh = bf_hi(v.z), wh = bf_hi(v.w);
                *(uint32_t*)(AH + j * 8)            = pack_bf16x2(xh, yh);
                *(uint32_t*)(AH + j * 8 + 4)        = pack_bf16x2(zh, wh);
                *(uint32_t*)(AH + 5120 + j * 8)     = pack_bf16x2(v.x - xh, v.y - yh);
                *(uint32_t*)(AH + 5120 + j * 8 + 4) = pack_bf16x2(v.z - zh, v.w - wh);
            }
            uint4* dst = (uint4*)(sm[0] + 10240);
#pragma unroll
            for (int j = 0; j < 5; j++) dst[tid + 128 * j] = pb[j];
        }
        __syncthreads();

        for (int kb = 0; kb < 8; kb++) {
            const int p = kb & 1;
            if (kb < 7) {
#pragma unroll
                for (int j = 0; j < 4; j++)
                    pa[j] = *(const float4*)(Ap + (kb + 1) * 32 + j * 4);
                const uint4* src = (const uint4*)(wqc + (size_t)((kb + 1) * 6 + nb) * 10240);
#pragma unroll
                for (int j = 0; j < 5; j++) pb[j] = src[tid + 128 * j];
            }
            const uint32_t base = sbase + p * 20480;
#pragma unroll
            for (int ks = 0; ks < 2; ks++) {
                const int cb = ks * 32 + chi;
                uint32_t aH[2][4], aL[2][4];
#pragma unroll
                for (int fm = 0; fm < 2; fm++) {
                    uint32_t ad = base + (wm + fm * 16 + rr16) * 80 + cb;
                    LDSM4(aH[fm], ad);
                    LDSM4(aL[fm], ad + 5120);
                }
                uint32_t bH[2][4], bL[2][4];
#pragma unroll
                for (int fp = 0; fp < 2; fp++) {
                    uint32_t bd = base + 10240 + (wn + fp * 16 + rr16) * 80 + cb;
                    LDSM4(bH[fp], bd);
                    LDSM4(bL[fp], bd + 5120);
                }
#pragma unroll
                for (int fm = 0; fm < 2; fm++)
#pragma unroll
                    for (int fn = 0; fn < 4; fn++) {
                        const int fp = fn >> 1, o = fn & 1;
                        uint32_t bh2[2] = {bH[fp][o], bH[fp][o + 2]};
                        uint32_t bl2[2] = {bL[fp][o], bL[fp][o + 2]};
                        mma_bf16(acc[fm][fn], aL[fm], bh2);
                        mma_bf16(acc[fm][fn], aH[fm], bl2);
                        mma_bf16(acc[fm][fn], aH[fm], bh2);
                    }
            }
            if (kb < 7) {
                char* bufn = sm[p ^ 1];
                char* AH = bufn + r * 80 + half * 32;
#pragma unroll
                for (int j = 0; j < 4; j++) {
                    float4 v = pa[j];
                    float xh = bf_hi(v.x), yh = bf_hi(v.y);
                    float zh = bf_hi(v.z), wh = bf_hi(v.w);
                    *(uint32_t*)(AH + j * 8)            = pack_bf16x2(xh, yh);
                    *(uint32_t*)(AH + j * 8 + 4)        = pack_bf16x2(zh, wh);
                    *(uint32_t*)(AH + 5120 + j * 8)     = pack_bf16x2(v.x - xh, v.y - yh);
                    *(uint32_t*)(AH + 5120 + j * 8 + 4) = pack_bf16x2(v.z - zh, v.w - wh);
                }
                uint4* dst = (uint4*)(bufn + 10240);
#pragma unroll
                for (int j = 0; j < 5; j++) dst[tid + 128 * j] = pb[j];
            }
            __syncthreads();
        }

        const bool is_aw = (n0 >= 256);
        const float* bias = is_aw ? b_aw : b_so;
        float* Cm = is_aw ? awr : offs;
        const int Nout = is_aw ? 128 : 256;
        const int ncol0 = is_aw ? (n0 - 256) : n0;
#pragma unroll
        for (int fn = 0; fn < 4; fn++) {
            int cn = ncol0 + wn + fn * 8 + t * 2;
            float b0 = bias[cn], b1 = bias[cn + 1];
#pragma unroll
            for (int fm = 0; fm < 2; fm++) {
                int r0 = m0 + wm + fm * 16 + g;
                *(float2*)&Cm[(size_t)r0 * Nout + cn] =
                    make_float2(acc[fm][fn][0] + b0, acc[fm][fn][1] + b1);
                *(float2*)&Cm[(size_t)(r0 + 8) * Nout + cn] =
                    make_float2(acc[fm][fn][2] + b0, acc[fm][fn][3] + b1);
            }
        }
    }
}

// ---------------------------------------------------------------------------
// out-proj GEMM: bf16x3, 64x64 tile, 128 threads (same as before)
// ---------------------------------------------------------------------------
__global__ void __launch_bounds__(128)
gemm_bf3(const float* __restrict__ A, const char* __restrict__ Bimg,
         const float* __restrict__ bias, float* __restrict__ Cm, int N)
{
    __shared__ __align__(16) char sm[2][20480];

    const int tid = threadIdx.x, wid = tid >> 5, lane = tid & 31;
    const int g = lane >> 2, t = lane & 3;
    const int m0 = blockIdx.x * 64, n0 = blockIdx.y * 64;
    const int wm = (wid & 1) * 32, wn = (wid >> 1) * 32;
    const int NBLK = N >> 6;

    const int r    = tid >> 1;
    const int half = tid & 1;
    const float* Ap = A + (size_t)(m0 + r) * 256 + half * 16;

    const uint32_t sbase = smem_u32(sm);

    float acc[2][4][4];
#pragma unroll
    for (int i = 0; i < 2; i++)
#pragma unroll
        for (int j = 0; j < 4; j++)
#pragma unroll
            for (int c = 0; c < 4; c++) acc[i][j][c] = 0.0f;

    float4 pa[4];
    uint4  pb[5];
#pragma unroll
    for (int j = 0; j < 4; j++) pa[j] = *(const float4*)(Ap + j * 4);
    {
        const uint4* src = (const uint4*)(Bimg + (size_t)blockIdx.y * 10240);
#pragma unroll
        for (int j = 0; j < 5; j++) pb[j] = src[tid + 128 * j];
    }
    {
        char* AH = sm[0] + r * 80 + half * 32;
#pragma unroll
        for (int j = 0; j < 4; j++) {
            float4 v = pa[j];
            float xh = bf_hi(v.x), yh = bf_hi(v.y);
            float zh = bf_hi(v.z), wh = bf_hi(v.w);
            *(uint32_t*)(AH + j * 8)            = pack_bf16x2(xh, yh);
            *(uint32_t*)(AH + j * 8 + 4)        = pack_bf16x2(zh, wh);
            *(uint32_t*)(AH + 5120 + j * 8)     = pack_bf16x2(v.x - xh, v.y - yh);
            *(uint32_t*)(AH + 5120 + j * 8 + 4) = pack_bf16x2(v.z - zh, v.w - wh);
        }
        uint4* dst = (uint4*)(sm[0] + 10240);
#pragma unroll
        for (int j = 0; j < 5; j++) dst[tid + 128 * j] = pb[j];
    }
    __syncthreads();

    const int rr16 = lane & 15;
    const int chi  = ((lane >> 4) & 1) * 16;

    for (int kb = 0; kb < 8; kb++) {
        const int p = kb & 1;
        if (kb < 7) {
#pragma unroll
            for (int j = 0; j < 4; j++)
                pa[j] = *(const float4*)(Ap + (kb + 1) * 32 + j * 4);
            const uint4* src = (const uint4*)(Bimg +
                (size_t)((kb + 1) * NBLK + blockIdx.y) * 10240);
#pragma unroll
            for (int j = 0; j < 5; j++) pb[j] = src[tid + 128 * j];
        }
        const uint32_t base = sbase + p * 20480;
#pragma unroll
        for (int ks = 0; ks < 2; ks++) {
            const int cb = ks * 32 + chi;
            uint32_t aH[2][4], aL[2][4];
#pragma unroll
            for (int fm = 0; fm < 2; fm++) {
                uint32_t ad = base + (wm + fm * 16 + rr16) * 80 + cb;
                LDSM4(aH[fm], ad);
                LDSM4(aL[fm], ad + 5120);
            }
            uint32_t bH[2][4], bL[2][4];
#pragma unroll
            for (int fp = 0; fp < 2; fp++) {
                uint32_t bd = base + 10240 + (wn + fp * 16 + rr16) * 80 + cb;
                LDSM4(bH[fp], bd);
                LDSM4(bL[fp], bd + 5120);
            }
#pragma unroll
            for (int fm = 0; fm < 2; fm++)
#pragma unroll
                for (int fn = 0; fn < 4; fn++) {
                    const int fp = fn >> 1, o = fn & 1;
                    uint32_t bh2[2] = {bH[fp][o], bH[fp][o + 2]};
                    uint32_t bl2[2] = {bL[fp][o], bL[fp][o + 2]};
                    mma_bf16(acc[fm][fn], aL[fm], bh2);
                    mma_bf16(acc[fm][fn], aH[fm], bl2);
                    mma_bf16(acc[fm][fn], aH[fm], bh2);
                }
        }
        if (kb < 7) {
            char* bufn = sm[p ^ 1];
            char* AH = bufn + r * 80 + half * 32;
#pragma unroll
            for (int j = 0; j < 4; j++) {
                float4 v = pa[j];
                float xh = bf_hi(v.x), yh = bf_hi(v.y);
                float zh = bf_hi(v.z), wh = bf_hi(v.w);
                *(uint32_t*)(AH + j * 8)            = pack_bf16x2(xh, yh);
                *(uint32_t*)(AH + j * 8 + 4)        = pack_bf16x2(zh, wh);
                *(uint32_t*)(AH + 5120 + j * 8)     = pack_bf16x2(v.x - xh, v.y - yh);
                *(uint32_t*)(AH + 5120 + j * 8 + 4) = pack_bf16x2(v.z - zh, v.w - wh);
            }
            uint4* dst = (uint4*)(bufn + 10240);
#pragma unroll
            for (int j = 0; j < 5; j++) dst[tid + 128 * j] = pb[j];
        }
        __syncthreads();
    }

#pragma unroll
    for (int fn = 0; fn < 4; fn++) {
        int cn = n0 + wn + fn * 8 + t * 2;
        float b0 = bias[cn], b1 = bias[cn + 1];
#pragma unroll
        for (int fm = 0; fm < 2; fm++) {
            int r0 = m0 + wm + fm * 16 + g;
            *(float2*)&Cm[(size_t)r0 * N + cn] =
                make_float2(acc[fm][fn][0] + b0, acc[fm][fn][1] + b1);
            *(float2*)&Cm[(size_t)(r0 + 8) * N + cn] =
                make_float2(acc[fm][fn][2] + b0, acc[fm][fn][3] + b1);
        }
    }
}

// ---------------------------------------------------------------------------
// Sampling kernel: 4 queries per block; branchless fp16 gathers.
// ---------------------------------------------------------------------------
#define QPB 4
__global__ __launch_bounds__(256)
void sample_kernel(const float* __restrict__ ref,
                   const int* __restrict__ batch_offsets)
{
    __shared__ float sL[QPB][128];
    __shared__ float hM[QPB][8];
    __shared__ float hR[QPB][8];
    __shared__ float sIS[QPB][2];
    __shared__ __align__(16) int   srow[QPB][128][4];
    __shared__ __align__(16) float swt [QPB][128][4];

    const int tid = threadIdx.x;
    const int q0  = blockIdx.x * QPB;
    const int boundary = batch_offsets[1];

#pragma unroll
    for (int j = tid; j < QPB * 128; j += 256)
        sL[j >> 7][j & 127] = g_awr[(size_t)(q0 + (j >> 7)) * 128 + (j & 127)];

    if (tid >= 224 && tid < 224 + QPB * 2) {
        int k = tid - 224;
        int qi = k >> 1, xy = k & 1;
        float v = ref[(q0 + qi) * 2 + xy];
        v = fminf(fmaxf(v, 0.0f), 1.0f);
        sIS[qi][xy] = logf(fmaxf(v, 1e-5f) / fmaxf(1.0f - v, 1e-5f));
    }
    __syncthreads();

    if (tid < QPB * 8) {
        int qi = tid >> 3, h = tid & 7;
        float m = -1e30f;
#pragma unroll
        for (int lp = 0; lp < 16; lp++) m = fmaxf(m, sL[qi][lp * 8 + h]);
        float s = 0.0f;
#pragma unroll
        for (int lp = 0; lp < 16; lp++) s += expf(sL[qi][lp * 8 + h] - m);
        hM[qi][h] = m;
        hR[qi][h] = 1.0f / s;
    }
    __syncthreads();

#pragma unroll
    for (int j = tid; j < QPB * 128; j += 256) {
        const int qi = j >> 7;
        const int i  = j & 127;
        const int q  = q0 + qi;
        const int h  = i & 7;
        const int lp = i >> 3;
        const int l  = lp >> 2;

        float aw = expf(sL[qi][i] - hM[qi][h]) * hR[qi][h];

        float ox = g_offs[(size_t)q * 256 + i * 2 + 0];
        float oy = g_offs[(size_t)q * 256 + i * 2 + 1];

        float locx = 1.0f / (1.0f + expf(-(sIS[qi][0] + ox)));
        float locy = 1.0f / (1.0f + expf(-(sIS[qi][1] + oy)));

        const int   Wl = HMAX_ >> l;
        const float Wf = (float)Wl;
        float x = locx * Wf - 0.5f;
        float y = locy * Wf - 0.5f;

        float x0f = floorf(x), y0f = floorf(y);
        float wx1 = x - x0f, wx0 = 1.0f - wx1;
        float wy1 = y - y0f, wy0 = 1.0f - wy1;
        int x0 = (int)x0f, y0 = (int)y0f;

        int b = (q >= boundary) ? 1 : 0;
        int lbase = (l >= 1 ? 16384 : 0) + (l >= 2 ? 4096 : 0) + (l >= 3 ? 1024 : 0);
        int base = b * ROWS_PER_B + lbase;

        int   xs[2]  = {x0, x0 + 1};
        int   ys2[2] = {y0, y0 + 1};
        float wxs[2] = {wx0, wx1};
        float wys[2] = {wy0, wy1};

#pragma unroll
        for (int cy = 0; cy < 2; cy++) {
#pragma unroll
            for (int cx = 0; cx < 2; cx++) {
                int c  = cy * 2 + cx;
                int xi = xs[cx], yi = ys2[cy];
                bool valid = (xi >= 0) & (xi < Wl) & (yi >= 0) & (yi < Wl);
                int xc = min(max(xi, 0), Wl - 1);
                int yc = min(max(yi, 0), Wl - 1);
                srow[qi][i][c] = base + yc * Wl + xc;
                swt [qi][i][c] = valid ? (aw * wys[cy] * wxs[cx]) : 0.0f;
            }
        }
    }
    __syncthreads();

    const int qi   = tid >> 6;
    const int tq   = tid & 63;
    const int h    = tq >> 3;
    const int coff = h * DH_ + (tq & 7) * 4;
    const int q    = q0 + qi;

    float4 acc = make_float4(0.0f, 0.0f, 0.0f, 0.0f);
#pragma unroll
    for (int lp = 0; lp < 16; lp++) {
        const int i = lp * 8 + h;
        int4   r4 = *(const int4*)  &srow[qi][i][0];
        float4 w4 = *(const float4*)&swt [qi][i][0];
        int   rr[4] = {r4.x, r4.y, r4.z, r4.w};
        float ww[4] = {w4.x, w4.y, w4.z, w4.w};
#pragma unroll
        for (int c = 0; c < 4; c++) {
            const __half2* vp = (const __half2*)&g_vproj[(size_t)rr[c] * C_ + coff];
            float2 f0 = __half22float2(__ldg(vp));
            float2 f1 = __half22float2(__ldg(vp + 1));
            acc.x += ww[c] * f0.x;
            acc.y += ww[c] * f0.y;
            acc.z += ww[c] * f1.x;
            acc.w += ww[c] * f1.y;
        }
    }
    *(float4*)&g_agg[(size_t)q * C_ + coff] = acc;
}

// ---------------------------------------------------------------------------
// kernel_launch
// ---------------------------------------------------------------------------
extern "C" void kernel_launch(void* const* d_in, const int* in_sizes, int n_in,
                              void* d_out, int out_size)
{
    const float* query  = (const float*)d_in[0];
    const float* ref    = (const float*)d_in[1];
    const float* values = (const float*)d_in[2];
    const float* W_so   = (const float*)d_in[3];
    const float* b_so   = (const float*)d_in[4];
    const float* W_aw   = (const float*)d_in[5];
    const float* b_aw   = (const float*)d_in[6];
    const float* W_v    = (const float*)d_in[7];
    const float* b_v    = (const float*)d_in[8];
    const float* W_o    = (const float*)d_in[9];
    const float* b_o    = (const float*)d_in[10];
    const int* batch_offsets = (const int*)d_in[11];
    float* out = (float*)d_out;
    (void)in_sizes; (void)n_in; (void)out_size;

    __half* vproj;
    float *offs, *awr, *agg;
    char *wvh, *wqc, *wo;
    cudaGetSymbolAddress((void**)&vproj, g_vproj);
    cudaGetSymbolAddress((void**)&offs,  g_offs);
    cudaGetSymbolAddress((void**)&awr,   g_awr);
    cudaGetSymbolAddress((void**)&agg,   g_agg);
    cudaGetSymbolAddress((void**)&wvh,   g_wvh_img);
    cudaGetSymbolAddress((void**)&wqc,   g_wqc_img);
    cudaGetSymbolAddress((void**)&wo,    g_wo_img);

    // 0) weight images (single launch)
    prep_all<<<448, 256>>>(W_v, W_so, W_aw, W_o, wvh, wqc, wo);

    // 1) vproj + offs + awr, one fused launch (3488 CTAs)
    gemm_all<<<NV_BLK + NQ_BLK, 128>>>(values, wvh, b_v, vproj,
                                       query, wqc, b_so, b_aw, offs, awr);

    // 2) softmax + bilinear sampling + head aggregation
    sample_kernel<<<Q_ / QPB, 256>>>(ref, batch_offsets);

    // 3) out = agg @ W_o^T + b_o  [8192 x 256] (bf16x3)
    {
        dim3 grid(Q_ / 64, 4);
        gemm_bf3<<<grid, 128>>>(agg, wo, b_o, out, 256);
    }
}

// round 11
// speedup vs baseline: 2.4741x; 1.0824x over previous
#include <cuda_runtime.h>
#include <cuda_bf16.h>
#include <cuda_fp16.h>
#include <cstdint>
#include <cstddef>

// ---------------------------------------------------------------------------
// Problem constants (fixed by the dataset)
// ---------------------------------------------------------------------------
#define Q_   8192
#define C_   256
#define LVL  4
#define NH_  8
#define DH_  32
#define HMAX_ 128

#define ROWS_PER_B 21760   // 16384+4096+1024+256
#define NROWS      43520   // 2 * ROWS_PER_B

// ---------------------------------------------------------------------------
// Scratch (device globals; no allocation allowed)
// ---------------------------------------------------------------------------
__device__ __half g_vproj[(size_t)NROWS * C_];  // projected valid values (fp16)
__device__ float  g_offs [(size_t)Q_ * 256];    // sampling-offset raw proj
__device__ float  g_awr  [(size_t)Q_ * 128];    // attention-weight logits
__device__ __half g_agg  [(size_t)Q_ * C_];     // per-query aggregated heads (fp16)

// bf16x3 weight image (combined W_so|W_aw): per (kb32, nb64): [hi 5120B | lo 5120B]
__device__ __align__(16) char g_wqc_img[491520];   // 384 rows: 8 kb x 6 nb x 10240
// fp16 weight images: per (kb, nb64) blob: 5120B (fp16x2 pairs)
__device__ __align__(16) char g_wvh_img[163840];   // W_v: 8 kb x 4 nb x 5120
__device__ __align__(16) char g_woh_img[163840];   // W_o: 8 kb x 4 nb x 5120

// ---------------------------------------------------------------------------
// Row mapping: compact row r -> offset into values[B,128,128,L,C]
// ---------------------------------------------------------------------------
__device__ __forceinline__ size_t map_a_row(int r) {
    int b  = r / ROWS_PER_B;
    int rr = r - b * ROWS_PER_B;
    int l, base, W;
    if (rr < 16384)      { l = 0; base = 0;     W = 128; }
    else if (rr < 20480) { l = 1; base = 16384; W = 64;  }
    else if (rr < 21504) { l = 2; base = 20480; W = 32;  }
    else                 { l = 3; base = 21504; W = 16;  }
    int idx = rr - base;
    int y = idx / W;
    int x = idx - y * W;
    return ((((size_t)b * HMAX_ + y) * HMAX_ + x) * LVL + l) * C_;
}

// ---------------------------------------------------------------------------
// helpers
// ---------------------------------------------------------------------------
__device__ __forceinline__ uint32_t smem_u32(const void* p) {
    uint32_t a;
    asm("{ .reg .u64 t; cvta.to.shared.u64 t, %1; cvt.u32.u64 %0, t; }"
        : "=r"(a) : "l"(p));
    return a;
}

__device__ __forceinline__ uint32_t pack_bf16x2(float e0, float e1) {
    uint32_t r;
    asm("cvt.rn.bf16x2.f32 %0, %1, %2;" : "=r"(r) : "f"(e1), "f"(e0));
    return r;
}

__device__ __forceinline__ uint32_t pack_f16x2(float e0, float e1) {
    uint32_t r;
    asm("cvt.rn.f16x2.f32 %0, %1, %2;" : "=r"(r) : "f"(e1), "f"(e0));
    return r;
}

__device__ __forceinline__ float bf_hi(float x) {
    return __bfloat162float(__float2bfloat16_rn(x));
}

__device__ __forceinline__ void mma_bf16(float* c, const uint32_t* a, const uint32_t* b) {
    asm volatile(
        "mma.sync.aligned.m16n8k16.row.col.f32.bf16.bf16.f32 "
        "{%0,%1,%2,%3}, {%4,%5,%6,%7}, {%8,%9}, {%0,%1,%2,%3};\n"
        : "+f"(c[0]), "+f"(c[1]), "+f"(c[2]), "+f"(c[3])
        : "r"(a[0]), "r"(a[1]), "r"(a[2]), "r"(a[3]), "r"(b[0]), "r"(b[1]));
}

__device__ __forceinline__ void mma_f16(float* c, const uint32_t* a, const uint32_t* b) {
    asm volatile(
        "mma.sync.aligned.m16n8k16.row.col.f32.f16.f16.f32 "
        "{%0,%1,%2,%3}, {%4,%5,%6,%7}, {%8,%9}, {%0,%1,%2,%3};\n"
        : "+f"(c[0]), "+f"(c[1]), "+f"(c[2]), "+f"(c[3])
        : "r"(a[0]), "r"(a[1]), "r"(a[2]), "r"(a[3]), "r"(b[0]), "r"(b[1]));
}

#define LDSM4(r, a) \
    asm volatile("ldmatrix.sync.aligned.m8n8.x4.shared.b16 {%0,%1,%2,%3}, [%4];" \
        : "=r"((r)[0]), "=r"((r)[1]), "=r"((r)[2]), "=r"((r)[3]) : "r"(a))

// ---------------------------------------------------------------------------
// Weight prep (single launch).
// blocks 0-127:   W_v -> fp16 image (256 rows)
// blocks 128-319: W_so|W_aw combined -> bf16x3 image (384 rows)
// blocks 320-447: W_o -> fp16 image (256 rows)
// ---------------------------------------------------------------------------
__global__ void prep_all(const float* __restrict__ Wv, const float* __restrict__ Wso,
                         const float* __restrict__ Waw, const float* __restrict__ Wo,
                         char* __restrict__ ivh, char* __restrict__ iqc,
                         char* __restrict__ ioh)
{
    int blk = blockIdx.x;
    if (blk < 128 || blk >= 320) {
        // fp16 image (W_v or W_o)
        const float* W = (blk < 128) ? Wv : Wo;
        char* img      = (blk < 128) ? ivh : ioh;
        int lb         = (blk < 128) ? blk : (blk - 320);
        int idx = lb * 256 + threadIdx.x;
        int n = idx >> 7, p = idx & 127;
        int k = p * 2;
        int kb = k >> 5, pl = (k & 31) >> 1;
        int nb = n >> 6, nl = n & 63;
        float a = W[(size_t)n * 256 + k];
        float b = W[(size_t)n * 256 + k + 1];
        char* blob = img + (size_t)(kb * 4 + nb) * 5120;
        *(uint32_t*)(blob + nl * 80 + pl * 4) = pack_f16x2(a, b);
        return;
    }
    // combined W_so|W_aw -> bf16x3 image (384 rows)
    int idx = (blk - 128) * 256 + threadIdx.x;
    int n = idx >> 7, p = idx & 127;
    const float* Wrow = (n < 256) ? (Wso + (size_t)n * 256) : (Waw + (size_t)(n - 256) * 256);
    int k = p * 2;
    int kb = k >> 5, pl = (k & 31) >> 1;
    int nb = n >> 6, nl = n & 63;
    float a = Wrow[k];
    float b = Wrow[k + 1];
    float ah = bf_hi(a), bh = bf_hi(b);
    char* blob = iqc + (size_t)(kb * 6 + nb) * 10240;
    uint32_t off = nl * 80 + pl * 4;
    *(uint32_t*)(blob + off)        = pack_bf16x2(ah, bh);
    *(uint32_t*)(blob + 5120 + off) = pack_bf16x2(a - ah, b - bh);
}

// ---------------------------------------------------------------------------
// Fused independent-GEMM batch, 64x64 tiles, 128 threads, double-buffered.
//  bid < 2720        : vproj tile (fp16 MMA)  C=values_map @ Wv^T -> fp16
//  bid >= 2720 (768) : query tile (bf16x3)    C=query @ [Wso|Waw]^T -> offs/awr
// ---------------------------------------------------------------------------
#define NV_BLK 2720   // (43520/64) * 4
#define NQ_BLK 768    // (8192/64) * 6

__global__ void __launch_bounds__(128)
gemm_all(const float* __restrict__ values, const char* __restrict__ wvh,
         const float* __restrict__ b_v, __half* __restrict__ vproj,
         const float* __restrict__ query, const char* __restrict__ wqc,
         const float* __restrict__ b_so, const float* __restrict__ b_aw,
         float* __restrict__ offs, float* __restrict__ awr)
{
    __shared__ __align__(16) char sm[2][20480];

    const int tid = threadIdx.x, wid = tid >> 5, lane = tid & 31;
    const int g = lane >> 2, t = lane & 3;
    const int wm = (wid & 1) * 32, wn = (wid >> 1) * 32;
    const int r    = tid >> 1;
    const int half = tid & 1;
    const int rr16 = lane & 15;
    const int chi  = ((lane >> 4) & 1) * 16;
    const uint32_t sbase = smem_u32(sm);

    float acc[2][4][4];
#pragma unroll
    for (int i = 0; i < 2; i++)
#pragma unroll
        for (int j = 0; j < 4; j++)
#pragma unroll
            for (int c = 0; c < 4; c++) acc[i][j][c] = 0.0f;

    const int bid = blockIdx.x;

    if (bid < NV_BLK) {
        // ================= vproj: fp16 MMA =================
        const int m0 = (bid >> 2) * 64, nb = bid & 3, n0 = nb * 64;
        const float* Ap = values + map_a_row(m0 + r) + half * 16;

        float4 pa[4];
        uint4  pb[3];
#pragma unroll
        for (int j = 0; j < 4; j++) pa[j] = *(const float4*)(Ap + j * 4);
        {
            const uint4* src = (const uint4*)(wvh + (size_t)nb * 5120);
#pragma unroll
            for (int j = 0; j < 3; j++) {
                int idx = tid + 128 * j;
                if (idx < 320) pb[j] = src[idx];
            }
        }
        {
            char* AH = sm[0] + r * 80 + half * 32;
#pragma unroll
            for (int j = 0; j < 4; j++) {
                float4 v = pa[j];
                *(uint32_t*)(AH + j * 8)     = pack_f16x2(v.x, v.y);
                *(uint32_t*)(AH + j * 8 + 4) = pack_f16x2(v.z, v.w);
            }
            uint4* dst = (uint4*)(sm[0] + 5120);
#pragma unroll
            for (int j = 0; j < 3; j++) {
                int idx = tid + 128 * j;
                if (idx < 320) dst[idx] = pb[j];
            }
        }
        __syncthreads();

        for (int kb = 0; kb < 8; kb++) {
            const int p = kb & 1;
            if (kb < 7) {
#pragma unroll
                for (int j = 0; j < 4; j++)
                    pa[j] = *(const float4*)(Ap + (kb + 1) * 32 + j * 4);
                const uint4* src = (const uint4*)(wvh + (size_t)((kb + 1) * 4 + nb) * 5120);
#pragma unroll
                for (int j = 0; j < 3; j++) {
                    int idx = tid + 128 * j;
                    if (idx < 320) pb[j] = src[idx];
                }
            }
            const uint32_t base = sbase + p * 20480;
#pragma unroll
            for (int ks = 0; ks < 2; ks++) {
                const int cb = ks * 32 + chi;
                uint32_t aH[2][4], bH[2][4];
#pragma unroll
                for (int fm = 0; fm < 2; fm++)
                    LDSM4(aH[fm], base + (wm + fm * 16 + rr16) * 80 + cb);
#pragma unroll
                for (int fp = 0; fp < 2; fp++)
                    LDSM4(bH[fp], base + 5120 + (wn + fp * 16 + rr16) * 80 + cb);
#pragma unroll
                for (int fm = 0; fm < 2; fm++)
#pragma unroll
                    for (int fn = 0; fn < 4; fn++) {
                        const int fp = fn >> 1, o = fn & 1;
                        uint32_t bh2[2] = {bH[fp][o], bH[fp][o + 2]};
                        mma_f16(acc[fm][fn], aH[fm], bh2);
                    }
            }
            if (kb < 7) {
                char* bufn = sm[p ^ 1];
                char* AH = bufn + r * 80 + half * 32;
#pragma unroll
                for (int j = 0; j < 4; j++) {
                    float4 v = pa[j];
                    *(uint32_t*)(AH + j * 8)     = pack_f16x2(v.x, v.y);
                    *(uint32_t*)(AH + j * 8 + 4) = pack_f16x2(v.z, v.w);
                }
                uint4* dst = (uint4*)(bufn + 5120);
#pragma unroll
                for (int j = 0; j < 3; j++) {
                    int idx = tid + 128 * j;
                    if (idx < 320) dst[idx] = pb[j];
                }
            }
            __syncthreads();
        }

#pragma unroll
        for (int fn = 0; fn < 4; fn++) {
            int cn = n0 + wn + fn * 8 + t * 2;
            float b0 = b_v[cn], b1 = b_v[cn + 1];
#pragma unroll
            for (int fm = 0; fm < 2; fm++) {
                int r0 = m0 + wm + fm * 16 + g;
                *(__half2*)&vproj[(size_t)r0 * 256 + cn] =
                    __floats2half2_rn(acc[fm][fn][0] + b0, acc[fm][fn][1] + b1);
                *(__half2*)&vproj[(size_t)(r0 + 8) * 256 + cn] =
                    __floats2half2_rn(acc[fm][fn][2] + b0, acc[fm][fn][3] + b1);
            }
        }
        return;
    }

    // ================= query offs+awr: bf16x3 =================
    {
        const int qid = bid - NV_BLK;
        const int m0 = (qid / 6) * 64, nb = qid % 6, n0 = nb * 64;
        const float* Ap = query + (size_t)(m0 + r) * 256 + half * 16;

        float4 pa[4];
        uint4  pb[5];
#pragma unroll
        for (int j = 0; j < 4; j++) pa[j] = *(const float4*)(Ap + j * 4);
        {
            const uint4* src = (const uint4*)(wqc + (size_t)nb * 10240);
#pragma unroll
            for (int j = 0; j < 5; j++) pb[j] = src[tid + 128 * j];
        }
        {
            char* AH = sm[0] + r * 80 + half * 32;
#pragma unroll
            for (int j = 0; j < 4; j++) {
                float4 v = pa[j];
                float xh = bf_hi(v.x), yh = bf_hi(v.y);
                float zh = bf_hi(v.z), wh = bf_hi(v.w);
                *(uint32_t*)(AH + j * 8)            = pack_bf16x2(xh, yh);
                *(uint32_t*)(AH + j * 8 + 4)        = pack_bf16x2(zh, wh);
                *(uint32_t*)(AH + 5120 + j * 8)     = pack_bf16x2(v.x - xh, v.y - yh);
                *(uint32_t*)(AH + 5120 + j * 8 + 4) = pack_bf16x2(v.z - zh, v.w - wh);
            }
            uint4* dst = (uint4*)(sm[0] + 10240);
#pragma unroll
            for (int j = 0; j < 5; j++) dst[tid + 128 * j] = pb[j];
        }
        __syncthreads();

        for (int kb = 0; kb < 8; kb++) {
            const int p = kb & 1;
            if (kb < 7) {
#pragma unroll
                for (int j = 0; j < 4; j++)
                    pa[j] = *(const float4*)(Ap + (kb + 1) * 32 + j * 4);
                const uint4* src = (const uint4*)(wqc + (size_t)((kb + 1) * 6 + nb) * 10240);
#pragma unroll
                for (int j = 0; j < 5; j++) pb[j] = src[tid + 128 * j];
            }
            const uint32_t base = sbase + p * 20480;
#pragma unroll
            for (int ks = 0; ks < 2; ks++) {
                const int cb = ks * 32 + chi;
                uint32_t aH[2][4], aL[2][4];
#pragma unroll
                for (int fm = 0; fm < 2; fm++) {
                    uint32_t ad = base + (wm + fm * 16 + rr16) * 80 + cb;
                    LDSM4(aH[fm], ad);
                    LDSM4(aL[fm], ad + 5120);
                }
                uint32_t bH[2][4], bL[2][4];
#pragma unroll
                for (int fp = 0; fp < 2; fp++) {
                    uint32_t bd = base + 10240 + (wn + fp * 16 + rr16) * 80 + cb;
                    LDSM4(bH[fp], bd);
                    LDSM4(bL[fp], bd + 5120);
                }
#pragma unroll
                for (int fm = 0; fm < 2; fm++)
#pragma unroll
                    for (int fn = 0; fn < 4; fn++) {
                        const int fp = fn >> 1, o = fn & 1;
                        uint32_t bh2[2] = {bH[fp][o], bH[fp][o + 2]};
                        uint32_t bl2[2] = {bL[fp][o], bL[fp][o + 2]};
                        mma_bf16(acc[fm][fn], aL[fm], bh2);
                        mma_bf16(acc[fm][fn], aH[fm], bl2);
                        mma_bf16(acc[fm][fn], aH[fm], bh2);
                    }
            }
            if (kb < 7) {
                char* bufn = sm[p ^ 1];
                char* AH = bufn + r * 80 + half * 32;
#pragma unroll
                for (int j = 0; j < 4; j++) {
                    float4 v = pa[j];
                    float xh = bf_hi(v.x), yh = bf_hi(v.y);
                    float zh = bf_hi(v.z), wh = bf_hi(v.w);
                    *(uint32_t*)(AH + j * 8)            = pack_bf16x2(xh, yh);
                    *(uint32_t*)(AH + j * 8 + 4)        = pack_bf16x2(zh, wh);
                    *(uint32_t*)(AH + 5120 + j * 8)     = pack_bf16x2(v.x - xh, v.y - yh);
                    *(uint32_t*)(AH + 5120 + j * 8 + 4) = pack_bf16x2(v.z - zh, v.w - wh);
                }
                uint4* dst = (uint4*)(bufn + 10240);
#pragma unroll
                for (int j = 0; j < 5; j++) dst[tid + 128 * j] = pb[j];
            }
            __syncthreads();
        }

        const bool is_aw = (n0 >= 256);
        const float* bias = is_aw ? b_aw : b_so;
        float* Cm = is_aw ? awr : offs;
        const int Nout = is_aw ? 128 : 256;
        const int ncol0 = is_aw ? (n0 - 256) : n0;
#pragma unroll
        for (int fn = 0; fn < 4; fn++) {
            int cn = ncol0 + wn + fn * 8 + t * 2;
            float b0 = bias[cn], b1 = bias[cn + 1];
#pragma unroll
            for (int fm = 0; fm < 2; fm++) {
                int r0 = m0 + wm + fm * 16 + g;
                *(float2*)&Cm[(size_t)r0 * Nout + cn] =
                    make_float2(acc[fm][fn][0] + b0, acc[fm][fn][1] + b1);
                *(float2*)&Cm[(size_t)(r0 + 8) * Nout + cn] =
                    make_float2(acc[fm][fn][2] + b0, acc[fm][fn][3] + b1);
            }
        }
    }
}

// ---------------------------------------------------------------------------
// out-proj GEMM: fp16 MMA, fp16 A (agg), 64x64 tile, 128 threads.
//   out[64 x 64] = agg[64 x 256] @ Wo[64 x 256]^T + b_o   (fp32 out)
// A is already fp16 row-major -> raw byte copy into ldmatrix layout.
// stage (10240B): A@0 (64 x 80), B@5120 (64 x 80). Double-buffered.
// ---------------------------------------------------------------------------
__global__ void __launch_bounds__(128)
gemm_out(const __half* __restrict__ A, const char* __restrict__ Bimg,
         const float* __restrict__ bias, float* __restrict__ Cm)
{
    __shared__ __align__(16) char sm[2][10240];

    const int tid = threadIdx.x, wid = tid >> 5, lane = tid & 31;
    const int g = lane >> 2, t = lane & 3;
    const int m0 = blockIdx.x * 64, n0 = blockIdx.y * 64;
    const int wm = (wid & 1) * 32, wn = (wid >> 1) * 32;
    const int r    = tid >> 1;
    const int half = tid & 1;
    const int rr16 = lane & 15;
    const int chi  = ((lane >> 4) & 1) * 16;
    const uint32_t sbase = smem_u32(sm);

    const __half* Ap = A + (size_t)(m0 + r) * 256 + half * 16;

    float acc[2][4][4];
#pragma unroll
    for (int i = 0; i < 2; i++)
#pragma unroll
        for (int j = 0; j < 4; j++)
#pragma unroll
            for (int c = 0; c < 4; c++) acc[i][j][c] = 0.0f;

    uint4 pa[2];
    uint4 pb[3];
    pa[0] = *(const uint4*)(Ap);
    pa[1] = *(const uint4*)(Ap + 8);
    {
        const uint4* src = (const uint4*)(Bimg + (size_t)blockIdx.y * 5120);
#pragma unroll
        for (int j = 0; j < 3; j++) {
            int idx = tid + 128 * j;
            if (idx < 320) pb[j] = src[idx];
        }
    }
    {
        char* AH = sm[0] + r * 80 + half * 32;
        *(uint4*)(AH)      = pa[0];
        *(uint4*)(AH + 16) = pa[1];
        uint4* dst = (uint4*)(sm[0] + 5120);
#pragma unroll
        for (int j = 0; j < 3; j++) {
            int idx = tid + 128 * j;
            if (idx < 320) dst[idx] = pb[j];
        }
    }
    __syncthreads();

    for (int kb = 0; kb < 8; kb++) {
        const int p = kb & 1;
        if (kb < 7) {
            pa[0] = *(const uint4*)(Ap + (kb + 1) * 32);
            pa[1] = *(const uint4*)(Ap + (kb + 1) * 32 + 8);
            const uint4* src = (const uint4*)(Bimg + (size_t)((kb + 1) * 4 + blockIdx.y) * 5120);
#pragma unroll
            for (int j = 0; j < 3; j++) {
                int idx = tid + 128 * j;
                if (idx < 320) pb[j] = src[idx];
            }
        }
        const uint32_t base = sbase + p * 10240;
#pragma unroll
        for (int ks = 0; ks < 2; ks++) {
            const int cb = ks * 32 + chi;
            uint32_t aH[2][4], bH[2][4];
#pragma unroll
            for (int fm = 0; fm < 2; fm++)
                LDSM4(aH[fm], base + (wm + fm * 16 + rr16) * 80 + cb);
#pragma unroll
            for (int fp = 0; fp < 2; fp++)
                LDSM4(bH[fp], base + 5120 + (wn + fp * 16 + rr16) * 80 + cb);
#pragma unroll
            for (int fm = 0; fm < 2; fm++)
#pragma unroll
                for (int fn = 0; fn < 4; fn++) {
                    const int fp = fn >> 1, o = fn & 1;
                    uint32_t bh2[2] = {bH[fp][o], bH[fp][o + 2]};
                    mma_f16(acc[fm][fn], aH[fm], bh2);
                }
        }
        if (kb < 7) {
            char* bufn = sm[p ^ 1];
            char* AH = bufn + r * 80 + half * 32;
            *(uint4*)(AH)      = pa[0];
            *(uint4*)(AH + 16) = pa[1];
            uint4* dst = (uint4*)(bufn + 5120);
#pragma unroll
            for (int j = 0; j < 3; j++) {
                int idx = tid + 128 * j;
                if (idx < 320) dst[idx] = pb[j];
            }
        }
        __syncthreads();
    }

#pragma unroll
    for (int fn = 0; fn < 4; fn++) {
        int cn = n0 + wn + fn * 8 + t * 2;
        float b0 = bias[cn], b1 = bias[cn + 1];
#pragma unroll
        for (int fm = 0; fm < 2; fm++) {
            int r0 = m0 + wm + fm * 16 + g;
            *(float2*)&Cm[(size_t)r0 * 256 + cn] =
                make_float2(acc[fm][fn][0] + b0, acc[fm][fn][1] + b1);
            *(float2*)&Cm[(size_t)(r0 + 8) * 256 + cn] =
                make_float2(acc[fm][fn][2] + b0, acc[fm][fn][3] + b1);
        }
    }
}

// ---------------------------------------------------------------------------
// Sampling kernel: 4 queries per block; branchless fp16 gathers; fp16 agg out.
// ---------------------------------------------------------------------------
#define QPB 4
__global__ __launch_bounds__(256)
void sample_kernel(const float* __restrict__ ref,
                   const int* __restrict__ batch_offsets)
{
    __shared__ float sL[QPB][128];
    __shared__ float hM[QPB][8];
    __shared__ float hR[QPB][8];
    __shared__ float sIS[QPB][2];
    __shared__ __align__(16) int   srow[QPB][128][4];
    __shared__ __align__(16) float swt [QPB][128][4];

    const int tid = threadIdx.x;
    const int q0  = blockIdx.x * QPB;
    const int boundary = batch_offsets[1];

#pragma unroll
    for (int j = tid; j < QPB * 128; j += 256)
        sL[j >> 7][j & 127] = g_awr[(size_t)(q0 + (j >> 7)) * 128 + (j & 127)];

    if (tid >= 224 && tid < 224 + QPB * 2) {
        int k = tid - 224;
        int qi = k >> 1, xy = k & 1;
        float v = ref[(q0 + qi) * 2 + xy];
        v = fminf(fmaxf(v, 0.0f), 1.0f);
        sIS[qi][xy] = logf(fmaxf(v, 1e-5f) / fmaxf(1.0f - v, 1e-5f));
    }
    __syncthreads();

    if (tid < QPB * 8) {
        int qi = tid >> 3, h = tid & 7;
        float m = -1e30f;
#pragma unroll
        for (int lp = 0; lp < 16; lp++) m = fmaxf(m, sL[qi][lp * 8 + h]);
        float s = 0.0f;
#pragma unroll
        for (int lp = 0; lp < 16; lp++) s += expf(sL[qi][lp * 8 + h] - m);
        hM[qi][h] = m;
        hR[qi][h] = 1.0f / s;
    }
    __syncthreads();

#pragma unroll
    for (int j = tid; j < QPB * 128; j += 256) {
        const int qi = j >> 7;
        const int i  = j & 127;
        const int q  = q0 + qi;
        const int h  = i & 7;
        const int lp = i >> 3;
        const int l  = lp >> 2;

        float aw = expf(sL[qi][i] - hM[qi][h]) * hR[qi][h];

        float ox = g_offs[(size_t)q * 256 + i * 2 + 0];
        float oy = g_offs[(size_t)q * 256 + i * 2 + 1];

        float locx = 1.0f / (1.0f + expf(-(sIS[qi][0] + ox)));
        float locy = 1.0f / (1.0f + expf(-(sIS[qi][1] + oy)));

        const int   Wl = HMAX_ >> l;
        const float Wf = (float)Wl;
        float x = locx * Wf - 0.5f;
        float y = locy * Wf - 0.5f;

        float x0f = floorf(x), y0f = floorf(y);
        float wx1 = x - x0f, wx0 = 1.0f - wx1;
        float wy1 = y - y0f, wy0 = 1.0f - wy1;
        int x0 = (int)x0f, y0 = (int)y0f;

        int b = (q >= boundary) ? 1 : 0;
        int lbase = (l >= 1 ? 16384 : 0) + (l >= 2 ? 4096 : 0) + (l >= 3 ? 1024 : 0);
        int base = b * ROWS_PER_B + lbase;

        int   xs[2]  = {x0, x0 + 1};
        int   ys2[2] = {y0, y0 + 1};
        float wxs[2] = {wx0, wx1};
        float wys[2] = {wy0, wy1};

#pragma unroll
        for (int cy = 0; cy < 2; cy++) {
#pragma unroll
            for (int cx = 0; cx < 2; cx++) {
                int c  = cy * 2 + cx;
                int xi = xs[cx], yi = ys2[cy];
                bool valid = (xi >= 0) & (xi < Wl) & (yi >= 0) & (yi < Wl);
                int xc = min(max(xi, 0), Wl - 1);
                int yc = min(max(yi, 0), Wl - 1);
                srow[qi][i][c] = base + yc * Wl + xc;
                swt [qi][i][c] = valid ? (aw * wys[cy] * wxs[cx]) : 0.0f;
            }
        }
    }
    __syncthreads();

    const int qi   = tid >> 6;
    const int tq   = tid & 63;
    const int h    = tq >> 3;
    const int coff = h * DH_ + (tq & 7) * 4;
    const int q    = q0 + qi;

    float4 acc = make_float4(0.0f, 0.0f, 0.0f, 0.0f);
#pragma unroll
    for (int lp = 0; lp < 16; lp++) {
        const int i = lp * 8 + h;
        int4   r4 = *(const int4*)  &srow[qi][i][0];
        float4 w4 = *(const float4*)&swt [qi][i][0];
        int   rr[4] = {r4.x, r4.y, r4.z, r4.w};
        float ww[4] = {w4.x, w4.y, w4.z, w4.w};
#pragma unroll
        for (int c = 0; c < 4; c++) {
            const __half2* vp = (const __half2*)&g_vproj[(size_t)rr[c] * C_ + coff];
            float2 f0 = __half22float2(__ldg(vp));
            float2 f1 = __half22float2(__ldg(vp + 1));
            acc.x += ww[c] * f0.x;
            acc.y += ww[c] * f0.y;
            acc.z += ww[c] * f1.x;
            acc.w += ww[c] * f1.y;
        }
    }
    *(__half2*)&g_agg[(size_t)q * C_ + coff]     = __floats2half2_rn(acc.x, acc.y);
    *(__half2*)&g_agg[(size_t)q * C_ + coff + 2] = __floats2half2_rn(acc.z, acc.w);
}

// ---------------------------------------------------------------------------
// kernel_launch
// ---------------------------------------------------------------------------
extern "C" void kernel_launch(void* const* d_in, const int* in_sizes, int n_in,
                              void* d_out, int out_size)
{
    const float* query  = (const float*)d_in[0];
    const float* ref    = (const float*)d_in[1];
    const float* values = (const float*)d_in[2];
    const float* W_so   = (const float*)d_in[3];
    const float* b_so   = (const float*)d_in[4];
    const float* W_aw   = (const float*)d_in[5];
    const float* b_aw   = (const float*)d_in[6];
    const float* W_v    = (const float*)d_in[7];
    const float* b_v    = (const float*)d_in[8];
    const float* W_o    = (const float*)d_in[9];
    const float* b_o    = (const float*)d_in[10];
    const int* batch_offsets = (const int*)d_in[11];
    float* out = (float*)d_out;
    (void)in_sizes; (void)n_in; (void)out_size;

    __half *vproj, *agg;
    float *offs, *awr;
    char *wvh, *wqc, *woh;
    cudaGetSymbolAddress((void**)&vproj, g_vproj);
    cudaGetSymbolAddress((void**)&offs,  g_offs);
    cudaGetSymbolAddress((void**)&awr,   g_awr);
    cudaGetSymbolAddress((void**)&agg,   g_agg);
    cudaGetSymbolAddress((void**)&wvh,   g_wvh_img);
    cudaGetSymbolAddress((void**)&wqc,   g_wqc_img);
    cudaGetSymbolAddress((void**)&woh,   g_woh_img);

    // 0) weight images (single launch)
    prep_all<<<448, 256>>>(W_v, W_so, W_aw, W_o, wvh, wqc, woh);

    // 1) vproj + offs + awr, one fused launch (3488 CTAs)
    gemm_all<<<NV_BLK + NQ_BLK, 128>>>(values, wvh, b_v, vproj,
                                       query, wqc, b_so, b_aw, offs, awr);

    // 2) softmax + bilinear sampling + head aggregation (fp16 agg out)
    sample_kernel<<<Q_ / QPB, 256>>>(ref, batch_offsets);

    // 3) out = agg @ W_o^T + b_o  [8192 x 256] (fp16 MMA)
    {
        dim3 grid(Q_ / 64, 4);
        gemm_out<<<grid, 128>>>(agg, woh, b_o, out);
    }
}

// round 12
// speedup vs baseline: 2.6027x; 1.0520x over previous
#include <cuda_runtime.h>
#include <cuda_bf16.h>
#include <cuda_fp16.h>
#include <cstdint>
#include <cstddef>

// ---------------------------------------------------------------------------
// Problem constants (fixed by the dataset)
// ---------------------------------------------------------------------------
#define Q_   8192
#define C_   256
#define LVL  4
#define NH_  8
#define DH_  32
#define HMAX_ 128

#define ROWS_PER_B 21760   // 16384+4096+1024+256
#define NROWS      43520   // 2 * ROWS_PER_B

// ---------------------------------------------------------------------------
// Scratch (device globals; no allocation allowed)
// ---------------------------------------------------------------------------
__device__ __half g_vproj[(size_t)NROWS * C_];  // projected valid values (fp16)
__device__ float  g_offs [(size_t)Q_ * 256];    // sampling-offset raw proj
__device__ float  g_awr  [(size_t)Q_ * 128];    // attention-weight logits
__device__ __half g_agg  [(size_t)Q_ * C_];     // per-query aggregated heads (fp16)

// bf16x3 weight image (combined W_so|W_aw): per (kb32, nb64): [hi 5120B | lo 5120B]
__device__ __align__(16) char g_wqc_img[491520];   // 384 rows: 8 kb x 6 nb x 10240
// fp16 weight images: per (kb, nb64) blob: 5120B (fp16x2 pairs)
__device__ __align__(16) char g_wvh_img[163840];   // W_v: 8 kb x 4 nb x 5120
__device__ __align__(16) char g_woh_img[163840];   // W_o: 8 kb x 4 nb x 5120

// ---------------------------------------------------------------------------
// Row mapping: compact row r -> offset into values[B,128,128,L,C]
// ---------------------------------------------------------------------------
__device__ __forceinline__ size_t map_a_row(int r) {
    int b  = r / ROWS_PER_B;
    int rr = r - b * ROWS_PER_B;
    int l, base, W;
    if (rr < 16384)      { l = 0; base = 0;     W = 128; }
    else if (rr < 20480) { l = 1; base = 16384; W = 64;  }
    else if (rr < 21504) { l = 2; base = 20480; W = 32;  }
    else                 { l = 3; base = 21504; W = 16;  }
    int idx = rr - base;
    int y = idx / W;
    int x = idx - y * W;
    return ((((size_t)b * HMAX_ + y) * HMAX_ + x) * LVL + l) * C_;
}

// ---------------------------------------------------------------------------
// helpers
// ---------------------------------------------------------------------------
__device__ __forceinline__ uint32_t smem_u32(const void* p) {
    uint32_t a;
    asm("{ .reg .u64 t; cvta.to.shared.u64 t, %1; cvt.u32.u64 %0, t; }"
        : "=r"(a) : "l"(p));
    return a;
}

__device__ __forceinline__ uint32_t pack_bf16x2(float e0, float e1) {
    uint32_t r;
    asm("cvt.rn.bf16x2.f32 %0, %1, %2;" : "=r"(r) : "f"(e1), "f"(e0));
    return r;
}

__device__ __forceinline__ uint32_t pack_f16x2(float e0, float e1) {
    uint32_t r;
    asm("cvt.rn.f16x2.f32 %0, %1, %2;" : "=r"(r) : "f"(e1), "f"(e0));
    return r;
}

__device__ __forceinline__ float bf_hi(float x) {
    return __bfloat162float(__float2bfloat16_rn(x));
}

__device__ __forceinline__ void mma_bf16(float* c, const uint32_t* a, const uint32_t* b) {
    asm volatile(
        "mma.sync.aligned.m16n8k16.row.col.f32.bf16.bf16.f32 "
        "{%0,%1,%2,%3}, {%4,%5,%6,%7}, {%8,%9}, {%0,%1,%2,%3};\n"
        : "+f"(c[0]), "+f"(c[1]), "+f"(c[2]), "+f"(c[3])
        : "r"(a[0]), "r"(a[1]), "r"(a[2]), "r"(a[3]), "r"(b[0]), "r"(b[1]));
}

__device__ __forceinline__ void mma_f16(float* c, const uint32_t* a, const uint32_t* b) {
    asm volatile(
        "mma.sync.aligned.m16n8k16.row.col.f32.f16.f16.f32 "
        "{%0,%1,%2,%3}, {%4,%5,%6,%7}, {%8,%9}, {%0,%1,%2,%3};\n"
        : "+f"(c[0]), "+f"(c[1]), "+f"(c[2]), "+f"(c[3])
        : "r"(a[0]), "r"(a[1]), "r"(a[2]), "r"(a[3]), "r"(b[0]), "r"(b[1]));
}

#define LDSM4(r, a) \
    asm volatile("ldmatrix.sync.aligned.m8n8.x4.shared.b16 {%0,%1,%2,%3}, [%4];" \
        : "=r"((r)[0]), "=r"((r)[1]), "=r"((r)[2]), "=r"((r)[3]) : "r"(a))

// ---------------------------------------------------------------------------
// Weight prep (single launch).
// blocks 0-127:   W_v -> fp16 image (256 rows)
// blocks 128-319: W_so|W_aw combined -> bf16x3 image (384 rows)
// blocks 320-447: W_o -> fp16 image (256 rows)
// ---------------------------------------------------------------------------
__global__ void prep_all(const float* __restrict__ Wv, const float* __restrict__ Wso,
                         const float* __restrict__ Waw, const float* __restrict__ Wo,
                         char* __restrict__ ivh, char* __restrict__ iqc,
                         char* __restrict__ ioh)
{
    int blk = blockIdx.x;
    if (blk < 128 || blk >= 320) {
        const float* W = (blk < 128) ? Wv : Wo;
        char* img      = (blk < 128) ? ivh : ioh;
        int lb         = (blk < 128) ? blk : (blk - 320);
        int idx = lb * 256 + threadIdx.x;
        int n = idx >> 7, p = idx & 127;
        int k = p * 2;
        int kb = k >> 5, pl = (k & 31) >> 1;
        int nb = n >> 6, nl = n & 63;
        float a = W[(size_t)n * 256 + k];
        float b = W[(size_t)n * 256 + k + 1];
        char* blob = img + (size_t)(kb * 4 + nb) * 5120;
        *(uint32_t*)(blob + nl * 80 + pl * 4) = pack_f16x2(a, b);
        return;
    }
    int idx = (blk - 128) * 256 + threadIdx.x;
    int n = idx >> 7, p = idx & 127;
    const float* Wrow = (n < 256) ? (Wso + (size_t)n * 256) : (Waw + (size_t)(n - 256) * 256);
    int k = p * 2;
    int kb = k >> 5, pl = (k & 31) >> 1;
    int nb = n >> 6, nl = n & 63;
    float a = Wrow[k];
    float b = Wrow[k + 1];
    float ah = bf_hi(a), bh = bf_hi(b);
    char* blob = iqc + (size_t)(kb * 6 + nb) * 10240;
    uint32_t off = nl * 80 + pl * 4;
    *(uint32_t*)(blob + off)        = pack_bf16x2(ah, bh);
    *(uint32_t*)(blob + 5120 + off) = pack_bf16x2(a - ah, b - bh);
}

// ---------------------------------------------------------------------------
// Fused independent-GEMM batch, 64x64 tiles, 256 threads (8 warps 2m x 4n,
// warp tile 32x16), double-buffered smem.
//  bid < 2720        : vproj tile (fp16 MMA)  C=values_map @ Wv^T -> fp16
//  bid >= 2720 (768) : query tile (bf16x3)    C=query @ [Wso|Waw]^T -> offs/awr
// A load: 4 threads/row, 8 floats each. Stage layouts:
//   vproj: A@0 (64x80), B@5120;  query: AH@0 AL@5120 B(hi|lo)@10240
// ---------------------------------------------------------------------------
#define NV_BLK 2720   // (43520/64) * 4
#define NQ_BLK 768    // (8192/64) * 6

__global__ void __launch_bounds__(256)
gemm_all(const float* __restrict__ values, const char* __restrict__ wvh,
         const float* __restrict__ b_v, __half* __restrict__ vproj,
         const float* __restrict__ query, const char* __restrict__ wqc,
         const float* __restrict__ b_so, const float* __restrict__ b_aw,
         float* __restrict__ offs, float* __restrict__ awr)
{
    __shared__ __align__(16) char sm[2][20480];

    const int tid = threadIdx.x, wid = tid >> 5, lane = tid & 31;
    const int g = lane >> 2, t = lane & 3;
    const int wm = (wid & 1) * 32, wn = (wid >> 1) * 16;
    const int r  = tid >> 2;
    const int q4 = tid & 3;
    const int rr16 = lane & 15;
    const int chi  = ((lane >> 4) & 1) * 16;
    const uint32_t sbase = smem_u32(sm);

    float acc[2][2][4];
#pragma unroll
    for (int i = 0; i < 2; i++)
#pragma unroll
        for (int j = 0; j < 2; j++)
#pragma unroll
            for (int c = 0; c < 4; c++) acc[i][j][c] = 0.0f;

    const int bid = blockIdx.x;

    if (bid < NV_BLK) {
        // ================= vproj: fp16 MMA =================
        const int m0 = (bid >> 2) * 64, nb = bid & 3, n0 = nb * 64;
        const float* Ap = values + map_a_row(m0 + r) + q4 * 8;

        float4 pa[2];
        uint4  pb[2];
        pa[0] = *(const float4*)(Ap);
        pa[1] = *(const float4*)(Ap + 4);
        {
            const uint4* src = (const uint4*)(wvh + (size_t)nb * 5120);
            pb[0] = src[tid];
            if (tid < 64) pb[1] = src[tid + 256];
        }
        {
            uint4 w;
            w.x = pack_f16x2(pa[0].x, pa[0].y);
            w.y = pack_f16x2(pa[0].z, pa[0].w);
            w.z = pack_f16x2(pa[1].x, pa[1].y);
            w.w = pack_f16x2(pa[1].z, pa[1].w);
            *(uint4*)(sm[0] + r * 80 + q4 * 16) = w;
            uint4* dst = (uint4*)(sm[0] + 5120);
            dst[tid] = pb[0];
            if (tid < 64) dst[tid + 256] = pb[1];
        }
        __syncthreads();

        for (int kb = 0; kb < 8; kb++) {
            const int p = kb & 1;
            if (kb < 7) {
                pa[0] = *(const float4*)(Ap + (kb + 1) * 32);
                pa[1] = *(const float4*)(Ap + (kb + 1) * 32 + 4);
                const uint4* src = (const uint4*)(wvh + (size_t)((kb + 1) * 4 + nb) * 5120);
                pb[0] = src[tid];
                if (tid < 64) pb[1] = src[tid + 256];
            }
            const uint32_t base = sbase + p * 20480;
#pragma unroll
            for (int ks = 0; ks < 2; ks++) {
                const int cb = ks * 32 + chi;
                uint32_t aH[2][4], bH[4];
#pragma unroll
                for (int fm = 0; fm < 2; fm++)
                    LDSM4(aH[fm], base + (wm + fm * 16 + rr16) * 80 + cb);
                LDSM4(bH, base + 5120 + (wn + rr16) * 80 + cb);
#pragma unroll
                for (int fm = 0; fm < 2; fm++)
#pragma unroll
                    for (int fn = 0; fn < 2; fn++) {
                        uint32_t bh2[2] = {bH[fn], bH[fn + 2]};
                        mma_f16(acc[fm][fn], aH[fm], bh2);
                    }
            }
            if (kb < 7) {
                char* bufn = sm[p ^ 1];
                uint4 w;
                w.x = pack_f16x2(pa[0].x, pa[0].y);
                w.y = pack_f16x2(pa[0].z, pa[0].w);
                w.z = pack_f16x2(pa[1].x, pa[1].y);
                w.w = pack_f16x2(pa[1].z, pa[1].w);
                *(uint4*)(bufn + r * 80 + q4 * 16) = w;
                uint4* dst = (uint4*)(bufn + 5120);
                dst[tid] = pb[0];
                if (tid < 64) dst[tid + 256] = pb[1];
            }
            __syncthreads();
        }

#pragma unroll
        for (int fn = 0; fn < 2; fn++) {
            int cn = n0 + wn + fn * 8 + t * 2;
            float b0 = b_v[cn], b1 = b_v[cn + 1];
#pragma unroll
            for (int fm = 0; fm < 2; fm++) {
                int r0 = m0 + wm + fm * 16 + g;
                *(__half2*)&vproj[(size_t)r0 * 256 + cn] =
                    __floats2half2_rn(acc[fm][fn][0] + b0, acc[fm][fn][1] + b1);
                *(__half2*)&vproj[(size_t)(r0 + 8) * 256 + cn] =
                    __floats2half2_rn(acc[fm][fn][2] + b0, acc[fm][fn][3] + b1);
            }
        }
        return;
    }

    // ================= query offs+awr: bf16x3 =================
    {
        const int qid = bid - NV_BLK;
        const int m0 = (qid / 6) * 64, nb = qid % 6, n0 = nb * 64;
        const float* Ap = query + (size_t)(m0 + r) * 256 + q4 * 8;

        float4 pa[2];
        uint4  pb[3];
        pa[0] = *(const float4*)(Ap);
        pa[1] = *(const float4*)(Ap + 4);
        {
            const uint4* src = (const uint4*)(wqc + (size_t)nb * 10240);
            pb[0] = src[tid];
            pb[1] = src[tid + 256];
            if (tid < 128) pb[2] = src[tid + 512];
        }
        {
            char* AH = sm[0] + r * 80 + q4 * 16;
            uint4 wh, wl;
            float xh = bf_hi(pa[0].x), yh = bf_hi(pa[0].y);
            float zh = bf_hi(pa[0].z), wwh = bf_hi(pa[0].w);
            float xh2 = bf_hi(pa[1].x), yh2 = bf_hi(pa[1].y);
            float zh2 = bf_hi(pa[1].z), wh2 = bf_hi(pa[1].w);
            wh.x = pack_bf16x2(xh, yh);   wh.y = pack_bf16x2(zh, wwh);
            wh.z = pack_bf16x2(xh2, yh2); wh.w = pack_bf16x2(zh2, wh2);
            wl.x = pack_bf16x2(pa[0].x - xh, pa[0].y - yh);
            wl.y = pack_bf16x2(pa[0].z - zh, pa[0].w - wwh);
            wl.z = pack_bf16x2(pa[1].x - xh2, pa[1].y - yh2);
            wl.w = pack_bf16x2(pa[1].z - zh2, pa[1].w - wh2);
            *(uint4*)(AH)        = wh;
            *(uint4*)(AH + 5120) = wl;
            uint4* dst = (uint4*)(sm[0] + 10240);
            dst[tid] = pb[0];
            dst[tid + 256] = pb[1];
            if (tid < 128) dst[tid + 512] = pb[2];
        }
        __syncthreads();

        for (int kb = 0; kb < 8; kb++) {
            const int p = kb & 1;
            if (kb < 7) {
                pa[0] = *(const float4*)(Ap + (kb + 1) * 32);
                pa[1] = *(const float4*)(Ap + (kb + 1) * 32 + 4);
                const uint4* src = (const uint4*)(wqc + (size_t)((kb + 1) * 6 + nb) * 10240);
                pb[0] = src[tid];
                pb[1] = src[tid + 256];
                if (tid < 128) pb[2] = src[tid + 512];
            }
            const uint32_t base = sbase + p * 20480;
#pragma unroll
            for (int ks = 0; ks < 2; ks++) {
                const int cb = ks * 32 + chi;
                uint32_t aH[2][4], aL[2][4], bH[4], bL[4];
#pragma unroll
                for (int fm = 0; fm < 2; fm++) {
                    uint32_t ad = base + (wm + fm * 16 + rr16) * 80 + cb;
                    LDSM4(aH[fm], ad);
                    LDSM4(aL[fm], ad + 5120);
                }
                {
                    uint32_t bd = base + 10240 + (wn + rr16) * 80 + cb;
                    LDSM4(bH, bd);
                    LDSM4(bL, bd + 5120);
                }
#pragma unroll
                for (int fm = 0; fm < 2; fm++)
#pragma unroll
                    for (int fn = 0; fn < 2; fn++) {
                        uint32_t bh2[2] = {bH[fn], bH[fn + 2]};
                        uint32_t bl2[2] = {bL[fn], bL[fn + 2]};
                        mma_bf16(acc[fm][fn], aL[fm], bh2);
                        mma_bf16(acc[fm][fn], aH[fm], bl2);
                        mma_bf16(acc[fm][fn], aH[fm], bh2);
                    }
            }
            if (kb < 7) {
                char* bufn = sm[p ^ 1];
                char* AH = bufn + r * 80 + q4 * 16;
                uint4 wh, wl;
                float xh = bf_hi(pa[0].x), yh = bf_hi(pa[0].y);
                float zh = bf_hi(pa[0].z), wwh = bf_hi(pa[0].w);
                float xh2 = bf_hi(pa[1].x), yh2 = bf_hi(pa[1].y);
                float zh2 = bf_hi(pa[1].z), wh2 = bf_hi(pa[1].w);
                wh.x = pack_bf16x2(xh, yh);   wh.y = pack_bf16x2(zh, wwh);
                wh.z = pack_bf16x2(xh2, yh2); wh.w = pack_bf16x2(zh2, wh2);
                wl.x = pack_bf16x2(pa[0].x - xh, pa[0].y - yh);
                wl.y = pack_bf16x2(pa[0].z - zh, pa[0].w - wwh);
                wl.z = pack_bf16x2(pa[1].x - xh2, pa[1].y - yh2);
                wl.w = pack_bf16x2(pa[1].z - zh2, pa[1].w - wh2);
                *(uint4*)(AH)        = wh;
                *(uint4*)(AH + 5120) = wl;
                uint4* dst = (uint4*)(bufn + 10240);
                dst[tid] = pb[0];
                dst[tid + 256] = pb[1];
                if (tid < 128) dst[tid + 512] = pb[2];
            }
            __syncthreads();
        }

        const bool is_aw = (n0 >= 256);
        const float* bias = is_aw ? b_aw : b_so;
        float* Cm = is_aw ? awr : offs;
        const int Nout = is_aw ? 128 : 256;
        const int ncol0 = is_aw ? (n0 - 256) : n0;
#pragma unroll
        for (int fn = 0; fn < 2; fn++) {
            int cn = ncol0 + wn + fn * 8 + t * 2;
            float b0 = bias[cn], b1 = bias[cn + 1];
#pragma unroll
            for (int fm = 0; fm < 2; fm++) {
                int r0 = m0 + wm + fm * 16 + g;
                *(float2*)&Cm[(size_t)r0 * Nout + cn] =
                    make_float2(acc[fm][fn][0] + b0, acc[fm][fn][1] + b1);
                *(float2*)&Cm[(size_t)(r0 + 8) * Nout + cn] =
                    make_float2(acc[fm][fn][2] + b0, acc[fm][fn][3] + b1);
            }
        }
    }
}

// ---------------------------------------------------------------------------
// out-proj GEMM: fp16 MMA, fp16 A (agg), 64x64 tile, 256 threads (8 warps).
//   out[64 x 64] = agg[64 x 256] @ Wo[64 x 256]^T + b_o   (fp32 out)
// stage (10240B): A@0 (64 x 80), B@5120 (64 x 80). Double-buffered.
// ---------------------------------------------------------------------------
__global__ void __launch_bounds__(256)
gemm_out(const __half* __restrict__ A, const char* __restrict__ Bimg,
         const float* __restrict__ bias, float* __restrict__ Cm)
{
    __shared__ __align__(16) char sm[2][10240];

    const int tid = threadIdx.x, wid = tid >> 5, lane = tid & 31;
    const int g = lane >> 2, t = lane & 3;
    const int m0 = blockIdx.x * 64, n0 = blockIdx.y * 64;
    const int wm = (wid & 1) * 32, wn = (wid >> 1) * 16;
    const int r  = tid >> 2;
    const int q4 = tid & 3;
    const int rr16 = lane & 15;
    const int chi  = ((lane >> 4) & 1) * 16;
    const uint32_t sbase = smem_u32(sm);

    const __half* Ap = A + (size_t)(m0 + r) * 256 + q4 * 8;

    float acc[2][2][4];
#pragma unroll
    for (int i = 0; i < 2; i++)
#pragma unroll
        for (int j = 0; j < 2; j++)
#pragma unroll
            for (int c = 0; c < 4; c++) acc[i][j][c] = 0.0f;

    uint4 pa;
    uint4 pb[2];
    pa = *(const uint4*)(Ap);
    {
        const uint4* src = (const uint4*)(Bimg + (size_t)blockIdx.y * 5120);
        pb[0] = src[tid];
        if (tid < 64) pb[1] = src[tid + 256];
    }
    {
        *(uint4*)(sm[0] + r * 80 + q4 * 16) = pa;
        uint4* dst = (uint4*)(sm[0] + 5120);
        dst[tid] = pb[0];
        if (tid < 64) dst[tid + 256] = pb[1];
    }
    __syncthreads();

    for (int kb = 0; kb < 8; kb++) {
        const int p = kb & 1;
        if (kb < 7) {
            pa = *(const uint4*)(Ap + (kb + 1) * 32);
            const uint4* src = (const uint4*)(Bimg + (size_t)((kb + 1) * 4 + blockIdx.y) * 5120);
            pb[0] = src[tid];
            if (tid < 64) pb[1] = src[tid + 256];
        }
        const uint32_t base = sbase + p * 10240;
#pragma unroll
        for (int ks = 0; ks < 2; ks++) {
            const int cb = ks * 32 + chi;
            uint32_t aH[2][4], bH[4];
#pragma unroll
            for (int fm = 0; fm < 2; fm++)
                LDSM4(aH[fm], base + (wm + fm * 16 + rr16) * 80 + cb);
            LDSM4(bH, base + 5120 + (wn + rr16) * 80 + cb);
#pragma unroll
            for (int fm = 0; fm < 2; fm++)
#pragma unroll
                for (int fn = 0; fn < 2; fn++) {
                    uint32_t bh2[2] = {bH[fn], bH[fn + 2]};
                    mma_f16(acc[fm][fn], aH[fm], bh2);
                }
        }
        if (kb < 7) {
            char* bufn = sm[p ^ 1];
            *(uint4*)(bufn + r * 80 + q4 * 16) = pa;
            uint4* dst = (uint4*)(bufn + 5120);
            dst[tid] = pb[0];
            if (tid < 64) dst[tid + 256] = pb[1];
        }
        __syncthreads();
    }

#pragma unroll
    for (int fn = 0; fn < 2; fn++) {
        int cn = n0 + wn + fn * 8 + t * 2;
        float b0 = bias[cn], b1 = bias[cn + 1];
#pragma unroll
        for (int fm = 0; fm < 2; fm++) {
            int r0 = m0 + wm + fm * 16 + g;
            *(float2*)&Cm[(size_t)r0 * 256 + cn] =
                make_float2(acc[fm][fn][0] + b0, acc[fm][fn][1] + b1);
            *(float2*)&Cm[(size_t)(r0 + 8) * 256 + cn] =
                make_float2(acc[fm][fn][2] + b0, acc[fm][fn][3] + b1);
        }
    }
}

// ---------------------------------------------------------------------------
// Sampling kernel: 4 queries per block; branchless fp16 gathers; fp16 agg out.
// ---------------------------------------------------------------------------
#define QPB 4
__global__ __launch_bounds__(256)
void sample_kernel(const float* __restrict__ ref,
                   const int* __restrict__ batch_offsets)
{
    __shared__ float sL[QPB][128];
    __shared__ float hM[QPB][8];
    __shared__ float hR[QPB][8];
    __shared__ float sIS[QPB][2];
    __shared__ __align__(16) int   srow[QPB][128][4];
    __shared__ __align__(16) float swt [QPB][128][4];

    const int tid = threadIdx.x;
    const int q0  = blockIdx.x * QPB;
    const int boundary = batch_offsets[1];

#pragma unroll
    for (int j = tid; j < QPB * 128; j += 256)
        sL[j >> 7][j & 127] = g_awr[(size_t)(q0 + (j >> 7)) * 128 + (j & 127)];

    if (tid >= 224 && tid < 224 + QPB * 2) {
        int k = tid - 224;
        int qi = k >> 1, xy = k & 1;
        float v = ref[(q0 + qi) * 2 + xy];
        v = fminf(fmaxf(v, 0.0f), 1.0f);
        sIS[qi][xy] = logf(fmaxf(v, 1e-5f) / fmaxf(1.0f - v, 1e-5f));
    }
    __syncthreads();

    if (tid < QPB * 8) {
        int qi = tid >> 3, h = tid & 7;
        float m = -1e30f;
#pragma unroll
        for (int lp = 0; lp < 16; lp++) m = fmaxf(m, sL[qi][lp * 8 + h]);
        float s = 0.0f;
#pragma unroll
        for (int lp = 0; lp < 16; lp++) s += expf(sL[qi][lp * 8 + h] - m);
        hM[qi][h] = m;
        hR[qi][h] = 1.0f / s;
    }
    __syncthreads();

#pragma unroll
    for (int j = tid; j < QPB * 128; j += 256) {
        const int qi = j >> 7;
        const int i  = j & 127;
        const int q  = q0 + qi;
        const int h  = i & 7;
        const int lp = i >> 3;
        const int l  = lp >> 2;

        float aw = expf(sL[qi][i] - hM[qi][h]) * hR[qi][h];

        float ox = g_offs[(size_t)q * 256 + i * 2 + 0];
        float oy = g_offs[(size_t)q * 256 + i * 2 + 1];

        float locx = 1.0f / (1.0f + expf(-(sIS[qi][0] + ox)));
        float locy = 1.0f / (1.0f + expf(-(sIS[qi][1] + oy)));

        const int   Wl = HMAX_ >> l;
        const float Wf = (float)Wl;
        float x = locx * Wf - 0.5f;
        float y = locy * Wf - 0.5f;

        float x0f = floorf(x), y0f = floorf(y);
        float wx1 = x - x0f, wx0 = 1.0f - wx1;
        float wy1 = y - y0f, wy0 = 1.0f - wy1;
        int x0 = (int)x0f, y0 = (int)y0f;

        int b = (q >= boundary) ? 1 : 0;
        int lbase = (l >= 1 ? 16384 : 0) + (l >= 2 ? 4096 : 0) + (l >= 3 ? 1024 : 0);
        int base = b * ROWS_PER_B + lbase;

        int   xs[2]  = {x0, x0 + 1};
        int   ys2[2] = {y0, y0 + 1};
        float wxs[2] = {wx0, wx1};
        float wys[2] = {wy0, wy1};

#pragma unroll
        for (int cy = 0; cy < 2; cy++) {
#pragma unroll
            for (int cx = 0; cx < 2; cx++) {
                int c  = cy * 2 + cx;
                int xi = xs[cx], yi = ys2[cy];
                bool valid = (xi >= 0) & (xi < Wl) & (yi >= 0) & (yi < Wl);
                int xc = min(max(xi, 0), Wl - 1);
                int yc = min(max(yi, 0), Wl - 1);
                srow[qi][i][c] = base + yc * Wl + xc;
                swt [qi][i][c] = valid ? (aw * wys[cy] * wxs[cx]) : 0.0f;
            }
        }
    }
    __syncthreads();

    const int qi   = tid >> 6;
    const int tq   = tid & 63;
    const int h    = tq >> 3;
    const int coff = h * DH_ + (tq & 7) * 4;
    const int q    = q0 + qi;

    float4 acc = make_float4(0.0f, 0.0f, 0.0f, 0.0f);
#pragma unroll
    for (int lp = 0; lp < 16; lp++) {
        const int i = lp * 8 + h;
        int4   r4 = *(const int4*)  &srow[qi][i][0];
        float4 w4 = *(const float4*)&swt [qi][i][0];
        int   rr[4] = {r4.x, r4.y, r4.z, r4.w};
        float ww[4] = {w4.x, w4.y, w4.z, w4.w};
#pragma unroll
        for (int c = 0; c < 4; c++) {
            const __half2* vp = (const __half2*)&g_vproj[(size_t)rr[c] * C_ + coff];
            float2 f0 = __half22float2(__ldg(vp));
            float2 f1 = __half22float2(__ldg(vp + 1));
            acc.x += ww[c] * f0.x;
            acc.y += ww[c] * f0.y;
            acc.z += ww[c] * f1.x;
            acc.w += ww[c] * f1.y;
        }
    }
    *(__half2*)&g_agg[(size_t)q * C_ + coff]     = __floats2half2_rn(acc.x, acc.y);
    *(__half2*)&g_agg[(size_t)q * C_ + coff + 2] = __floats2half2_rn(acc.z, acc.w);
}

// ---------------------------------------------------------------------------
// kernel_launch
// ---------------------------------------------------------------------------
extern "C" void kernel_launch(void* const* d_in, const int* in_sizes, int n_in,
                              void* d_out, int out_size)
{
    const float* query  = (const float*)d_in[0];
    const float* ref    = (const float*)d_in[1];
    const float* values = (const float*)d_in[2];
    const float* W_so   = (const float*)d_in[3];
    const float* b_so   = (const float*)d_in[4];
    const float* W_aw   = (const float*)d_in[5];
    const float* b_aw   = (const float*)d_in[6];
    const float* W_v    = (const float*)d_in[7];
    const float* b_v    = (const float*)d_in[8];
    const float* W_o    = (const float*)d_in[9];
    const float* b_o    = (const float*)d_in[10];
    const int* batch_offsets = (const int*)d_in[11];
    float* out = (float*)d_out;
    (void)in_sizes; (void)n_in; (void)out_size;

    __half *vproj, *agg;
    float *offs, *awr;
    char *wvh, *wqc, *woh;
    cudaGetSymbolAddress((void**)&vproj, g_vproj);
    cudaGetSymbolAddress((void**)&offs,  g_offs);
    cudaGetSymbolAddress((void**)&awr,   g_awr);
    cudaGetSymbolAddress((void**)&agg,   g_agg);
    cudaGetSymbolAddress((void**)&wvh,   g_wvh_img);
    cudaGetSymbolAddress((void**)&wqc,   g_wqc_img);
    cudaGetSymbolAddress((void**)&woh,   g_woh_img);

    // 0) weight images (single launch)
    prep_all<<<448, 256>>>(W_v, W_so, W_aw, W_o, wvh, wqc, woh);

    // 1) vproj + offs + awr, one fused launch (3488 CTAs, 8 warps each)
    gemm_all<<<NV_BLK + NQ_BLK, 256>>>(values, wvh, b_v, vproj,
                                       query, wqc, b_so, b_aw, offs, awr);

    // 2) softmax + bilinear sampling + head aggregation (fp16 agg out)
    sample_kernel<<<Q_ / QPB, 256>>>(ref, batch_offsets);

    // 3) out = agg @ W_o^T + b_o  [8192 x 256] (fp16 MMA, 8 warps/CTA)
    {
        dim3 grid(Q_ / 64, 4);
        gemm_out<<<grid, 256>>>(agg, woh, b_o, out);
    }
}

// round 13
// speedup vs baseline: 2.8549x; 1.0969x over previous
#include <cuda_runtime.h>
#include <cuda_bf16.h>
#include <cuda_fp16.h>
#include <cstdint>
#include <cstddef>

// ---------------------------------------------------------------------------
// Problem constants (fixed by the dataset)
// ---------------------------------------------------------------------------
#define Q_   8192
#define C_   256
#define LVL  4
#define NH_  8
#define DH_  32
#define HMAX_ 128

#define ROWS_PER_B 21760   // 16384+4096+1024+256
#define NROWS      43520   // 2 * ROWS_PER_B

// ---------------------------------------------------------------------------
// Scratch (device globals; no allocation allowed)
// ---------------------------------------------------------------------------
__device__ __half g_vproj[(size_t)NROWS * C_];  // projected valid values (fp16)
__device__ float  g_offs [(size_t)Q_ * 256];    // sampling-offset raw proj
__device__ float  g_awr  [(size_t)Q_ * 128];    // attention-weight logits
__device__ __half g_agg  [(size_t)Q_ * C_];     // per-query aggregated heads (fp16)

// bf16x3 weight image (combined W_so|W_aw): per (kb32, nb64): [hi 5120B | lo 5120B]
__device__ __align__(16) char g_wqc_img[491520];   // 384 rows: 8 kb x 6 nb x 10240
// fp16 weight images: per (kb, nb64) blob: 5120B (fp16x2 pairs)
__device__ __align__(16) char g_wvh_img[163840];   // W_v: 8 kb x 4 nb x 5120
__device__ __align__(16) char g_woh_img[163840];   // W_o: 8 kb x 4 nb x 5120

// ---------------------------------------------------------------------------
// Row mapping: compact row r -> offset into values[B,128,128,L,C]
// ---------------------------------------------------------------------------
__device__ __forceinline__ size_t map_a_row(int r) {
    int b  = r / ROWS_PER_B;
    int rr = r - b * ROWS_PER_B;
    int l, base, W;
    if (rr < 16384)      { l = 0; base = 0;     W = 128; }
    else if (rr < 20480) { l = 1; base = 16384; W = 64;  }
    else if (rr < 21504) { l = 2; base = 20480; W = 32;  }
    else                 { l = 3; base = 21504; W = 16;  }
    int idx = rr - base;
    int y = idx / W;
    int x = idx - y * W;
    return ((((size_t)b * HMAX_ + y) * HMAX_ + x) * LVL + l) * C_;
}

// ---------------------------------------------------------------------------
// helpers
// ---------------------------------------------------------------------------
__device__ __forceinline__ uint32_t smem_u32(const void* p) {
    uint32_t a;
    asm("{ .reg .u64 t; cvta.to.shared.u64 t, %1; cvt.u32.u64 %0, t; }"
        : "=r"(a) : "l"(p));
    return a;
}

__device__ __forceinline__ uint32_t pack_bf16x2(float e0, float e1) {
    uint32_t r;
    asm("cvt.rn.bf16x2.f32 %0, %1, %2;" : "=r"(r) : "f"(e1), "f"(e0));
    return r;
}

__device__ __forceinline__ uint32_t pack_f16x2(float e0, float e1) {
    uint32_t r;
    asm("cvt.rn.f16x2.f32 %0, %1, %2;" : "=r"(r) : "f"(e1), "f"(e0));
    return r;
}

__device__ __forceinline__ float bf_hi(float x) {
    return __bfloat162float(__float2bfloat16_rn(x));
}

__device__ __forceinline__ void mma_bf16(float* c, const uint32_t* a, const uint32_t* b) {
    asm volatile(
        "mma.sync.aligned.m16n8k16.row.col.f32.bf16.bf16.f32 "
        "{%0,%1,%2,%3}, {%4,%5,%6,%7}, {%8,%9}, {%0,%1,%2,%3};\n"
        : "+f"(c[0]), "+f"(c[1]), "+f"(c[2]), "+f"(c[3])
        : "r"(a[0]), "r"(a[1]), "r"(a[2]), "r"(a[3]), "r"(b[0]), "r"(b[1]));
}

__device__ __forceinline__ void mma_f16(float* c, const uint32_t* a, const uint32_t* b) {
    asm volatile(
        "mma.sync.aligned.m16n8k16.row.col.f32.f16.f16.f32 "
        "{%0,%1,%2,%3}, {%4,%5,%6,%7}, {%8,%9}, {%0,%1,%2,%3};\n"
        : "+f"(c[0]), "+f"(c[1]), "+f"(c[2]), "+f"(c[3])
        : "r"(a[0]), "r"(a[1]), "r"(a[2]), "r"(a[3]), "r"(b[0]), "r"(b[1]));
}

#define LDSM4(r, a) \
    asm volatile("ldmatrix.sync.aligned.m8n8.x4.shared.b16 {%0,%1,%2,%3}, [%4];" \
        : "=r"((r)[0]), "=r"((r)[1]), "=r"((r)[2]), "=r"((r)[3]) : "r"(a))

__device__ __forceinline__ void cp16(uint32_t dst, const void* src) {
    asm volatile("cp.async.cg.shared.global [%0], [%1], 16;"
                 :: "r"(dst), "l"(src) : "memory");
}
#define CP_COMMIT() asm volatile("cp.async.commit_group;" ::: "memory")
#define CP_WAIT(n)  asm volatile("cp.async.wait_group %0;" :: "n"(n) : "memory")

// tail-aware wait: guarantee stage kb complete given issue schedule (3-ahead)
__device__ __forceinline__ void cp_wait_stage(int kb) {
    if (kb < 6)      CP_WAIT(2);
    else if (kb == 6) CP_WAIT(1);
    else              CP_WAIT(0);
}

// ---------------------------------------------------------------------------
// Weight prep (single launch).
// blocks 0-127:   W_v -> fp16 image (256 rows)
// blocks 128-319: W_so|W_aw combined -> bf16x3 image (384 rows)
// blocks 320-447: W_o -> fp16 image (256 rows)
// ---------------------------------------------------------------------------
__global__ void prep_all(const float* __restrict__ Wv, const float* __restrict__ Wso,
                         const float* __restrict__ Waw, const float* __restrict__ Wo,
                         char* __restrict__ ivh, char* __restrict__ iqc,
                         char* __restrict__ ioh)
{
    int blk = blockIdx.x;
    if (blk < 128 || blk >= 320) {
        const float* W = (blk < 128) ? Wv : Wo;
        char* img      = (blk < 128) ? ivh : ioh;
        int lb         = (blk < 128) ? blk : (blk - 320);
        int idx = lb * 256 + threadIdx.x;
        int n = idx >> 7, p = idx & 127;
        int k = p * 2;
        int kb = k >> 5, pl = (k & 31) >> 1;
        int nb = n >> 6, nl = n & 63;
        float a = W[(size_t)n * 256 + k];
        float b = W[(size_t)n * 256 + k + 1];
        char* blob = img + (size_t)(kb * 4 + nb) * 5120;
        *(uint32_t*)(blob + nl * 80 + pl * 4) = pack_f16x2(a, b);
        return;
    }
    int idx = (blk - 128) * 256 + threadIdx.x;
    int n = idx >> 7, p = idx & 127;
    const float* Wrow = (n < 256) ? (Wso + (size_t)n * 256) : (Waw + (size_t)(n - 256) * 256);
    int k = p * 2;
    int kb = k >> 5, pl = (k & 31) >> 1;
    int nb = n >> 6, nl = n & 63;
    float a = Wrow[k];
    float b = Wrow[k + 1];
    float ah = bf_hi(a), bh = bf_hi(b);
    char* blob = iqc + (size_t)(kb * 6 + nb) * 10240;
    uint32_t off = nl * 80 + pl * 4;
    *(uint32_t*)(blob + off)        = pack_bf16x2(ah, bh);
    *(uint32_t*)(blob + 5120 + off) = pack_bf16x2(a - ah, b - bh);
}

// ---------------------------------------------------------------------------
// Fused independent-GEMM batch, 64x64 tiles, 256 threads (8 warps 2m x 4n).
//  bid < 2720        : vproj tile (fp16 MMA)  C=values_map @ Wv^T -> fp16
//  bid >= 2720 (768) : query tile (bf16x3)    C=query @ [Wso|Waw]^T -> offs/awr
// B: 4-stage cp.async; A: 2-deep register prefetch (needs conversion).
// smem: vproj  A p*5120 (2 bufs), B 10240+s*5120 (4 stages)       = 30720
//       query  A p*10240 [hi|lo@+5120] (2), B 20480+s*10240 (4)   = 61440
// ---------------------------------------------------------------------------
#define NV_BLK 2720   // (43520/64) * 4
#define NQ_BLK 768    // (8192/64) * 6

__global__ void __launch_bounds__(256)
gemm_all(const float* __restrict__ values, const char* __restrict__ wvh,
         const float* __restrict__ b_v, __half* __restrict__ vproj,
         const float* __restrict__ query, const char* __restrict__ wqc,
         const float* __restrict__ b_so, const float* __restrict__ b_aw,
         float* __restrict__ offs, float* __restrict__ awr)
{
    __shared__ __align__(16) char sm[61440];

    const int tid = threadIdx.x, wid = tid >> 5, lane = tid & 31;
    const int g = lane >> 2, t = lane & 3;
    const int wm = (wid & 1) * 32, wn = (wid >> 1) * 16;
    const int r  = tid >> 2;
    const int q4 = tid & 3;
    const int rr16 = lane & 15;
    const int chi  = ((lane >> 4) & 1) * 16;
    const uint32_t sbase = smem_u32(sm);

    float acc[2][2][4];
#pragma unroll
    for (int i = 0; i < 2; i++)
#pragma unroll
        for (int j = 0; j < 2; j++)
#pragma unroll
            for (int c = 0; c < 4; c++) acc[i][j][c] = 0.0f;

    const int bid = blockIdx.x;

    if (bid < NV_BLK) {
        // ================= vproj: fp16 MMA =================
        const int m0 = (bid >> 2) * 64, nb = bid & 3, n0 = nb * 64;
        const float* Ap = values + map_a_row(m0 + r) + q4 * 8;
        const uint32_t aoff = r * 80 + q4 * 16;

        // B issue helper data
        const char* bsrc0 = wvh + (size_t)nb * 5120;

        // prologue: A stage0 -> smem; A stages 1,2 -> regs; B stages 0..2 async
        {
            float4 v0 = *(const float4*)(Ap);
            float4 v1 = *(const float4*)(Ap + 4);
            uint4 w;
            w.x = pack_f16x2(v0.x, v0.y); w.y = pack_f16x2(v0.z, v0.w);
            w.z = pack_f16x2(v1.x, v1.y); w.w = pack_f16x2(v1.z, v1.w);
            *(uint4*)(sm + aoff) = w;
        }
        float4 rA[2][2];
        rA[0][0] = *(const float4*)(Ap + 32);
        rA[0][1] = *(const float4*)(Ap + 36);
        rA[1][0] = *(const float4*)(Ap + 64);
        rA[1][1] = *(const float4*)(Ap + 68);
#pragma unroll
        for (int s = 0; s < 3; s++) {
            uint32_t bd = sbase + 10240 + s * 5120;
            const char* bs = bsrc0 + (size_t)s * 4 * 5120;
            cp16(bd + tid * 16, bs + tid * 16);
            if (tid < 64) cp16(bd + (tid + 256) * 16, bs + (tid + 256) * 16);
            CP_COMMIT();
        }

#pragma unroll
        for (int kb = 0; kb < 8; kb++) {
            cp_wait_stage(kb);
            __syncthreads();

            // store A stage kb+1 from rA[0]; shift; LDG stage kb+3
            if (kb < 7) {
                uint4 w;
                w.x = pack_f16x2(rA[0][0].x, rA[0][0].y);
                w.y = pack_f16x2(rA[0][0].z, rA[0][0].w);
                w.z = pack_f16x2(rA[0][1].x, rA[0][1].y);
                w.w = pack_f16x2(rA[0][1].z, rA[0][1].w);
                *(uint4*)(sm + ((kb + 1) & 1) * 5120 + aoff) = w;
                rA[0][0] = rA[1][0]; rA[0][1] = rA[1][1];
                if (kb + 3 < 8) {
                    rA[1][0] = *(const float4*)(Ap + (kb + 3) * 32);
                    rA[1][1] = *(const float4*)(Ap + (kb + 3) * 32 + 4);
                }
            }
            // issue B stage kb+3
            if (kb + 3 < 8) {
                uint32_t bd = sbase + 10240 + ((kb + 3) & 3) * 5120;
                const char* bs = bsrc0 + (size_t)(kb + 3) * 4 * 5120;
                cp16(bd + tid * 16, bs + tid * 16);
                if (tid < 64) cp16(bd + (tid + 256) * 16, bs + (tid + 256) * 16);
                CP_COMMIT();
            }

            const uint32_t baseA = sbase + (kb & 1) * 5120;
            const uint32_t baseB = sbase + 10240 + (kb & 3) * 5120;
#pragma unroll
            for (int ks = 0; ks < 2; ks++) {
                const int cb = ks * 32 + chi;
                uint32_t aH[2][4], bH[4];
#pragma unroll
                for (int fm = 0; fm < 2; fm++)
                    LDSM4(aH[fm], baseA + (wm + fm * 16 + rr16) * 80 + cb);
                LDSM4(bH, baseB + (wn + rr16) * 80 + cb);
#pragma unroll
                for (int fm = 0; fm < 2; fm++)
#pragma unroll
                    for (int fn = 0; fn < 2; fn++) {
                        uint32_t bh2[2] = {bH[fn], bH[fn + 2]};
                        mma_f16(acc[fm][fn], aH[fm], bh2);
                    }
            }
        }

#pragma unroll
        for (int fn = 0; fn < 2; fn++) {
            int cn = n0 + wn + fn * 8 + t * 2;
            float b0 = b_v[cn], b1 = b_v[cn + 1];
#pragma unroll
            for (int fm = 0; fm < 2; fm++) {
                int r0 = m0 + wm + fm * 16 + g;
                *(__half2*)&vproj[(size_t)r0 * 256 + cn] =
                    __floats2half2_rn(acc[fm][fn][0] + b0, acc[fm][fn][1] + b1);
                *(__half2*)&vproj[(size_t)(r0 + 8) * 256 + cn] =
                    __floats2half2_rn(acc[fm][fn][2] + b0, acc[fm][fn][3] + b1);
            }
        }
        return;
    }

    // ================= query offs+awr: bf16x3 =================
    {
        const int qid = bid - NV_BLK;
        const int m0 = (qid / 6) * 64, nb = qid % 6, n0 = nb * 64;
        const float* Ap = query + (size_t)(m0 + r) * 256 + q4 * 8;
        const uint32_t aoff = r * 80 + q4 * 16;
        const char* bsrc0 = wqc + (size_t)nb * 10240;

        // prologue
        {
            float4 v0 = *(const float4*)(Ap);
            float4 v1 = *(const float4*)(Ap + 4);
            float xh = bf_hi(v0.x), yh = bf_hi(v0.y);
            float zh = bf_hi(v0.z), wwh = bf_hi(v0.w);
            float xh2 = bf_hi(v1.x), yh2 = bf_hi(v1.y);
            float zh2 = bf_hi(v1.z), wh2 = bf_hi(v1.w);
            uint4 wh, wl;
            wh.x = pack_bf16x2(xh, yh);   wh.y = pack_bf16x2(zh, wwh);
            wh.z = pack_bf16x2(xh2, yh2); wh.w = pack_bf16x2(zh2, wh2);
            wl.x = pack_bf16x2(v0.x - xh, v0.y - yh);
            wl.y = pack_bf16x2(v0.z - zh, v0.w - wwh);
            wl.z = pack_bf16x2(v1.x - xh2, v1.y - yh2);
            wl.w = pack_bf16x2(v1.z - zh2, v1.w - wh2);
            *(uint4*)(sm + aoff)        = wh;
            *(uint4*)(sm + 5120 + aoff) = wl;
        }
        float4 rA[2][2];
        rA[0][0] = *(const float4*)(Ap + 32);
        rA[0][1] = *(const float4*)(Ap + 36);
        rA[1][0] = *(const float4*)(Ap + 64);
        rA[1][1] = *(const float4*)(Ap + 68);
#pragma unroll
        for (int s = 0; s < 3; s++) {
            uint32_t bd = sbase + 20480 + s * 10240;
            const char* bs = bsrc0 + (size_t)s * 6 * 10240;
            cp16(bd + tid * 16, bs + tid * 16);
            cp16(bd + (tid + 256) * 16, bs + (tid + 256) * 16);
            if (tid < 128) cp16(bd + (tid + 512) * 16, bs + (tid + 512) * 16);
            CP_COMMIT();
        }

#pragma unroll
        for (int kb = 0; kb < 8; kb++) {
            cp_wait_stage(kb);
            __syncthreads();

            if (kb < 7) {
                float4 v0 = rA[0][0], v1 = rA[0][1];
                float xh = bf_hi(v0.x), yh = bf_hi(v0.y);
                float zh = bf_hi(v0.z), wwh = bf_hi(v0.w);
                float xh2 = bf_hi(v1.x), yh2 = bf_hi(v1.y);
                float zh2 = bf_hi(v1.z), wh2 = bf_hi(v1.w);
                uint4 wh, wl;
                wh.x = pack_bf16x2(xh, yh);   wh.y = pack_bf16x2(zh, wwh);
                wh.z = pack_bf16x2(xh2, yh2); wh.w = pack_bf16x2(zh2, wh2);
                wl.x = pack_bf16x2(v0.x - xh, v0.y - yh);
                wl.y = pack_bf16x2(v0.z - zh, v0.w - wwh);
                wl.z = pack_bf16x2(v1.x - xh2, v1.y - yh2);
                wl.w = pack_bf16x2(v1.z - zh2, v1.w - wh2);
                uint32_t ab = ((kb + 1) & 1) * 10240;
                *(uint4*)(sm + ab + aoff)        = wh;
                *(uint4*)(sm + ab + 5120 + aoff) = wl;
                rA[0][0] = rA[1][0]; rA[0][1] = rA[1][1];
                if (kb + 3 < 8) {
                    rA[1][0] = *(const float4*)(Ap + (kb + 3) * 32);
                    rA[1][1] = *(const float4*)(Ap + (kb + 3) * 32 + 4);
                }
            }
            if (kb + 3 < 8) {
                uint32_t bd = sbase + 20480 + ((kb + 3) & 3) * 10240;
                const char* bs = bsrc0 + (size_t)(kb + 3) * 6 * 10240;
                cp16(bd + tid * 16, bs + tid * 16);
                cp16(bd + (tid + 256) * 16, bs + (tid + 256) * 16);
                if (tid < 128) cp16(bd + (tid + 512) * 16, bs + (tid + 512) * 16);
                CP_COMMIT();
            }

            const uint32_t baseA = sbase + (kb & 1) * 10240;
            const uint32_t baseB = sbase + 20480 + (kb & 3) * 10240;
#pragma unroll
            for (int ks = 0; ks < 2; ks++) {
                const int cb = ks * 32 + chi;
                uint32_t aH[2][4], aL[2][4], bH[4], bL[4];
#pragma unroll
                for (int fm = 0; fm < 2; fm++) {
                    uint32_t ad = baseA + (wm + fm * 16 + rr16) * 80 + cb;
                    LDSM4(aH[fm], ad);
                    LDSM4(aL[fm], ad + 5120);
                }
                {
                    uint32_t bd = baseB + (wn + rr16) * 80 + cb;
                    LDSM4(bH, bd);
                    LDSM4(bL, bd + 5120);
                }
#pragma unroll
                for (int fm = 0; fm < 2; fm++)
#pragma unroll
                    for (int fn = 0; fn < 2; fn++) {
                        uint32_t bh2[2] = {bH[fn], bH[fn + 2]};
                        uint32_t bl2[2] = {bL[fn], bL[fn + 2]};
                        mma_bf16(acc[fm][fn], aL[fm], bh2);
                        mma_bf16(acc[fm][fn], aH[fm], bl2);
                        mma_bf16(acc[fm][fn], aH[fm], bh2);
                    }
            }
        }

        const bool is_aw = (n0 >= 256);
        const float* bias = is_aw ? b_aw : b_so;
        float* Cm = is_aw ? awr : offs;
        const int Nout = is_aw ? 128 : 256;
        const int ncol0 = is_aw ? (n0 - 256) : n0;
#pragma unroll
        for (int fn = 0; fn < 2; fn++) {
            int cn = ncol0 + wn + fn * 8 + t * 2;
            float b0 = bias[cn], b1 = bias[cn + 1];
#pragma unroll
            for (int fm = 0; fm < 2; fm++) {
                int r0 = m0 + wm + fm * 16 + g;
                *(float2*)&Cm[(size_t)r0 * Nout + cn] =
                    make_float2(acc[fm][fn][0] + b0, acc[fm][fn][1] + b1);
                *(float2*)&Cm[(size_t)(r0 + 8) * Nout + cn] =
                    make_float2(acc[fm][fn][2] + b0, acc[fm][fn][3] + b1);
            }
        }
    }
}

// ---------------------------------------------------------------------------
// out-proj GEMM: fp16 MMA, pure 4-stage cp.async (A and B raw copies).
//   out[64 x 64] = agg[64 x 256] @ Wo[64 x 256]^T + b_o  (fp32 out)
// stage (10240B): A@0 (64 x 80), B@5120. 4 stages = 40KB.
// ---------------------------------------------------------------------------
__global__ void __launch_bounds__(256)
gemm_out(const __half* __restrict__ A, const char* __restrict__ Bimg,
         const float* __restrict__ bias, float* __restrict__ Cm)
{
    __shared__ __align__(16) char sm[40960];

    const int tid = threadIdx.x, wid = tid >> 5, lane = tid & 31;
    const int g = lane >> 2, t = lane & 3;
    const int m0 = blockIdx.x * 64, n0 = blockIdx.y * 64;
    const int wm = (wid & 1) * 32, wn = (wid >> 1) * 16;
    const int r  = tid >> 2;
    const int q4 = tid & 3;
    const int rr16 = lane & 15;
    const int chi  = ((lane >> 4) & 1) * 16;
    const uint32_t sbase = smem_u32(sm);

    const char* asrc = (const char*)(A + (size_t)(m0 + r) * 256) + q4 * 16;
    const char* bsrc0 = Bimg + (size_t)blockIdx.y * 5120;
    const uint32_t aoff = r * 80 + q4 * 16;

    float acc[2][2][4];
#pragma unroll
    for (int i = 0; i < 2; i++)
#pragma unroll
        for (int j = 0; j < 2; j++)
#pragma unroll
            for (int c = 0; c < 4; c++) acc[i][j][c] = 0.0f;

    // prologue: issue stages 0..2
#pragma unroll
    for (int s = 0; s < 3; s++) {
        uint32_t sb = sbase + s * 10240;
        cp16(sb + aoff, asrc + (size_t)s * 64);
        uint32_t bd = sb + 5120;
        const char* bs = bsrc0 + (size_t)s * 4 * 5120;
        cp16(bd + tid * 16, bs + tid * 16);
        if (tid < 64) cp16(bd + (tid + 256) * 16, bs + (tid + 256) * 16);
        CP_COMMIT();
    }

#pragma unroll
    for (int kb = 0; kb < 8; kb++) {
        cp_wait_stage(kb);
        __syncthreads();

        if (kb + 3 < 8) {
            uint32_t sb = sbase + ((kb + 3) & 3) * 10240;
            cp16(sb + aoff, asrc + (size_t)(kb + 3) * 64);
            uint32_t bd = sb + 5120;
            const char* bs = bsrc0 + (size_t)(kb + 3) * 4 * 5120;
            cp16(bd + tid * 16, bs + tid * 16);
            if (tid < 64) cp16(bd + (tid + 256) * 16, bs + (tid + 256) * 16);
            CP_COMMIT();
        }

        const uint32_t base = sbase + (kb & 3) * 10240;
#pragma unroll
        for (int ks = 0; ks < 2; ks++) {
            const int cb = ks * 32 + chi;
            uint32_t aH[2][4], bH[4];
#pragma unroll
            for (int fm = 0; fm < 2; fm++)
                LDSM4(aH[fm], base + (wm + fm * 16 + rr16) * 80 + cb);
            LDSM4(bH, base + 5120 + (wn + rr16) * 80 + cb);
#pragma unroll
            for (int fm = 0; fm < 2; fm++)
#pragma unroll
                for (int fn = 0; fn < 2; fn++) {
                    uint32_t bh2[2] = {bH[fn], bH[fn + 2]};
                    mma_f16(acc[fm][fn], aH[fm], bh2);
                }
        }
    }

#pragma unroll
    for (int fn = 0; fn < 2; fn++) {
        int cn = n0 + wn + fn * 8 + t * 2;
        float b0 = bias[cn], b1 = bias[cn + 1];
#pragma unroll
        for (int fm = 0; fm < 2; fm++) {
            int r0 = m0 + wm + fm * 16 + g;
            *(float2*)&Cm[(size_t)r0 * 256 + cn] =
                make_float2(acc[fm][fn][0] + b0, acc[fm][fn][1] + b1);
            *(float2*)&Cm[(size_t)(r0 + 8) * 256 + cn] =
                make_float2(acc[fm][fn][2] + b0, acc[fm][fn][3] + b1);
        }
    }
}

// ---------------------------------------------------------------------------
// Sampling kernel: 4 queries per block; branchless fp16 gathers; fp16 agg out.
// ---------------------------------------------------------------------------
#define QPB 4
__global__ __launch_bounds__(256)
void sample_kernel(const float* __restrict__ ref,
                   const int* __restrict__ batch_offsets)
{
    __shared__ float sL[QPB][128];
    __shared__ float hM[QPB][8];
    __shared__ float hR[QPB][8];
    __shared__ float sIS[QPB][2];
    __shared__ __align__(16) int   srow[QPB][128][4];
    __shared__ __align__(16) float swt [QPB][128][4];

    const int tid = threadIdx.x;
    const int q0  = blockIdx.x * QPB;
    const int boundary = batch_offsets[1];

#pragma unroll
    for (int j = tid; j < QPB * 128; j += 256)
        sL[j >> 7][j & 127] = g_awr[(size_t)(q0 + (j >> 7)) * 128 + (j & 127)];

    if (tid >= 224 && tid < 224 + QPB * 2) {
        int k = tid - 224;
        int qi = k >> 1, xy = k & 1;
        float v = ref[(q0 + qi) * 2 + xy];
        v = fminf(fmaxf(v, 0.0f), 1.0f);
        sIS[qi][xy] = logf(fmaxf(v, 1e-5f) / fmaxf(1.0f - v, 1e-5f));
    }
    __syncthreads();

    if (tid < QPB * 8) {
        int qi = tid >> 3, h = tid & 7;
        float m = -1e30f;
#pragma unroll
        for (int lp = 0; lp < 16; lp++) m = fmaxf(m, sL[qi][lp * 8 + h]);
        float s = 0.0f;
#pragma unroll
        for (int lp = 0; lp < 16; lp++) s += expf(sL[qi][lp * 8 + h] - m);
        hM[qi][h] = m;
        hR[qi][h] = 1.0f / s;
    }
    __syncthreads();

#pragma unroll
    for (int j = tid; j < QPB * 128; j += 256) {
        const int qi = j >> 7;
        const int i  = j & 127;
        const int q  = q0 + qi;
        const int h  = i & 7;
        const int lp = i >> 3;
        const int l  = lp >> 2;

        float aw = expf(sL[qi][i] - hM[qi][h]) * hR[qi][h];

        float ox = g_offs[(size_t)q * 256 + i * 2 + 0];
        float oy = g_offs[(size_t)q * 256 + i * 2 + 1];

        float locx = 1.0f / (1.0f + expf(-(sIS[qi][0] + ox)));
        float locy = 1.0f / (1.0f + expf(-(sIS[qi][1] + oy)));

        const int   Wl = HMAX_ >> l;
        const float Wf = (float)Wl;
        float x = locx * Wf - 0.5f;
        float y = locy * Wf - 0.5f;

        float x0f = floorf(x), y0f = floorf(y);
        float wx1 = x - x0f, wx0 = 1.0f - wx1;
        float wy1 = y - y0f, wy0 = 1.0f - wy1;
        int x0 = (int)x0f, y0 = (int)y0f;

        int b = (q >= boundary) ? 1 : 0;
        int lbase = (l >= 1 ? 16384 : 0) + (l >= 2 ? 4096 : 0) + (l >= 3 ? 1024 : 0);
        int base = b * ROWS_PER_B + lbase;

        int   xs[2]  = {x0, x0 + 1};
        int   ys2[2] = {y0, y0 + 1};
        float wxs[2] = {wx0, wx1};
        float wys[2] = {wy0, wy1};

#pragma unroll
        for (int cy = 0; cy < 2; cy++) {
#pragma unroll
            for (int cx = 0; cx < 2; cx++) {
                int c  = cy * 2 + cx;
                int xi = xs[cx], yi = ys2[cy];
                bool valid = (xi >= 0) & (xi < Wl) & (yi >= 0) & (yi < Wl);
                int xc = min(max(xi, 0), Wl - 1);
                int yc = min(max(yi, 0), Wl - 1);
                srow[qi][i][c] = base + yc * Wl + xc;
                swt [qi][i][c] = valid ? (aw * wys[cy] * wxs[cx]) : 0.0f;
            }
        }
    }
    __syncthreads();

    const int qi   = tid >> 6;
    const int tq   = tid & 63;
    const int h    = tq >> 3;
    const int coff = h * DH_ + (tq & 7) * 4;
    const int q    = q0 + qi;

    float4 acc = make_float4(0.0f, 0.0f, 0.0f, 0.0f);
#pragma unroll
    for (int lp = 0; lp < 16; lp++) {
        const int i = lp * 8 + h;
        int4   r4 = *(const int4*)  &srow[qi][i][0];
        float4 w4 = *(const float4*)&swt [qi][i][0];
        int   rr[4] = {r4.x, r4.y, r4.z, r4.w};
        float ww[4] = {w4.x, w4.y, w4.z, w4.w};
#pragma unroll
        for (int c = 0; c < 4; c++) {
            const __half2* vp = (const __half2*)&g_vproj[(size_t)rr[c] * C_ + coff];
            float2 f0 = __half22float2(__ldg(vp));
            float2 f1 = __half22float2(__ldg(vp + 1));
            acc.x += ww[c] * f0.x;
            acc.y += ww[c] * f0.y;
            acc.z += ww[c] * f1.x;
            acc.w += ww[c] * f1.y;
        }
    }
    *(__half2*)&g_agg[(size_t)q * C_ + coff]     = __floats2half2_rn(acc.x, acc.y);
    *(__half2*)&g_agg[(size_t)q * C_ + coff + 2] = __floats2half2_rn(acc.z, acc.w);
}

// ---------------------------------------------------------------------------
// kernel_launch
// ---------------------------------------------------------------------------
extern "C" void kernel_launch(void* const* d_in, const int* in_sizes, int n_in,
                              void* d_out, int out_size)
{
    const float* query  = (const float*)d_in[0];
    const float* ref    = (const float*)d_in[1];
    const float* values = (const float*)d_in[2];
    const float* W_so   = (const float*)d_in[3];
    const float* b_so   = (const float*)d_in[4];
    const float* W_aw   = (const float*)d_in[5];
    const float* b_aw   = (const float*)d_in[6];
    const float* W_v    = (const float*)d_in[7];
    const float* b_v    = (const float*)d_in[8];
    const float* W_o    = (const float*)d_in[9];
    const float* b_o    = (const float*)d_in[10];
    const int* batch_offsets = (const int*)d_in[11];
    float* out = (float*)d_out;
    (void)in_sizes; (void)n_in; (void)out_size;

    __half *vproj, *agg;
    float *offs, *awr;
    char *wvh, *wqc, *woh;
    cudaGetSymbolAddress((void**)&vproj, g_vproj);
    cudaGetSymbolAddress((void**)&offs,  g_offs);
    cudaGetSymbolAddress((void**)&awr,   g_awr);
    cudaGetSymbolAddress((void**)&agg,   g_agg);
    cudaGetSymbolAddress((void**)&wvh,   g_wvh_img);
    cudaGetSymbolAddress((void**)&wqc,   g_wqc_img);
    cudaGetSymbolAddress((void**)&woh,   g_woh_img);

    // 0) weight images (single launch)
    prep_all<<<448, 256>>>(W_v, W_so, W_aw, W_o, wvh, wqc, woh);

    // 1) vproj + offs + awr, one fused launch (3488 CTAs, 8 warps each)
    gemm_all<<<NV_BLK + NQ_BLK, 256>>>(values, wvh, b_v, vproj,
                                       query, wqc, b_so, b_aw, offs, awr);

    // 2) softmax + bilinear sampling + head aggregation (fp16 agg out)
    sample_kernel<<<Q_ / QPB, 256>>>(ref, batch_offsets);

    // 3) out = agg @ W_o^T + b_o  [8192 x 256] (fp16 MMA, cp.async 4-stage)
    {
        dim3 grid(Q_ / 64, 4);
        gemm_out<<<grid, 256>>>(agg, woh, b_o, out);
    }
}

// round 14
// speedup vs baseline: 2.9568x; 1.0357x over previous
#include <cuda_runtime.h>
#include <cuda_bf16.h>
#include <cuda_fp16.h>
#include <cstdint>
#include <cstddef>

// ---------------------------------------------------------------------------
// Problem constants (fixed by the dataset)
// ---------------------------------------------------------------------------
#define Q_   8192
#define C_   256
#define LVL  4
#define NH_  8
#define DH_  32
#define HMAX_ 128

#define ROWS_PER_B 21760   // 16384+4096+1024+256
#define NROWS      43520   // 2 * ROWS_PER_B

// ---------------------------------------------------------------------------
// Scratch (device globals; no allocation allowed)
// ---------------------------------------------------------------------------
__device__ __half g_vproj[(size_t)NROWS * C_];  // projected valid values (fp16)
__device__ float  g_offs [(size_t)Q_ * 256];    // sampling-offset raw proj
__device__ float  g_awr  [(size_t)Q_ * 128];    // attention-weight logits
__device__ __half g_agg  [(size_t)Q_ * C_];     // per-query aggregated heads (fp16)

// bf16x3 weight image (combined W_so|W_aw): per (kb32, nb64): [hi 5120B | lo 5120B]
__device__ __align__(16) char g_wqc_img[491520];   // 384 rows: 8 kb x 6 nb x 10240
// fp16 weight images: per (kb, nb64) blob: 5120B (fp16x2 pairs)
__device__ __align__(16) char g_wvh_img[163840];   // W_v: 8 kb x 4 nb x 5120
__device__ __align__(16) char g_woh_img[163840];   // W_o: 8 kb x 4 nb x 5120

// ---------------------------------------------------------------------------
// Row mapping: compact row r -> offset into values[B,128,128,L,C]
// ---------------------------------------------------------------------------
__device__ __forceinline__ size_t map_a_row(int r) {
    int b  = r / ROWS_PER_B;
    int rr = r - b * ROWS_PER_B;
    int l, base, W;
    if (rr < 16384)      { l = 0; base = 0;     W = 128; }
    else if (rr < 20480) { l = 1; base = 16384; W = 64;  }
    else if (rr < 21504) { l = 2; base = 20480; W = 32;  }
    else                 { l = 3; base = 21504; W = 16;  }
    int idx = rr - base;
    int y = idx / W;
    int x = idx - y * W;
    return ((((size_t)b * HMAX_ + y) * HMAX_ + x) * LVL + l) * C_;
}

// ---------------------------------------------------------------------------
// helpers
// ---------------------------------------------------------------------------
__device__ __forceinline__ uint32_t smem_u32(const void* p) {
    uint32_t a;
    asm("{ .reg .u64 t; cvta.to.shared.u64 t, %1; cvt.u32.u64 %0, t; }"
        : "=r"(a) : "l"(p));
    return a;
}

__device__ __forceinline__ uint32_t pack_bf16x2(float e0, float e1) {
    uint32_t r;
    asm("cvt.rn.bf16x2.f32 %0, %1, %2;" : "=r"(r) : "f"(e1), "f"(e0));
    return r;
}

__device__ __forceinline__ uint32_t pack_f16x2(float e0, float e1) {
    uint32_t r;
    asm("cvt.rn.f16x2.f32 %0, %1, %2;" : "=r"(r) : "f"(e1), "f"(e0));
    return r;
}

__device__ __forceinline__ float bf_hi(float x) {
    return __bfloat162float(__float2bfloat16_rn(x));
}

__device__ __forceinline__ void mma_bf16(float* c, const uint32_t* a, const uint32_t* b) {
    asm volatile(
        "mma.sync.aligned.m16n8k16.row.col.f32.bf16.bf16.f32 "
        "{%0,%1,%2,%3}, {%4,%5,%6,%7}, {%8,%9}, {%0,%1,%2,%3};\n"
        : "+f"(c[0]), "+f"(c[1]), "+f"(c[2]), "+f"(c[3])
        : "r"(a[0]), "r"(a[1]), "r"(a[2]), "r"(a[3]), "r"(b[0]), "r"(b[1]));
}

__device__ __forceinline__ void mma_f16(float* c, const uint32_t* a, const uint32_t* b) {
    asm volatile(
        "mma.sync.aligned.m16n8k16.row.col.f32.f16.f16.f32 "
        "{%0,%1,%2,%3}, {%4,%5,%6,%7}, {%8,%9}, {%0,%1,%2,%3};\n"
        : "+f"(c[0]), "+f"(c[1]), "+f"(c[2]), "+f"(c[3])
        : "r"(a[0]), "r"(a[1]), "r"(a[2]), "r"(a[3]), "r"(b[0]), "r"(b[1]));
}

#define LDSM4(r, a) \
    asm volatile("ldmatrix.sync.aligned.m8n8.x4.shared.b16 {%0,%1,%2,%3}, [%4];" \
        : "=r"((r)[0]), "=r"((r)[1]), "=r"((r)[2]), "=r"((r)[3]) : "r"(a))

__device__ __forceinline__ void cp16(uint32_t dst, const void* src) {
    asm volatile("cp.async.cg.shared.global [%0], [%1], 16;"
                 :: "r"(dst), "l"(src) : "memory");
}
#define CP_COMMIT() asm volatile("cp.async.commit_group;" ::: "memory")
#define CP_WAIT(n)  asm volatile("cp.async.wait_group %0;" :: "n"(n) : "memory")

// tail-aware wait: guarantee stage kb complete given issue schedule (3-ahead)
__device__ __forceinline__ void cp_wait_stage(int kb) {
    if (kb < 6)      CP_WAIT(2);
    else if (kb == 6) CP_WAIT(1);
    else              CP_WAIT(0);
}

// ---------------------------------------------------------------------------
// Weight prep (single launch).
// blocks 0-127:   W_v -> fp16 image (256 rows)
// blocks 128-319: W_so|W_aw combined -> bf16x3 image (384 rows)
// blocks 320-447: W_o -> fp16 image (256 rows)
// ---------------------------------------------------------------------------
__global__ void prep_all(const float* __restrict__ Wv, const float* __restrict__ Wso,
                         const float* __restrict__ Waw, const float* __restrict__ Wo,
                         char* __restrict__ ivh, char* __restrict__ iqc,
                         char* __restrict__ ioh)
{
    int blk = blockIdx.x;
    if (blk < 128 || blk >= 320) {
        const float* W = (blk < 128) ? Wv : Wo;
        char* img      = (blk < 128) ? ivh : ioh;
        int lb         = (blk < 128) ? blk : (blk - 320);
        int idx = lb * 256 + threadIdx.x;
        int n = idx >> 7, p = idx & 127;
        int k = p * 2;
        int kb = k >> 5, pl = (k & 31) >> 1;
        int nb = n >> 6, nl = n & 63;
        float a = W[(size_t)n * 256 + k];
        float b = W[(size_t)n * 256 + k + 1];
        char* blob = img + (size_t)(kb * 4 + nb) * 5120;
        *(uint32_t*)(blob + nl * 80 + pl * 4) = pack_f16x2(a, b);
        return;
    }
    int idx = (blk - 128) * 256 + threadIdx.x;
    int n = idx >> 7, p = idx & 127;
    const float* Wrow = (n < 256) ? (Wso + (size_t)n * 256) : (Waw + (size_t)(n - 256) * 256);
    int k = p * 2;
    int kb = k >> 5, pl = (k & 31) >> 1;
    int nb = n >> 6, nl = n & 63;
    float a = Wrow[k];
    float b = Wrow[k + 1];
    float ah = bf_hi(a), bh = bf_hi(b);
    char* blob = iqc + (size_t)(kb * 6 + nb) * 10240;
    uint32_t off = nl * 80 + pl * 4;
    *(uint32_t*)(blob + off)        = pack_bf16x2(ah, bh);
    *(uint32_t*)(blob + 5120 + off) = pack_bf16x2(a - ah, b - bh);
}

// ---------------------------------------------------------------------------
// Fused independent-GEMM batch, 64x64 tiles, 256 threads (8 warps 2m x 4n).
//  bid < 2720        : vproj tile (fp16 MMA)  C=values_map @ Wv^T -> fp16
//  bid >= 2720 (768) : query tile (bf16x3)    C=query @ [Wso|Waw]^T -> offs/awr
// B: 4-stage cp.async; A: 2-deep register prefetch (needs conversion).
// ---------------------------------------------------------------------------
#define NV_BLK 2720   // (43520/64) * 4
#define NQ_BLK 768    // (8192/64) * 6

__global__ void __launch_bounds__(256)
gemm_all(const float* __restrict__ values, const char* __restrict__ wvh,
         const float* __restrict__ b_v, __half* __restrict__ vproj,
         const float* __restrict__ query, const char* __restrict__ wqc,
         const float* __restrict__ b_so, const float* __restrict__ b_aw,
         float* __restrict__ offs, float* __restrict__ awr)
{
    __shared__ __align__(16) char sm[61440];

    const int tid = threadIdx.x, wid = tid >> 5, lane = tid & 31;
    const int g = lane >> 2, t = lane & 3;
    const int wm = (wid & 1) * 32, wn = (wid >> 1) * 16;
    const int r  = tid >> 2;
    const int q4 = tid & 3;
    const int rr16 = lane & 15;
    const int chi  = ((lane >> 4) & 1) * 16;
    const uint32_t sbase = smem_u32(sm);

    float acc[2][2][4];
#pragma unroll
    for (int i = 0; i < 2; i++)
#pragma unroll
        for (int j = 0; j < 2; j++)
#pragma unroll
            for (int c = 0; c < 4; c++) acc[i][j][c] = 0.0f;

    const int bid = blockIdx.x;

    if (bid < NV_BLK) {
        // ================= vproj: fp16 MMA =================
        const int m0 = (bid >> 2) * 64, nb = bid & 3, n0 = nb * 64;
        const float* Ap = values + map_a_row(m0 + r) + q4 * 8;
        const uint32_t aoff = r * 80 + q4 * 16;
        const char* bsrc0 = wvh + (size_t)nb * 5120;

        {
            float4 v0 = *(const float4*)(Ap);
            float4 v1 = *(const float4*)(Ap + 4);
            uint4 w;
            w.x = pack_f16x2(v0.x, v0.y); w.y = pack_f16x2(v0.z, v0.w);
            w.z = pack_f16x2(v1.x, v1.y); w.w = pack_f16x2(v1.z, v1.w);
            *(uint4*)(sm + aoff) = w;
        }
        float4 rA[2][2];
        rA[0][0] = *(const float4*)(Ap + 32);
        rA[0][1] = *(const float4*)(Ap + 36);
        rA[1][0] = *(const float4*)(Ap + 64);
        rA[1][1] = *(const float4*)(Ap + 68);
#pragma unroll
        for (int s = 0; s < 3; s++) {
            uint32_t bd = sbase + 10240 + s * 5120;
            const char* bs = bsrc0 + (size_t)s * 4 * 5120;
            cp16(bd + tid * 16, bs + tid * 16);
            if (tid < 64) cp16(bd + (tid + 256) * 16, bs + (tid + 256) * 16);
            CP_COMMIT();
        }

#pragma unroll
        for (int kb = 0; kb < 8; kb++) {
            cp_wait_stage(kb);
            __syncthreads();

            if (kb < 7) {
                uint4 w;
                w.x = pack_f16x2(rA[0][0].x, rA[0][0].y);
                w.y = pack_f16x2(rA[0][0].z, rA[0][0].w);
                w.z = pack_f16x2(rA[0][1].x, rA[0][1].y);
                w.w = pack_f16x2(rA[0][1].z, rA[0][1].w);
                *(uint4*)(sm + ((kb + 1) & 1) * 5120 + aoff) = w;
                rA[0][0] = rA[1][0]; rA[0][1] = rA[1][1];
                if (kb + 3 < 8) {
                    rA[1][0] = *(const float4*)(Ap + (kb + 3) * 32);
                    rA[1][1] = *(const float4*)(Ap + (kb + 3) * 32 + 4);
                }
            }
            if (kb + 3 < 8) {
                uint32_t bd = sbase + 10240 + ((kb + 3) & 3) * 5120;
                const char* bs = bsrc0 + (size_t)(kb + 3) * 4 * 5120;
                cp16(bd + tid * 16, bs + tid * 16);
                if (tid < 64) cp16(bd + (tid + 256) * 16, bs + (tid + 256) * 16);
                CP_COMMIT();
            }

            const uint32_t baseA = sbase + (kb & 1) * 5120;
            const uint32_t baseB = sbase + 10240 + (kb & 3) * 5120;
#pragma unroll
            for (int ks = 0; ks < 2; ks++) {
                const int cb = ks * 32 + chi;
                uint32_t aH[2][4], bH[4];
#pragma unroll
                for (int fm = 0; fm < 2; fm++)
                    LDSM4(aH[fm], baseA + (wm + fm * 16 + rr16) * 80 + cb);
                LDSM4(bH, baseB + (wn + rr16) * 80 + cb);
#pragma unroll
                for (int fm = 0; fm < 2; fm++)
#pragma unroll
                    for (int fn = 0; fn < 2; fn++) {
                        uint32_t bh2[2] = {bH[fn], bH[fn + 2]};
                        mma_f16(acc[fm][fn], aH[fm], bh2);
                    }
            }
        }

#pragma unroll
        for (int fn = 0; fn < 2; fn++) {
            int cn = n0 + wn + fn * 8 + t * 2;
            float b0 = b_v[cn], b1 = b_v[cn + 1];
#pragma unroll
            for (int fm = 0; fm < 2; fm++) {
                int r0 = m0 + wm + fm * 16 + g;
                *(__half2*)&vproj[(size_t)r0 * 256 + cn] =
                    __floats2half2_rn(acc[fm][fn][0] + b0, acc[fm][fn][1] + b1);
                *(__half2*)&vproj[(size_t)(r0 + 8) * 256 + cn] =
                    __floats2half2_rn(acc[fm][fn][2] + b0, acc[fm][fn][3] + b1);
            }
        }
        return;
    }

    // ================= query offs+awr: bf16x3 =================
    {
        const int qid = bid - NV_BLK;
        const int m0 = (qid / 6) * 64, nb = qid % 6, n0 = nb * 64;
        const float* Ap = query + (size_t)(m0 + r) * 256 + q4 * 8;
        const uint32_t aoff = r * 80 + q4 * 16;
        const char* bsrc0 = wqc + (size_t)nb * 10240;

        {
            float4 v0 = *(const float4*)(Ap);
            float4 v1 = *(const float4*)(Ap + 4);
            float xh = bf_hi(v0.x), yh = bf_hi(v0.y);
            float zh = bf_hi(v0.z), wwh = bf_hi(v0.w);
            float xh2 = bf_hi(v1.x), yh2 = bf_hi(v1.y);
            float zh2 = bf_hi(v1.z), wh2 = bf_hi(v1.w);
            uint4 wh, wl;
            wh.x = pack_bf16x2(xh, yh);   wh.y = pack_bf16x2(zh, wwh);
            wh.z = pack_bf16x2(xh2, yh2); wh.w = pack_bf16x2(zh2, wh2);
            wl.x = pack_bf16x2(v0.x - xh, v0.y - yh);
            wl.y = pack_bf16x2(v0.z - zh, v0.w - wwh);
            wl.z = pack_bf16x2(v1.x - xh2, v1.y - yh2);
            wl.w = pack_bf16x2(v1.z - zh2, v1.w - wh2);
            *(uint4*)(sm + aoff)        = wh;
            *(uint4*)(sm + 5120 + aoff) = wl;
        }
        float4 rA[2][2];
        rA[0][0] = *(const float4*)(Ap + 32);
        rA[0][1] = *(const float4*)(Ap + 36);
        rA[1][0] = *(const float4*)(Ap + 64);
        rA[1][1] = *(const float4*)(Ap + 68);
#pragma unroll
        for (int s = 0; s < 3; s++) {
            uint32_t bd = sbase + 20480 + s * 10240;
            const char* bs = bsrc0 + (size_t)s * 6 * 10240;
            cp16(bd + tid * 16, bs + tid * 16);
            cp16(bd + (tid + 256) * 16, bs + (tid + 256) * 16);
            if (tid < 128) cp16(bd + (tid + 512) * 16, bs + (tid + 512) * 16);
            CP_COMMIT();
        }

#pragma unroll
        for (int kb = 0; kb < 8; kb++) {
            cp_wait_stage(kb);
            __syncthreads();

            if (kb < 7) {
                float4 v0 = rA[0][0], v1 = rA[0][1];
                float xh = bf_hi(v0.x), yh = bf_hi(v0.y);
                float zh = bf_hi(v0.z), wwh = bf_hi(v0.w);
                float xh2 = bf_hi(v1.x), yh2 = bf_hi(v1.y);
                float zh2 = bf_hi(v1.z), wh2 = bf_hi(v1.w);
                uint4 wh, wl;
                wh.x = pack_bf16x2(xh, yh);   wh.y = pack_bf16x2(zh, wwh);
                wh.z = pack_bf16x2(xh2, yh2); wh.w = pack_bf16x2(zh2, wh2);
                wl.x = pack_bf16x2(v0.x - xh, v0.y - yh);
                wl.y = pack_bf16x2(v0.z - zh, v0.w - wwh);
                wl.z = pack_bf16x2(v1.x - xh2, v1.y - yh2);
                wl.w = pack_bf16x2(v1.z - zh2, v1.w - wh2);
                uint32_t ab = ((kb + 1) & 1) * 10240;
                *(uint4*)(sm + ab + aoff)        = wh;
                *(uint4*)(sm + ab + 5120 + aoff) = wl;
                rA[0][0] = rA[1][0]; rA[0][1] = rA[1][1];
                if (kb + 3 < 8) {
                    rA[1][0] = *(const float4*)(Ap + (kb + 3) * 32);
                    rA[1][1] = *(const float4*)(Ap + (kb + 3) * 32 + 4);
                }
            }
            if (kb + 3 < 8) {
                uint32_t bd = sbase + 20480 + ((kb + 3) & 3) * 10240;
                const char* bs = bsrc0 + (size_t)(kb + 3) * 6 * 10240;
                cp16(bd + tid * 16, bs + tid * 16);
                cp16(bd + (tid + 256) * 16, bs + (tid + 256) * 16);
                if (tid < 128) cp16(bd + (tid + 512) * 16, bs + (tid + 512) * 16);
                CP_COMMIT();
            }

            const uint32_t baseA = sbase + (kb & 1) * 10240;
            const uint32_t baseB = sbase + 20480 + (kb & 3) * 10240;
#pragma unroll
            for (int ks = 0; ks < 2; ks++) {
                const int cb = ks * 32 + chi;
                uint32_t aH[2][4], aL[2][4], bH[4], bL[4];
#pragma unroll
                for (int fm = 0; fm < 2; fm++) {
                    uint32_t ad = baseA + (wm + fm * 16 + rr16) * 80 + cb;
                    LDSM4(aH[fm], ad);
                    LDSM4(aL[fm], ad + 5120);
                }
                {
                    uint32_t bd = baseB + (wn + rr16) * 80 + cb;
                    LDSM4(bH, bd);
                    LDSM4(bL, bd + 5120);
                }
#pragma unroll
                for (int fm = 0; fm < 2; fm++)
#pragma unroll
                    for (int fn = 0; fn < 2; fn++) {
                        uint32_t bh2[2] = {bH[fn], bH[fn + 2]};
                        uint32_t bl2[2] = {bL[fn], bL[fn + 2]};
                        mma_bf16(acc[fm][fn], aL[fm], bh2);
                        mma_bf16(acc[fm][fn], aH[fm], bl2);
                        mma_bf16(acc[fm][fn], aH[fm], bh2);
                    }
            }
        }

        const bool is_aw = (n0 >= 256);
        const float* bias = is_aw ? b_aw : b_so;
        float* Cm = is_aw ? awr : offs;
        const int Nout = is_aw ? 128 : 256;
        const int ncol0 = is_aw ? (n0 - 256) : n0;
#pragma unroll
        for (int fn = 0; fn < 2; fn++) {
            int cn = ncol0 + wn + fn * 8 + t * 2;
            float b0 = bias[cn], b1 = bias[cn + 1];
#pragma unroll
            for (int fm = 0; fm < 2; fm++) {
                int r0 = m0 + wm + fm * 16 + g;
                *(float2*)&Cm[(size_t)r0 * Nout + cn] =
                    make_float2(acc[fm][fn][0] + b0, acc[fm][fn][1] + b1);
                *(float2*)&Cm[(size_t)(r0 + 8) * Nout + cn] =
                    make_float2(acc[fm][fn][2] + b0, acc[fm][fn][3] + b1);
            }
        }
    }
}

// ---------------------------------------------------------------------------
// out-proj GEMM: fp16 MMA, pure 4-stage cp.async (A and B raw copies).
// ---------------------------------------------------------------------------
__global__ void __launch_bounds__(256)
gemm_out(const __half* __restrict__ A, const char* __restrict__ Bimg,
         const float* __restrict__ bias, float* __restrict__ Cm)
{
    __shared__ __align__(16) char sm[40960];

    const int tid = threadIdx.x, wid = tid >> 5, lane = tid & 31;
    const int g = lane >> 2, t = lane & 3;
    const int m0 = blockIdx.x * 64, n0 = blockIdx.y * 64;
    const int wm = (wid & 1) * 32, wn = (wid >> 1) * 16;
    const int r  = tid >> 2;
    const int q4 = tid & 3;
    const int rr16 = lane & 15;
    const int chi  = ((lane >> 4) & 1) * 16;
    const uint32_t sbase = smem_u32(sm);

    const char* asrc = (const char*)(A + (size_t)(m0 + r) * 256) + q4 * 16;
    const char* bsrc0 = Bimg + (size_t)blockIdx.y * 5120;
    const uint32_t aoff = r * 80 + q4 * 16;

    float acc[2][2][4];
#pragma unroll
    for (int i = 0; i < 2; i++)
#pragma unroll
        for (int j = 0; j < 2; j++)
#pragma unroll
            for (int c = 0; c < 4; c++) acc[i][j][c] = 0.0f;

#pragma unroll
    for (int s = 0; s < 3; s++) {
        uint32_t sb = sbase + s * 10240;
        cp16(sb + aoff, asrc + (size_t)s * 64);
        uint32_t bd = sb + 5120;
        const char* bs = bsrc0 + (size_t)s * 4 * 5120;
        cp16(bd + tid * 16, bs + tid * 16);
        if (tid < 64) cp16(bd + (tid + 256) * 16, bs + (tid + 256) * 16);
        CP_COMMIT();
    }

#pragma unroll
    for (int kb = 0; kb < 8; kb++) {
        cp_wait_stage(kb);
        __syncthreads();

        if (kb + 3 < 8) {
            uint32_t sb = sbase + ((kb + 3) & 3) * 10240;
            cp16(sb + aoff, asrc + (size_t)(kb + 3) * 64);
            uint32_t bd = sb + 5120;
            const char* bs = bsrc0 + (size_t)(kb + 3) * 4 * 5120;
            cp16(bd + tid * 16, bs + tid * 16);
            if (tid < 64) cp16(bd + (tid + 256) * 16, bs + (tid + 256) * 16);
            CP_COMMIT();
        }

        const uint32_t base = sbase + (kb & 3) * 10240;
#pragma unroll
        for (int ks = 0; ks < 2; ks++) {
            const int cb = ks * 32 + chi;
            uint32_t aH[2][4], bH[4];
#pragma unroll
            for (int fm = 0; fm < 2; fm++)
                LDSM4(aH[fm], base + (wm + fm * 16 + rr16) * 80 + cb);
            LDSM4(bH, base + 5120 + (wn + rr16) * 80 + cb);
#pragma unroll
            for (int fm = 0; fm < 2; fm++)
#pragma unroll
                for (int fn = 0; fn < 2; fn++) {
                    uint32_t bh2[2] = {bH[fn], bH[fn + 2]};
                    mma_f16(acc[fm][fn], aH[fm], bh2);
                }
        }
    }

#pragma unroll
    for (int fn = 0; fn < 2; fn++) {
        int cn = n0 + wn + fn * 8 + t * 2;
        float b0 = bias[cn], b1 = bias[cn + 1];
#pragma unroll
        for (int fm = 0; fm < 2; fm++) {
            int r0 = m0 + wm + fm * 16 + g;
            *(float2*)&Cm[(size_t)r0 * 256 + cn] =
                make_float2(acc[fm][fn][0] + b0, acc[fm][fn][1] + b1);
            *(float2*)&Cm[(size_t)(r0 + 8) * 256 + cn] =
                make_float2(acc[fm][fn][2] + b0, acc[fm][fn][3] + b1);
        }
    }
}

// ---------------------------------------------------------------------------
// Sampling kernel: 8 queries per block (256 threads); 16B vectorized gathers.
// Gather phase: 32 threads per query, each owns 8 channels (one uint4 load
// per corner). Arithmetic identical to previous rounds.
// ---------------------------------------------------------------------------
#define QPB 8
__global__ __launch_bounds__(256)
void sample_kernel(const float* __restrict__ ref,
                   const int* __restrict__ batch_offsets)
{
    __shared__ float sL[QPB][128];
    __shared__ float hM[QPB][8];
    __shared__ float hR[QPB][8];
    __shared__ float sIS[QPB][2];
    __shared__ __align__(16) int   srow[QPB][128][4];
    __shared__ __align__(16) float swt [QPB][128][4];

    const int tid = threadIdx.x;
    const int q0  = blockIdx.x * QPB;
    const int boundary = batch_offsets[1];

#pragma unroll
    for (int j = tid; j < QPB * 128; j += 256)
        sL[j >> 7][j & 127] = g_awr[(size_t)(q0 + (j >> 7)) * 128 + (j & 127)];

    if (tid >= 224 && tid < 224 + QPB * 2) {
        int k = tid - 224;
        int qi = k >> 1, xy = k & 1;
        float v = ref[(q0 + qi) * 2 + xy];
        v = fminf(fmaxf(v, 0.0f), 1.0f);
        sIS[qi][xy] = logf(fmaxf(v, 1e-5f) / fmaxf(1.0f - v, 1e-5f));
    }
    __syncthreads();

    if (tid < QPB * 8) {
        int qi = tid >> 3, h = tid & 7;
        float m = -1e30f;
#pragma unroll
        for (int lp = 0; lp < 16; lp++) m = fmaxf(m, sL[qi][lp * 8 + h]);
        float s = 0.0f;
#pragma unroll
        for (int lp = 0; lp < 16; lp++) s += expf(sL[qi][lp * 8 + h] - m);
        hM[qi][h] = m;
        hR[qi][h] = 1.0f / s;
    }
    __syncthreads();

#pragma unroll
    for (int j = tid; j < QPB * 128; j += 256) {
        const int qi = j >> 7;
        const int i  = j & 127;
        const int q  = q0 + qi;
        const int h  = i & 7;
        const int lp = i >> 3;
        const int l  = lp >> 2;

        float aw = expf(sL[qi][i] - hM[qi][h]) * hR[qi][h];

        float ox = g_offs[(size_t)q * 256 + i * 2 + 0];
        float oy = g_offs[(size_t)q * 256 + i * 2 + 1];

        float locx = 1.0f / (1.0f + expf(-(sIS[qi][0] + ox)));
        float locy = 1.0f / (1.0f + expf(-(sIS[qi][1] + oy)));

        const int   Wl = HMAX_ >> l;
        const float Wf = (float)Wl;
        float x = locx * Wf - 0.5f;
        float y = locy * Wf - 0.5f;

        float x0f = floorf(x), y0f = floorf(y);
        float wx1 = x - x0f, wx0 = 1.0f - wx1;
        float wy1 = y - y0f, wy0 = 1.0f - wy1;
        int x0 = (int)x0f, y0 = (int)y0f;

        int b = (q >= boundary) ? 1 : 0;
        int lbase = (l >= 1 ? 16384 : 0) + (l >= 2 ? 4096 : 0) + (l >= 3 ? 1024 : 0);
        int base = b * ROWS_PER_B + lbase;

        int   xs[2]  = {x0, x0 + 1};
        int   ys2[2] = {y0, y0 + 1};
        float wxs[2] = {wx0, wx1};
        float wys[2] = {wy0, wy1};

#pragma unroll
        for (int cy = 0; cy < 2; cy++) {
#pragma unroll
            for (int cx = 0; cx < 2; cx++) {
                int c  = cy * 2 + cx;
                int xi = xs[cx], yi = ys2[cy];
                bool valid = (xi >= 0) & (xi < Wl) & (yi >= 0) & (yi < Wl);
                int xc = min(max(xi, 0), Wl - 1);
                int yc = min(max(yi, 0), Wl - 1);
                srow[qi][i][c] = base + yc * Wl + xc;
                swt [qi][i][c] = valid ? (aw * wys[cy] * wxs[cx]) : 0.0f;
            }
        }
    }
    __syncthreads();

    // gather: 32 threads per query, 8 channels each (16B loads)
    const int qi   = tid >> 5;
    const int tq   = tid & 31;
    const int h    = tq >> 2;
    const int coff = h * DH_ + (tq & 3) * 8;
    const int q    = q0 + qi;

    float acc[8];
#pragma unroll
    for (int e = 0; e < 8; e++) acc[e] = 0.0f;

#pragma unroll
    for (int lp = 0; lp < 16; lp++) {
        const int i = lp * 8 + h;
        int4   r4 = *(const int4*)  &srow[qi][i][0];
        float4 w4 = *(const float4*)&swt [qi][i][0];
        int   rr[4] = {r4.x, r4.y, r4.z, r4.w};
        float ww[4] = {w4.x, w4.y, w4.z, w4.w};
#pragma unroll
        for (int c = 0; c < 4; c++) {
            const uint4 v = __ldg((const uint4*)&g_vproj[(size_t)rr[c] * C_ + coff]);
            const __half2* hp = (const __half2*)&v;
            float w = ww[c];
#pragma unroll
            for (int e = 0; e < 4; e++) {
                float2 f = __half22float2(hp[e]);
                acc[e * 2 + 0] += w * f.x;
                acc[e * 2 + 1] += w * f.y;
            }
        }
    }
    uint4 outv;
    outv.x = pack_f16x2(acc[0], acc[1]);
    outv.y = pack_f16x2(acc[2], acc[3]);
    outv.z = pack_f16x2(acc[4], acc[5]);
    outv.w = pack_f16x2(acc[6], acc[7]);
    *(uint4*)&g_agg[(size_t)q * C_ + coff] = outv;
}

// ---------------------------------------------------------------------------
// kernel_launch
// ---------------------------------------------------------------------------
extern "C" void kernel_launch(void* const* d_in, const int* in_sizes, int n_in,
                              void* d_out, int out_size)
{
    const float* query  = (const float*)d_in[0];
    const float* ref    = (const float*)d_in[1];
    const float* values = (const float*)d_in[2];
    const float* W_so   = (const float*)d_in[3];
    const float* b_so   = (const float*)d_in[4];
    const float* W_aw   = (const float*)d_in[5];
    const float* b_aw   = (const float*)d_in[6];
    const float* W_v    = (const float*)d_in[7];
    const float* b_v    = (const float*)d_in[8];
    const float* W_o    = (const float*)d_in[9];
    const float* b_o    = (const float*)d_in[10];
    const int* batch_offsets = (const int*)d_in[11];
    float* out = (float*)d_out;
    (void)in_sizes; (void)n_in; (void)out_size;

    __half *vproj, *agg;
    float *offs, *awr;
    char *wvh, *wqc, *woh;
    cudaGetSymbolAddress((void**)&vproj, g_vproj);
    cudaGetSymbolAddress((void**)&offs,  g_offs);
    cudaGetSymbolAddress((void**)&awr,   g_awr);
    cudaGetSymbolAddress((void**)&agg,   g_agg);
    cudaGetSymbolAddress((void**)&wvh,   g_wvh_img);
    cudaGetSymbolAddress((void**)&wqc,   g_wqc_img);
    cudaGetSymbolAddress((void**)&woh,   g_woh_img);

    // 0) weight images (single launch)
    prep_all<<<448, 256>>>(W_v, W_so, W_aw, W_o, wvh, wqc, woh);

    // 1) vproj + offs + awr, one fused launch (3488 CTAs, 8 warps each)
    gemm_all<<<NV_BLK + NQ_BLK, 256>>>(values, wvh, b_v, vproj,
                                       query, wqc, b_so, b_aw, offs, awr);

    // 2) softmax + bilinear sampling + head aggregation (fp16 agg out)
    sample_kernel<<<Q_ / QPB, 256>>>(ref, batch_offsets);

    // 3) out = agg @ W_o^T + b_o  [8192 x 256] (fp16 MMA, cp.async 4-stage)
    {
        dim3 grid(Q_ / 64, 4);
        gemm_out<<<grid, 256>>>(agg, woh, b_o, out);
    }
}

// round 15
// speedup vs baseline: 3.2513x; 1.0996x over previous
#include <cuda_runtime.h>
#include <cuda_bf16.h>
#include <cuda_fp16.h>
#include <cstdint>
#include <cstddef>

// ---------------------------------------------------------------------------
// Problem constants (fixed by the dataset)
// ---------------------------------------------------------------------------
#define Q_   8192
#define C_   256
#define LVL  4
#define NH_  8
#define DH_  32
#define HMAX_ 128

#define ROWS_PER_B 21760   // 16384+4096+1024+256
#define NROWS      43520   // 2 * ROWS_PER_B

// ---------------------------------------------------------------------------
// Scratch (device globals; no allocation allowed)
// ---------------------------------------------------------------------------
__device__ __half g_vproj[(size_t)NROWS * C_];  // projected valid values (fp16)
__device__ float  g_offs [(size_t)Q_ * 256];    // sampling-offset raw proj
__device__ float  g_awr  [(size_t)Q_ * 128];    // attention-weight logits
__device__ __half g_agg  [(size_t)Q_ * C_];     // per-query aggregated heads (fp16)

// bf16x3 weight image (combined W_so|W_aw): per (kb32, nb64): [hi 5120B | lo 5120B]
__device__ __align__(16) char g_wqc_img[491520];   // 384 rows: 8 kb x 6 nb x 10240
// fp16 weight images: per (kb, nb64) blob: 5120B (fp16x2 pairs)
__device__ __align__(16) char g_wvh_img[163840];   // W_v: 8 kb x 4 nb x 5120
__device__ __align__(16) char g_woh_img[163840];   // W_o: 8 kb x 4 nb x 5120

// ---------------------------------------------------------------------------
// Row mapping: compact row r -> offset into values[B,128,128,L,C]
// ---------------------------------------------------------------------------
__device__ __forceinline__ size_t map_a_row(int r) {
    int b  = r / ROWS_PER_B;
    int rr = r - b * ROWS_PER_B;
    int l, base, W;
    if (rr < 16384)      { l = 0; base = 0;     W = 128; }
    else if (rr < 20480) { l = 1; base = 16384; W = 64;  }
    else if (rr < 21504) { l = 2; base = 20480; W = 32;  }
    else                 { l = 3; base = 21504; W = 16;  }
    int idx = rr - base;
    int y = idx / W;
    int x = idx - y * W;
    return ((((size_t)b * HMAX_ + y) * HMAX_ + x) * LVL + l) * C_;
}

// ---------------------------------------------------------------------------
// helpers
// ---------------------------------------------------------------------------
__device__ __forceinline__ uint32_t smem_u32(const void* p) {
    uint32_t a;
    asm("{ .reg .u64 t; cvta.to.shared.u64 t, %1; cvt.u32.u64 %0, t; }"
        : "=r"(a) : "l"(p));
    return a;
}

__device__ __forceinline__ uint32_t pack_bf16x2(float e0, float e1) {
    uint32_t r;
    asm("cvt.rn.bf16x2.f32 %0, %1, %2;" : "=r"(r) : "f"(e1), "f"(e0));
    return r;
}

__device__ __forceinline__ uint32_t pack_f16x2(float e0, float e1) {
    uint32_t r;
    asm("cvt.rn.f16x2.f32 %0, %1, %2;" : "=r"(r) : "f"(e1), "f"(e0));
    return r;
}

__device__ __forceinline__ float bf_hi(float x) {
    return __bfloat162float(__float2bfloat16_rn(x));
}

__device__ __forceinline__ void mma_bf16(float* c, const uint32_t* a, const uint32_t* b) {
    asm volatile(
        "mma.sync.aligned.m16n8k16.row.col.f32.bf16.bf16.f32 "
        "{%0,%1,%2,%3}, {%4,%5,%6,%7}, {%8,%9}, {%0,%1,%2,%3};\n"
        : "+f"(c[0]), "+f"(c[1]), "+f"(c[2]), "+f"(c[3])
        : "r"(a[0]), "r"(a[1]), "r"(a[2]), "r"(a[3]), "r"(b[0]), "r"(b[1]));
}

__device__ __forceinline__ void mma_f16(float* c, const uint32_t* a, const uint32_t* b) {
    asm volatile(
        "mma.sync.aligned.m16n8k16.row.col.f32.f16.f16.f32 "
        "{%0,%1,%2,%3}, {%4,%5,%6,%7}, {%8,%9}, {%0,%1,%2,%3};\n"
        : "+f"(c[0]), "+f"(c[1]), "+f"(c[2]), "+f"(c[3])
        : "r"(a[0]), "r"(a[1]), "r"(a[2]), "r"(a[3]), "r"(b[0]), "r"(b[1]));
}

#define LDSM4(r, a) \
    asm volatile("ldmatrix.sync.aligned.m8n8.x4.shared.b16 {%0,%1,%2,%3}, [%4];" \
        : "=r"((r)[0]), "=r"((r)[1]), "=r"((r)[2]), "=r"((r)[3]) : "r"(a))

__device__ __forceinline__ void cp16(uint32_t dst, const void* src) {
    asm volatile("cp.async.cg.shared.global [%0], [%1], 16;"
                 :: "r"(dst), "l"(src) : "memory");
}
#define CP_COMMIT() asm volatile("cp.async.commit_group;" ::: "memory")
#define CP_WAIT(n)  asm volatile("cp.async.wait_group %0;" :: "n"(n) : "memory")

// ---------------------------------------------------------------------------
// Weight prep (single launch).
// blocks 0-127:   W_v -> fp16 image (256 rows)
// blocks 128-319: W_so|W_aw combined -> bf16x3 image (384 rows)
// blocks 320-447: W_o -> fp16 image (256 rows)
// ---------------------------------------------------------------------------
__global__ void prep_all(const float* __restrict__ Wv, const float* __restrict__ Wso,
                         const float* __restrict__ Waw, const float* __restrict__ Wo,
                         char* __restrict__ ivh, char* __restrict__ iqc,
                         char* __restrict__ ioh)
{
    int blk = blockIdx.x;
    if (blk < 128 || blk >= 320) {
        const float* W = (blk < 128) ? Wv : Wo;
        char* img      = (blk < 128) ? ivh : ioh;
        int lb         = (blk < 128) ? blk : (blk - 320);
        int idx = lb * 256 + threadIdx.x;
        int n = idx >> 7, p = idx & 127;
        int k = p * 2;
        int kb = k >> 5, pl = (k & 31) >> 1;
        int nb = n >> 6, nl = n & 63;
        float a = W[(size_t)n * 256 + k];
        float b = W[(size_t)n * 256 + k + 1];
        char* blob = img + (size_t)(kb * 4 + nb) * 5120;
        *(uint32_t*)(blob + nl * 80 + pl * 4) = pack_f16x2(a, b);
        return;
    }
    int idx = (blk - 128) * 256 + threadIdx.x;
    int n = idx >> 7, p = idx & 127;
    const float* Wrow = (n < 256) ? (Wso + (size_t)n * 256) : (Waw + (size_t)(n - 256) * 256);
    int k = p * 2;
    int kb = k >> 5, pl = (k & 31) >> 1;
    int nb = n >> 6, nl = n & 63;
    float a = Wrow[k];
    float b = Wrow[k + 1];
    float ah = bf_hi(a), bh = bf_hi(b);
    char* blob = iqc + (size_t)(kb * 6 + nb) * 10240;
    uint32_t off = nl * 80 + pl * 4;
    *(uint32_t*)(blob + off)        = pack_bf16x2(ah, bh);
    *(uint32_t*)(blob + 5120 + off) = pack_bf16x2(a - ah, b - bh);
}

// ---------------------------------------------------------------------------
// Fused independent-GEMM batch, 256 threads (8 warps 2m x 4n, warp tile 32x16).
//  bid < 680         : vproj tile 64x256 (fp16 MMA), A resident in smem,
//                      B streamed 4-deep cp.async over 32 stages (4 nb x 8 kb).
//  bid >= 680 (768)  : query tile 64x64 (bf16x3), as before.
// vproj smem: A kb-blocks at kb*5120 (40960B), B ring at 40960+(s&3)*5120.
// query smem: A dbl-buf 0/10240, B ring at 20480+(kb&3)*10240.
// ---------------------------------------------------------------------------
#define NV_BLK 680    // 43520/64
#define NQ_BLK 768    // (8192/64) * 6

__global__ void __launch_bounds__(256)
gemm_all(const float* __restrict__ values, const char* __restrict__ wvh,
         const float* __restrict__ b_v, __half* __restrict__ vproj,
         const float* __restrict__ query, const char* __restrict__ wqc,
         const float* __restrict__ b_so, const float* __restrict__ b_aw,
         float* __restrict__ offs, float* __restrict__ awr)
{
    __shared__ __align__(16) char sm[61440];

    const int tid = threadIdx.x, wid = tid >> 5, lane = tid & 31;
    const int g = lane >> 2, t = lane & 3;
    const int wm = (wid & 1) * 32, wn = (wid >> 1) * 16;
    const int r  = tid >> 2;
    const int q4 = tid & 3;
    const int rr16 = lane & 15;
    const int chi  = ((lane >> 4) & 1) * 16;
    const uint32_t sbase = smem_u32(sm);

    float acc[2][2][4];
#pragma unroll
    for (int i = 0; i < 2; i++)
#pragma unroll
        for (int j = 0; j < 2; j++)
#pragma unroll
            for (int c = 0; c < 4; c++) acc[i][j][c] = 0.0f;

    const int bid = blockIdx.x;

    if (bid < NV_BLK) {
        // ========== vproj: fp16 MMA, A-resident, 32 B-stages ==========
        const int m0 = bid * 64;
        const float* Ap = values + map_a_row(m0 + r) + q4 * 8;
        const uint32_t aoff = r * 80 + q4 * 16;

        // issue B stages 0..2 (stage s: nb=s>>3, kb=s&7; blob=(kb*4+nb)*5120)
#pragma unroll
        for (int s = 0; s < 3; s++) {
            uint32_t bd = sbase + 40960 + s * 5120;
            const char* bs = wvh + (size_t)((s & 7) * 4 + (s >> 3)) * 5120;
            cp16(bd + tid * 16, bs + tid * 16);
            if (tid < 64) cp16(bd + (tid + 256) * 16, bs + (tid + 256) * 16);
            CP_COMMIT();
        }

        // load + convert the full A tile once (8 kb-blocks, 40KB)
#pragma unroll
        for (int kb = 0; kb < 8; kb++) {
            float4 v0 = *(const float4*)(Ap + kb * 32);
            float4 v1 = *(const float4*)(Ap + kb * 32 + 4);
            uint4 w;
            w.x = pack_f16x2(v0.x, v0.y); w.y = pack_f16x2(v0.z, v0.w);
            w.z = pack_f16x2(v1.x, v1.y); w.w = pack_f16x2(v1.z, v1.w);
            *(uint4*)(sm + kb * 5120 + aoff) = w;
        }
        __syncthreads();   // A image visible to all warps

        for (int s = 0; s < 32; s++) {
            const int kb = s & 7, nb = s >> 3;

            // wait for B stage s (3-ahead issue schedule over 32 stages)
            if (s < 30)      CP_WAIT(2);
            else if (s == 30) CP_WAIT(1);
            else              CP_WAIT(0);
            __syncthreads();

            // issue B stage s+3
            if (s + 3 < 32) {
                const int s3 = s + 3;
                uint32_t bd = sbase + 40960 + (s3 & 3) * 5120;
                const char* bs = wvh + (size_t)((s3 & 7) * 4 + (s3 >> 3)) * 5120;
                cp16(bd + tid * 16, bs + tid * 16);
                if (tid < 64) cp16(bd + (tid + 256) * 16, bs + (tid + 256) * 16);
                CP_COMMIT();
            }

            const uint32_t baseA = sbase + kb * 5120;
            const uint32_t baseB = sbase + 40960 + (s & 3) * 5120;
#pragma unroll
            for (int ks = 0; ks < 2; ks++) {
                const int cb = ks * 32 + chi;
                uint32_t aH[2][4], bH[4];
#pragma unroll
                for (int fm = 0; fm < 2; fm++)
                    LDSM4(aH[fm], baseA + (wm + fm * 16 + rr16) * 80 + cb);
                LDSM4(bH, baseB + (wn + rr16) * 80 + cb);
#pragma unroll
                for (int fm = 0; fm < 2; fm++)
#pragma unroll
                    for (int fn = 0; fn < 2; fn++) {
                        uint32_t bh2[2] = {bH[fn], bH[fn + 2]};
                        mma_f16(acc[fm][fn], aH[fm], bh2);
                    }
            }

            // epilogue at the end of each nb pass
            if (kb == 7) {
                const int n0 = nb * 64;
#pragma unroll
                for (int fn = 0; fn < 2; fn++) {
                    int cn = n0 + wn + fn * 8 + t * 2;
                    float b0 = b_v[cn], b1 = b_v[cn + 1];
#pragma unroll
                    for (int fm = 0; fm < 2; fm++) {
                        int r0 = m0 + wm + fm * 16 + g;
                        *(__half2*)&vproj[(size_t)r0 * 256 + cn] =
                            __floats2half2_rn(acc[fm][fn][0] + b0, acc[fm][fn][1] + b1);
                        *(__half2*)&vproj[(size_t)(r0 + 8) * 256 + cn] =
                            __floats2half2_rn(acc[fm][fn][2] + b0, acc[fm][fn][3] + b1);
                        acc[fm][fn][0] = 0.0f; acc[fm][fn][1] = 0.0f;
                        acc[fm][fn][2] = 0.0f; acc[fm][fn][3] = 0.0f;
                    }
                }
            }
        }
        return;
    }

    // ================= query offs+awr: bf16x3 =================
    {
        const int qid = bid - NV_BLK;
        const int m0 = (qid / 6) * 64, nb = qid % 6, n0 = nb * 64;
        const float* Ap = query + (size_t)(m0 + r) * 256 + q4 * 8;
        const uint32_t aoff = r * 80 + q4 * 16;
        const char* bsrc0 = wqc + (size_t)nb * 10240;

        {
            float4 v0 = *(const float4*)(Ap);
            float4 v1 = *(const float4*)(Ap + 4);
            float xh = bf_hi(v0.x), yh = bf_hi(v0.y);
            float zh = bf_hi(v0.z), wwh = bf_hi(v0.w);
            float xh2 = bf_hi(v1.x), yh2 = bf_hi(v1.y);
            float zh2 = bf_hi(v1.z), wh2 = bf_hi(v1.w);
            uint4 wh, wl;
            wh.x = pack_bf16x2(xh, yh);   wh.y = pack_bf16x2(zh, wwh);
            wh.z = pack_bf16x2(xh2, yh2); wh.w = pack_bf16x2(zh2, wh2);
            wl.x = pack_bf16x2(v0.x - xh, v0.y - yh);
            wl.y = pack_bf16x2(v0.z - zh, v0.w - wwh);
            wl.z = pack_bf16x2(v1.x - xh2, v1.y - yh2);
            wl.w = pack_bf16x2(v1.z - zh2, v1.w - wh2);
            *(uint4*)(sm + aoff)        = wh;
            *(uint4*)(sm + 5120 + aoff) = wl;
        }
        float4 rA[2][2];
        rA[0][0] = *(const float4*)(Ap + 32);
        rA[0][1] = *(const float4*)(Ap + 36);
        rA[1][0] = *(const float4*)(Ap + 64);
        rA[1][1] = *(const float4*)(Ap + 68);
#pragma unroll
        for (int s = 0; s < 3; s++) {
            uint32_t bd = sbase + 20480 + s * 10240;
            const char* bs = bsrc0 + (size_t)s * 6 * 10240;
            cp16(bd + tid * 16, bs + tid * 16);
            cp16(bd + (tid + 256) * 16, bs + (tid + 256) * 16);
            if (tid < 128) cp16(bd + (tid + 512) * 16, bs + (tid + 512) * 16);
            CP_COMMIT();
        }

#pragma unroll
        for (int kb = 0; kb < 8; kb++) {
            if (kb < 6)      CP_WAIT(2);
            else if (kb == 6) CP_WAIT(1);
            else              CP_WAIT(0);
            __syncthreads();

            if (kb < 7) {
                float4 v0 = rA[0][0], v1 = rA[0][1];
                float xh = bf_hi(v0.x), yh = bf_hi(v0.y);
                float zh = bf_hi(v0.z), wwh = bf_hi(v0.w);
                float xh2 = bf_hi(v1.x), yh2 = bf_hi(v1.y);
                float zh2 = bf_hi(v1.z), wh2 = bf_hi(v1.w);
                uint4 wh, wl;
                wh.x = pack_bf16x2(xh, yh);   wh.y = pack_bf16x2(zh, wwh);
                wh.z = pack_bf16x2(xh2, yh2); wh.w = pack_bf16x2(zh2, wh2);
                wl.x = pack_bf16x2(v0.x - xh, v0.y - yh);
                wl.y = pack_bf16x2(v0.z - zh, v0.w - wwh);
                wl.z = pack_bf16x2(v1.x - xh2, v1.y - yh2);
                wl.w = pack_bf16x2(v1.z - zh2, v1.w - wh2);
                uint32_t ab = ((kb + 1) & 1) * 10240;
                *(uint4*)(sm + ab + aoff)        = wh;
                *(uint4*)(sm + ab + 5120 + aoff) = wl;
                rA[0][0] = rA[1][0]; rA[0][1] = rA[1][1];
                if (kb + 3 < 8) {
                    rA[1][0] = *(const float4*)(Ap + (kb + 3) * 32);
                    rA[1][1] = *(const float4*)(Ap + (kb + 3) * 32 + 4);
                }
            }
            if (kb + 3 < 8) {
                uint32_t bd = sbase + 20480 + ((kb + 3) & 3) * 10240;
                const char* bs = bsrc0 + (size_t)(kb + 3) * 6 * 10240;
                cp16(bd + tid * 16, bs + tid * 16);
                cp16(bd + (tid + 256) * 16, bs + (tid + 256) * 16);
                if (tid < 128) cp16(bd + (tid + 512) * 16, bs + (tid + 512) * 16);
                CP_COMMIT();
            }

            const uint32_t baseA = sbase + (kb & 1) * 10240;
            const uint32_t baseB = sbase + 20480 + (kb & 3) * 10240;
#pragma unroll
            for (int ks = 0; ks < 2; ks++) {
                const int cb = ks * 32 + chi;
                uint32_t aH[2][4], aL[2][4], bH[4], bL[4];
#pragma unroll
                for (int fm = 0; fm < 2; fm++) {
                    uint32_t ad = baseA + (wm + fm * 16 + rr16) * 80 + cb;
                    LDSM4(aH[fm], ad);
                    LDSM4(aL[fm], ad + 5120);
                }
                {
                    uint32_t bd = baseB + (wn + rr16) * 80 + cb;
                    LDSM4(bH, bd);
                    LDSM4(bL, bd + 5120);
                }
#pragma unroll
                for (int fm = 0; fm < 2; fm++)
#pragma unroll
                    for (int fn = 0; fn < 2; fn++) {
                        uint32_t bh2[2] = {bH[fn], bH[fn + 2]};
                        uint32_t bl2[2] = {bL[fn], bL[fn + 2]};
                        mma_bf16(acc[fm][fn], aL[fm], bh2);
                        mma_bf16(acc[fm][fn], aH[fm], bl2);
                        mma_bf16(acc[fm][fn], aH[fm], bh2);
                    }
            }
        }

        const bool is_aw = (n0 >= 256);
        const float* bias = is_aw ? b_aw : b_so;
        float* Cm = is_aw ? awr : offs;
        const int Nout = is_aw ? 128 : 256;
        const int ncol0 = is_aw ? (n0 - 256) : n0;
#pragma unroll
        for (int fn = 0; fn < 2; fn++) {
            int cn = ncol0 + wn + fn * 8 + t * 2;
            float b0 = bias[cn], b1 = bias[cn + 1];
#pragma unroll
            for (int fm = 0; fm < 2; fm++) {
                int r0 = m0 + wm + fm * 16 + g;
                *(float2*)&Cm[(size_t)r0 * Nout + cn] =
                    make_float2(acc[fm][fn][0] + b0, acc[fm][fn][1] + b1);
                *(float2*)&Cm[(size_t)(r0 + 8) * Nout + cn] =
                    make_float2(acc[fm][fn][2] + b0, acc[fm][fn][3] + b1);
            }
        }
    }
}

// ---------------------------------------------------------------------------
// out-proj GEMM: fp16 MMA, pure 4-stage cp.async (A and B raw copies).
// ---------------------------------------------------------------------------
__global__ void __launch_bounds__(256)
gemm_out(const __half* __restrict__ A, const char* __restrict__ Bimg,
         const float* __restrict__ bias, float* __restrict__ Cm)
{
    __shared__ __align__(16) char sm[40960];

    const int tid = threadIdx.x, wid = tid >> 5, lane = tid & 31;
    const int g = lane >> 2, t = lane & 3;
    const int m0 = blockIdx.x * 64, n0 = blockIdx.y * 64;
    const int wm = (wid & 1) * 32, wn = (wid >> 1) * 16;
    const int r  = tid >> 2;
    const int q4 = tid & 3;
    const int rr16 = lane & 15;
    const int chi  = ((lane >> 4) & 1) * 16;
    const uint32_t sbase = smem_u32(sm);

    const char* asrc = (const char*)(A + (size_t)(m0 + r) * 256) + q4 * 16;
    const char* bsrc0 = Bimg + (size_t)blockIdx.y * 5120;
    const uint32_t aoff = r * 80 + q4 * 16;

    float acc[2][2][4];
#pragma unroll
    for (int i = 0; i < 2; i++)
#pragma unroll
        for (int j = 0; j < 2; j++)
#pragma unroll
            for (int c = 0; c < 4; c++) acc[i][j][c] = 0.0f;

#pragma unroll
    for (int s = 0; s < 3; s++) {
        uint32_t sb = sbase + s * 10240;
        cp16(sb + aoff, asrc + (size_t)s * 64);
        uint32_t bd = sb + 5120;
        const char* bs = bsrc0 + (size_t)s * 4 * 5120;
        cp16(bd + tid * 16, bs + tid * 16);
        if (tid < 64) cp16(bd + (tid + 256) * 16, bs + (tid + 256) * 16);
        CP_COMMIT();
    }

#pragma unroll
    for (int kb = 0; kb < 8; kb++) {
        if (kb < 6)      CP_WAIT(2);
        else if (kb == 6) CP_WAIT(1);
        else              CP_WAIT(0);
        __syncthreads();

        if (kb + 3 < 8) {
            uint32_t sb = sbase + ((kb + 3) & 3) * 10240;
            cp16(sb + aoff, asrc + (size_t)(kb + 3) * 64);
            uint32_t bd = sb + 5120;
            const char* bs = bsrc0 + (size_t)(kb + 3) * 4 * 5120;
            cp16(bd + tid * 16, bs + tid * 16);
            if (tid < 64) cp16(bd + (tid + 256) * 16, bs + (tid + 256) * 16);
            CP_COMMIT();
        }

        const uint32_t base = sbase + (kb & 3) * 10240;
#pragma unroll
        for (int ks = 0; ks < 2; ks++) {
            const int cb = ks * 32 + chi;
            uint32_t aH[2][4], bH[4];
#pragma unroll
            for (int fm = 0; fm < 2; fm++)
                LDSM4(aH[fm], base + (wm + fm * 16 + rr16) * 80 + cb);
            LDSM4(bH, base + 5120 + (wn + rr16) * 80 + cb);
#pragma unroll
            for (int fm = 0; fm < 2; fm++)
#pragma unroll
                for (int fn = 0; fn < 2; fn++) {
                    uint32_t bh2[2] = {bH[fn], bH[fn + 2]};
                    mma_f16(acc[fm][fn], aH[fm], bh2);
                }
        }
    }

#pragma unroll
    for (int fn = 0; fn < 2; fn++) {
        int cn = n0 + wn + fn * 8 + t * 2;
        float b0 = bias[cn], b1 = bias[cn + 1];
#pragma unroll
        for (int fm = 0; fm < 2; fm++) {
            int r0 = m0 + wm + fm * 16 + g;
            *(float2*)&Cm[(size_t)r0 * 256 + cn] =
                make_float2(acc[fm][fn][0] + b0, acc[fm][fn][1] + b1);
            *(float2*)&Cm[(size_t)(r0 + 8) * 256 + cn] =
                make_float2(acc[fm][fn][2] + b0, acc[fm][fn][3] + b1);
        }
    }
}

// ---------------------------------------------------------------------------
// Sampling kernel: 8 queries per block (256 threads); 16B vectorized gathers.
// ---------------------------------------------------------------------------
#define QPB 8
__global__ __launch_bounds__(256)
void sample_kernel(const float* __restrict__ ref,
                   const int* __restrict__ batch_offsets)
{
    __shared__ float sL[QPB][128];
    __shared__ float hM[QPB][8];
    __shared__ float hR[QPB][8];
    __shared__ float sIS[QPB][2];
    __shared__ __align__(16) int   srow[QPB][128][4];
    __shared__ __align__(16) float swt [QPB][128][4];

    const int tid = threadIdx.x;
    const int q0  = blockIdx.x * QPB;
    const int boundary = batch_offsets[1];

#pragma unroll
    for (int j = tid; j < QPB * 128; j += 256)
        sL[j >> 7][j & 127] = g_awr[(size_t)(q0 + (j >> 7)) * 128 + (j & 127)];

    if (tid >= 224 && tid < 224 + QPB * 2) {
        int k = tid - 224;
        int qi = k >> 1, xy = k & 1;
        float v = ref[(q0 + qi) * 2 + xy];
        v = fminf(fmaxf(v, 0.0f), 1.0f);
        sIS[qi][xy] = logf(fmaxf(v, 1e-5f) / fmaxf(1.0f - v, 1e-5f));
    }
    __syncthreads();

    if (tid < QPB * 8) {
        int qi = tid >> 3, h = tid & 7;
        float m = -1e30f;
#pragma unroll
        for (int lp = 0; lp < 16; lp++) m = fmaxf(m, sL[qi][lp * 8 + h]);
        float s = 0.0f;
#pragma unroll
        for (int lp = 0; lp < 16; lp++) s += expf(sL[qi][lp * 8 + h] - m);
        hM[qi][h] = m;
        hR[qi][h] = 1.0f / s;
    }
    __syncthreads();

#pragma unroll
    for (int j = tid; j < QPB * 128; j += 256) {
        const int qi = j >> 7;
        const int i  = j & 127;
        const int q  = q0 + qi;
        const int h  = i & 7;
        const int lp = i >> 3;
        const int l  = lp >> 2;

        float aw = expf(sL[qi][i] - hM[qi][h]) * hR[qi][h];

        float ox = g_offs[(size_t)q * 256 + i * 2 + 0];
        float oy = g_offs[(size_t)q * 256 + i * 2 + 1];

        float locx = 1.0f / (1.0f + expf(-(sIS[qi][0] + ox)));
        float locy = 1.0f / (1.0f + expf(-(sIS[qi][1] + oy)));

        const int   Wl = HMAX_ >> l;
        const float Wf = (float)Wl;
        float x = locx * Wf - 0.5f;
        float y = locy * Wf - 0.5f;

        float x0f = floorf(x), y0f = floorf(y);
        float wx1 = x - x0f, wx0 = 1.0f - wx1;
        float wy1 = y - y0f, wy0 = 1.0f - wy1;
        int x0 = (int)x0f, y0 = (int)y0f;

        int b = (q >= boundary) ? 1 : 0;
        int lbase = (l >= 1 ? 16384 : 0) + (l >= 2 ? 4096 : 0) + (l >= 3 ? 1024 : 0);
        int base = b * ROWS_PER_B + lbase;

        int   xs[2]  = {x0, x0 + 1};
        int   ys2[2] = {y0, y0 + 1};
        float wxs[2] = {wx0, wx1};
        float wys[2] = {wy0, wy1};

#pragma unroll
        for (int cy = 0; cy < 2; cy++) {
#pragma unroll
            for (int cx = 0; cx < 2; cx++) {
                int c  = cy * 2 + cx;
                int xi = xs[cx], yi = ys2[cy];
                bool valid = (xi >= 0) & (xi < Wl) & (yi >= 0) & (yi < Wl);
                int xc = min(max(xi, 0), Wl - 1);
                int yc = min(max(yi, 0), Wl - 1);
                srow[qi][i][c] = base + yc * Wl + xc;
                swt [qi][i][c] = valid ? (aw * wys[cy] * wxs[cx]) : 0.0f;
            }
        }
    }
    __syncthreads();

    // gather: 32 threads per query, 8 channels each (16B loads)
    const int qi   = tid >> 5;
    const int tq   = tid & 31;
    const int h    = tq >> 2;
    const int coff = h * DH_ + (tq & 3) * 8;
    const int q    = q0 + qi;

    float acc[8];
#pragma unroll
    for (int e = 0; e < 8; e++) acc[e] = 0.0f;

#pragma unroll
    for (int lp = 0; lp < 16; lp++) {
        const int i = lp * 8 + h;
        int4   r4 = *(const int4*)  &srow[qi][i][0];
        float4 w4 = *(const float4*)&swt [qi][i][0];
        int   rr[4] = {r4.x, r4.y, r4.z, r4.w};
        float ww[4] = {w4.x, w4.y, w4.z, w4.w};
#pragma unroll
        for (int c = 0; c < 4; c++) {
            const uint4 v = __ldg((const uint4*)&g_vproj[(size_t)rr[c] * C_ + coff]);
            const __half2* hp = (const __half2*)&v;
            float w = ww[c];
#pragma unroll
            for (int e = 0; e < 4; e++) {
                float2 f = __half22float2(hp[e]);
                acc[e * 2 + 0] += w * f.x;
                acc[e * 2 + 1] += w * f.y;
            }
        }
    }
    uint4 outv;
    outv.x = pack_f16x2(acc[0], acc[1]);
    outv.y = pack_f16x2(acc[2], acc[3]);
    outv.z = pack_f16x2(acc[4], acc[5]);
    outv.w = pack_f16x2(acc[6], acc[7]);
    *(uint4*)&g_agg[(size_t)q * C_ + coff] = outv;
}

// ---------------------------------------------------------------------------
// kernel_launch
// ---------------------------------------------------------------------------
extern "C" void kernel_launch(void* const* d_in, const int* in_sizes, int n_in,
                              void* d_out, int out_size)
{
    const float* query  = (const float*)d_in[0];
    const float* ref    = (const float*)d_in[1];
    const float* values = (const float*)d_in[2];
    const float* W_so   = (const float*)d_in[3];
    const float* b_so   = (const float*)d_in[4];
    const float* W_aw   = (const float*)d_in[5];
    const float* b_aw   = (const float*)d_in[6];
    const float* W_v    = (const float*)d_in[7];
    const float* b_v    = (const float*)d_in[8];
    const float* W_o    = (const float*)d_in[9];
    const float* b_o    = (const float*)d_in[10];
    const int* batch_offsets = (const int*)d_in[11];
    float* out = (float*)d_out;
    (void)in_sizes; (void)n_in; (void)out_size;

    __half *vproj, *agg;
    float *offs, *awr;
    char *wvh, *wqc, *woh;
    cudaGetSymbolAddress((void**)&vproj, g_vproj);
    cudaGetSymbolAddress((void**)&offs,  g_offs);
    cudaGetSymbolAddress((void**)&awr,   g_awr);
    cudaGetSymbolAddress((void**)&agg,   g_agg);
    cudaGetSymbolAddress((void**)&wvh,   g_wvh_img);
    cudaGetSymbolAddress((void**)&wqc,   g_wqc_img);
    cudaGetSymbolAddress((void**)&woh,   g_woh_img);

    // 0) weight images (single launch)
    prep_all<<<448, 256>>>(W_v, W_so, W_aw, W_o, wvh, wqc, woh);

    // 1) vproj + offs + awr, one fused launch (1448 CTAs, 8 warps each)
    gemm_all<<<NV_BLK + NQ_BLK, 256>>>(values, wvh, b_v, vproj,
                                       query, wqc, b_so, b_aw, offs, awr);

    // 2) softmax + bilinear sampling + head aggregation (fp16 agg out)
    sample_kernel<<<Q_ / QPB, 256>>>(ref, batch_offsets);

    // 3) out = agg @ W_o^T + b_o  [8192 x 256] (fp16 MMA, cp.async 4-stage)
    {
        dim3 grid(Q_ / 64, 4);
        gemm_out<<<grid, 256>>>(agg, woh, b_o, out);
    }
}